// round 11
// baseline (speedup 1.0000x reference)
#include <cuda_runtime.h>
#include <cuda_bf16.h>
#include <math.h>
#include <stdint.h>

// ---------------------------------------------------------------------------
// Problem constants
// ---------------------------------------------------------------------------
#define NNODES 10000
#define NIN    2000
#define D1     500
#define D2     500
#define D3     2000
#define NZC    64
#define COMS_D 3064
#define EMAX   131072
#define WOFF   (2u * 1024u * 1024u)   // second weight-buffer region (elements)

// ---------------------------------------------------------------------------
// Scratch (device globals; no allocations allowed)
// ---------------------------------------------------------------------------
__device__ float g_zbuf [NNODES * NZC];
__device__ float g_gbuf [NNODES * 2000];
__device__ float g_traw [NNODES * 2000];
__device__ float g_t1[NNODES * 500];
__device__ float g_t2[NNODES * 500];
__device__ float g_t3[NNODES * 2000];
__device__ float g_t4[NNODES * NZC];
__device__ float g_u [NNODES * 5];
__device__ float g_ztopo[NNODES * NZC];
__device__ float g_embp[NNODES * NZC];
__device__ float g_mean[4096];
__device__ float g_rstd[4096];

// CSR build
__device__ int   g_cnt[NNODES + 1];
__device__ int   g_rowptr[NNODES + 1];
__device__ int   g_wp[NNODES];
__device__ int   g_scol[EMAX];
__device__ float g_sval[EMAX];

// bf16 split-precision ping-pong A buffers + weight buffers (2 regions each)
__device__ __align__(256) __nv_bfloat16 g_A0hi[(size_t)NNODES * 3072];
__device__ __align__(256) __nv_bfloat16 g_A0lo[(size_t)NNODES * 3072];
__device__ __align__(256) __nv_bfloat16 g_A1hi[(size_t)NNODES * 3072];
__device__ __align__(256) __nv_bfloat16 g_A1lo[(size_t)NNODES * 3072];
__device__ __align__(256) __nv_bfloat16 g_Whi[2048 * 3072];
__device__ __align__(256) __nv_bfloat16 g_Wlo[2048 * 3072];

// ---------------------------------------------------------------------------
// PTX helpers
// ---------------------------------------------------------------------------
__device__ __forceinline__ void ldsm4(uint32_t* r, uint32_t addr) {
    asm volatile("ldmatrix.sync.aligned.m8n8.x4.shared.b16 {%0,%1,%2,%3}, [%4];"
                 : "=r"(r[0]), "=r"(r[1]), "=r"(r[2]), "=r"(r[3]) : "r"(addr));
}
__device__ __forceinline__ uint32_t smem_u32(const void* p) {
    uint32_t a;
    asm("{ .reg .u64 t; cvta.to.shared.u64 t, %1; cvt.u32.u64 %0, t; }" : "=r"(a) : "l"(p));
    return a;
}
__device__ __forceinline__ void mma16816(float* c, const uint32_t* a, const uint32_t* b) {
    asm volatile(
        "mma.sync.aligned.m16n8k16.row.col.f32.bf16.bf16.f32 "
        "{%0,%1,%2,%3}, {%4,%5,%6,%7}, {%8,%9}, {%0,%1,%2,%3};"
        : "+f"(c[0]), "+f"(c[1]), "+f"(c[2]), "+f"(c[3])
        : "r"(a[0]), "r"(a[1]), "r"(a[2]), "r"(a[3]), "r"(b[0]), "r"(b[1]));
}
__device__ __forceinline__ void split_bf16(float v, __nv_bfloat16& h, __nv_bfloat16& l) {
    h = __float2bfloat16(v);
    l = __float2bfloat16(v - __bfloat162float(h));
}
__device__ __forceinline__ void cpa16(uint32_t dst, const void* src) {
    asm volatile("cp.async.cg.shared.global [%0], [%1], 16;" :: "r"(dst), "l"(src));
}
__device__ __forceinline__ void cp_commit() {
    asm volatile("cp.async.commit_group;" ::: "memory");
}
template<int N>
__device__ __forceinline__ void cp_wait() {
    asm volatile("cp.async.wait_group %0;" :: "n"(N) : "memory");
}

// ---------------------------------------------------------------------------
// Split-bf16 mma.sync GEMM: BM=128, BN=128, BK=32, 256 threads, 8 warps
// (4m x 2n), warp tile 32x64 (acc = 64 regs). cp.async 2-stage pipeline.
// C may be nullptr. mode: 0 none, 1 +bias, 2 +bias+elu
// ---------------------------------------------------------------------------
#define ROWB 80
#define TILE_BYTES (128 * ROWB)        // 10240 each of Ahi/Alo/Bhi/Blo
#define STAGE_BYTES (4 * TILE_BYTES)   // 40960
#define GEMM_DSMEM (2 * STAGE_BYTES)   // 81920

__device__ __forceinline__ void load_stage_async(
    uint32_t sbase,
    const __nv_bfloat16* __restrict__ Ahi, const __nv_bfloat16* __restrict__ Alo,
    const __nv_bfloat16* __restrict__ Bhi, const __nv_bfloat16* __restrict__ Blo,
    int mBase, int M, int nBase, int N, int Kpad, int k0, int tid)
{
#pragma unroll
    for (int it = 0; it < 2; it++) {
        int t = tid + it * 256;
        int row = t >> 2, seg = t & 3;
        uint32_t d = sbase + row * ROWB + seg * 16;
        int gr = mBase + row;
        int sr = (gr < M) ? gr : 0;
        size_t aoff = (size_t)sr * Kpad + k0 + seg * 8;
        cpa16(d,              Ahi + aoff);
        cpa16(d + TILE_BYTES, Alo + aoff);
        int gn = nBase + row;
        int sn = (gn < N) ? gn : 0;
        size_t boff = (size_t)sn * Kpad + k0 + seg * 8;
        cpa16(d + 2 * TILE_BYTES, Bhi + boff);
        cpa16(d + 3 * TILE_BYTES, Blo + boff);
    }
}

__global__ __launch_bounds__(256, 2) void mma_gemm_kernel(
    const __nv_bfloat16* __restrict__ Ahi, const __nv_bfloat16* __restrict__ Alo,
    const __nv_bfloat16* __restrict__ Bhi, const __nv_bfloat16* __restrict__ Blo,
    const float* __restrict__ bias, float* __restrict__ C,
    __nv_bfloat16* __restrict__ outHi, __nv_bfloat16* __restrict__ outLo, int KpadOut,
    int M, int Ncol, int Kpad, int mode)
{
    extern __shared__ __align__(256) char smem[];
    uint32_t sb = smem_u32(smem);
    int tid = threadIdx.x;
    int wid = tid >> 5, lane = tid & 31;
    int wm = wid & 3;          // m-warp 0..3 (32 rows each)
    int wn = wid >> 2;         // n-warp 0..1 (64 cols each)
    int mBase = blockIdx.y * 128;
    int nBase = blockIdx.x * 128;

    float acc[2][8][4];
#pragma unroll
    for (int mt = 0; mt < 2; mt++)
#pragma unroll
        for (int nt = 0; nt < 8; nt++)
#pragma unroll
            for (int r = 0; r < 4; r++) acc[mt][nt][r] = 0.f;

    const int nc = Kpad >> 5;

    load_stage_async(sb, Ahi, Alo, Bhi, Blo, mBase, M, nBase, Ncol, Kpad, 0, tid);
    cp_commit();
    if (nc > 1) {
        load_stage_async(sb + STAGE_BYTES, Ahi, Alo, Bhi, Blo, mBase, M, nBase, Ncol, Kpad, 32, tid);
        cp_commit();
    }

    int lrow = (lane & 7) + ((lane >> 3) & 1) * 8;
    int lcol8 = (lane >> 4) * 8;

    for (int c = 0; c < nc; c++) {
        if (c + 1 < nc) cp_wait<1>(); else cp_wait<0>();
        __syncthreads();

        uint32_t bufU = sb + (c & 1) * STAGE_BYTES;
        uint32_t aHiS = bufU;
        uint32_t aLoS = bufU + TILE_BYTES;
        uint32_t bHiS = bufU + 2 * TILE_BYTES;
        uint32_t bLoS = bufU + 3 * TILE_BYTES;

#pragma unroll
        for (int ks = 0; ks < 2; ks++) {
            int kc = ks * 16 + lcol8;
            uint32_t ah[2][4], al[2][4], bb[8][2];
            // A-hi (32 rows) + B-hi (64 cols)
#pragma unroll
            for (int mt = 0; mt < 2; mt++)
                ldsm4(ah[mt], aHiS + (wm * 32 + mt * 16 + lrow) * ROWB + kc * 2);
#pragma unroll
            for (int ntp = 0; ntp < 4; ntp++) {
                uint32_t t[4];
                ldsm4(t, bHiS + (wn * 64 + ntp * 16 + lrow) * ROWB + kc * 2);
                bb[2 * ntp][0] = t[0]; bb[2 * ntp][1] = t[2];
                bb[2 * ntp + 1][0] = t[1]; bb[2 * ntp + 1][1] = t[3];
            }
            // pass 1: hi*hi
#pragma unroll
            for (int mt = 0; mt < 2; mt++)
#pragma unroll
                for (int nt = 0; nt < 8; nt++)
                    mma16816(acc[mt][nt], ah[mt], bb[nt]);
            // A-lo; pass 2: lo*hi (B-hi still live)
#pragma unroll
            for (int mt = 0; mt < 2; mt++)
                ldsm4(al[mt], aLoS + (wm * 32 + mt * 16 + lrow) * ROWB + kc * 2);
#pragma unroll
            for (int mt = 0; mt < 2; mt++)
#pragma unroll
                for (int nt = 0; nt < 8; nt++)
                    mma16816(acc[mt][nt], al[mt], bb[nt]);
            // B-lo overwrites bb; pass 3: hi*lo
#pragma unroll
            for (int ntp = 0; ntp < 4; ntp++) {
                uint32_t t[4];
                ldsm4(t, bLoS + (wn * 64 + ntp * 16 + lrow) * ROWB + kc * 2);
                bb[2 * ntp][0] = t[0]; bb[2 * ntp][1] = t[2];
                bb[2 * ntp + 1][0] = t[1]; bb[2 * ntp + 1][1] = t[3];
            }
#pragma unroll
            for (int mt = 0; mt < 2; mt++)
#pragma unroll
                for (int nt = 0; nt < 8; nt++)
                    mma16816(acc[mt][nt], ah[mt], bb[nt]);
        }
        __syncthreads();
        if (c + 2 < nc) {
            load_stage_async(sb + (c & 1) * STAGE_BYTES, Ahi, Alo, Bhi, Blo,
                             mBase, M, nBase, Ncol, Kpad, (c + 2) * 32, tid);
            cp_commit();
        }
    }

    // Epilogue
    int qr = lane >> 2;
    int qc = (lane & 3) * 2;
#pragma unroll
    for (int mt = 0; mt < 2; mt++) {
#pragma unroll
        for (int nt = 0; nt < 8; nt++) {
#pragma unroll
            for (int half = 0; half < 2; half++) {
                int gr = mBase + wm * 32 + mt * 16 + qr + half * 8;
                if (gr >= M) continue;
#pragma unroll
                for (int e = 0; e < 2; e++) {
                    int gc = nBase + wn * 64 + nt * 8 + qc + e;
                    float v = acc[mt][nt][half * 2 + e];
                    if (gc < Ncol) {
                        if (mode >= 1) v += bias[gc];
                        if (mode == 2) v = v > 0.f ? v : expm1f(v);
                        if (C) C[(size_t)gr * Ncol + gc] = v;
                    } else {
                        v = 0.f;
                    }
                    if (outHi && gc < KpadOut) {
                        __nv_bfloat16 h, l;
                        split_bf16(v, h, l);
                        outHi[(size_t)gr * KpadOut + gc] = h;
                        outLo[(size_t)gr * KpadOut + gc] = l;
                    }
                }
            }
        }
    }
}

// ---------------------------------------------------------------------------
// Conversions
// ---------------------------------------------------------------------------
__global__ void convA_kernel(const float* __restrict__ src,
                             __nv_bfloat16* __restrict__ hi, __nv_bfloat16* __restrict__ lo,
                             int K, int Kpad, long total)
{
    long i = (long)blockIdx.x * blockDim.x + threadIdx.x;
    if (i >= total) return;
    long r = i / Kpad;
    int  k = (int)(i - r * Kpad);
    float v = (k < K) ? src[r * K + k] : 0.f;
    __nv_bfloat16 h, l;
    split_bf16(v, h, l);
    hi[i] = h; lo[i] = l;
}

__global__ void convBT_kernel(const float* __restrict__ B,
                              __nv_bfloat16* __restrict__ bhi, __nv_bfloat16* __restrict__ blo,
                              int K, int N, int Kpad)
{
    __shared__ float sm[32][33];
    int k0 = blockIdx.x * 32, n0 = blockIdx.y * 32;
    int tx = threadIdx.x, ty = threadIdx.y;
    for (int i = ty; i < 32; i += 8) {
        int k = k0 + i, n = n0 + tx;
        sm[i][tx] = (k < K && n < N) ? B[(size_t)k * N + n] : 0.f;
    }
    __syncthreads();
    for (int i = ty; i < 32; i += 8) {
        int n = n0 + i, k = k0 + tx;
        if (n < N && k < Kpad) {
            __nv_bfloat16 h, l;
            split_bf16(sm[tx][i], h, l);
            bhi[(size_t)n * Kpad + k] = h;
            blo[(size_t)n * Kpad + k] = l;
        }
    }
}

// ---------------------------------------------------------------------------
// CSR build + CSR SpMM with fused activation
// ---------------------------------------------------------------------------
__global__ void csr_zero_kernel(int* cnt) {
    int i = blockIdx.x * blockDim.x + threadIdx.x;
    if (i <= NNODES) cnt[i] = 0;
}
__global__ void csr_count_kernel(const int* __restrict__ row, int* cnt, int E) {
    int e = blockIdx.x * blockDim.x + threadIdx.x;
    if (e < E) atomicAdd(&cnt[row[e] + 1], 1);
}
#define SCAN_PER 10
__global__ __launch_bounds__(1024) void csr_scan_kernel(const int* __restrict__ cnt,
                                                        int* rowptr, int* wp)
{
    __shared__ int sh[1024];
    int t = threadIdx.x;
    int base = t * SCAN_PER;
    int local[SCAN_PER];
    int s = 0;
#pragma unroll
    for (int i = 0; i < SCAN_PER; i++) {
        int idx = base + i;
        int v = (idx < NNODES) ? cnt[idx + 1] : 0;
        s += v;
        local[i] = s;
    }
    sh[t] = s;
    __syncthreads();
    for (int off = 1; off < 1024; off <<= 1) {
        int v = (t >= off) ? sh[t - off] : 0;
        __syncthreads();
        sh[t] += v;
        __syncthreads();
    }
    int prev = (t > 0) ? sh[t - 1] : 0;
    if (t == 0) rowptr[0] = 0;
#pragma unroll
    for (int i = 0; i < SCAN_PER; i++) {
        int idx = base + i;
        if (idx < NNODES) {
            rowptr[idx + 1] = prev + local[i];
            wp[idx] = (i == 0) ? prev : prev + local[i - 1];
        }
    }
}
__global__ void csr_scatter_kernel(const int* __restrict__ row, const int* __restrict__ col,
                                   const float* __restrict__ val, int* wp,
                                   int* scol, float* sval, int E)
{
    int e = blockIdx.x * blockDim.x + threadIdx.x;
    if (e >= E) return;
    int p = atomicAdd(&wp[row[e]], 1);
    scol[p] = col[e];
    sval[p] = val[e];
}

__global__ void spmm_csr_kernel(const float* __restrict__ H,
                                const int* __restrict__ rowptr,
                                const int* __restrict__ scol, const float* __restrict__ sval,
                                float* __restrict__ out, int D, int actmode)
{
    int r = blockIdx.x;
    int s = rowptr[r], e_end = rowptr[r + 1];
    int nt = blockDim.x;
    float acc[8];
    int nreg = (D + nt - 1) / nt;
#pragma unroll 8
    for (int i = 0; i < 8; i++) acc[i] = 0.f;
    for (int e = s; e < e_end; e++) {
        int c = scol[e];
        float v = sval[e];
        const float* hrow = H + (size_t)c * D;
#pragma unroll 8
        for (int i = 0; i < 8; i++) {
            if (i >= nreg) break;
            int d = threadIdx.x + i * nt;
            if (d < D) acc[i] = fmaf(v, hrow[d], acc[i]);
        }
    }
#pragma unroll 8
    for (int i = 0; i < 8; i++) {
        if (i >= nreg) break;
        int d = threadIdx.x + i * nt;
        if (d < D) {
            float o = acc[i];
            if (actmode == 0) o = o > 0.f ? o : expm1f(0.2f * o);
            else if (actmode == 1) o = o > 0.f ? o : expm1f(o);
            out[(size_t)r * D + d] = o;
        }
    }
}
static inline void spmm_csr(const float* H, float* out, int D, int actmode,
                            const int* rowptr, const int* scol, const float* sval)
{
    int threads = (D >= 256) ? 256 : ((D + 31) & ~31);
    spmm_csr_kernel<<<NNODES, threads>>>(H, rowptr, scol, sval, out, D, actmode);
}

// ---------------------------------------------------------------------------
// BatchNorm
// ---------------------------------------------------------------------------
__global__ void bn_stats_kernel(const float* __restrict__ h, int n, int d,
                                float* __restrict__ mean, float* __restrict__ rstd)
{
    __shared__ float ssum[8][32];
    __shared__ float ssq[8][32];
    int c = blockIdx.x * 32 + threadIdx.x;
    float s = 0.f, q = 0.f;
    if (c < d) {
        for (int r = threadIdx.y; r < n; r += 8) {
            float v = h[(size_t)r * d + c];
            s += v; q += v * v;
        }
    }
    ssum[threadIdx.y][threadIdx.x] = s;
    ssq[threadIdx.y][threadIdx.x] = q;
    __syncthreads();
    if (threadIdx.y == 0 && c < d) {
#pragma unroll
        for (int i = 1; i < 8; i++) { s += ssum[i][threadIdx.x]; q += ssq[i][threadIdx.x]; }
        float m = s / (float)n;
        float var = q / (float)n - m * m;
        if (var < 0.f) var = 0.f;
        mean[c] = m;
        rstd[c] = rsqrtf(var + 1e-5f);
    }
}
__global__ void bn_apply_kernel(const float* __restrict__ src, float* __restrict__ dst,
                                long total, int d, int Kpad,
                                const float* __restrict__ mean, const float* __restrict__ rstd,
                                __nv_bfloat16* __restrict__ outHi, __nv_bfloat16* __restrict__ outLo)
{
    long i = (long)blockIdx.x * blockDim.x + threadIdx.x;
    if (i >= total) return;
    long r = i / Kpad;
    int  c = (int)(i - r * Kpad);
    float v = 0.f;
    if (c < d) {
        v = (src[r * d + c] - mean[c]) * rstd[c];
        dst[r * d + c] = v;
    }
    if (outHi) {
        __nv_bfloat16 h, l;
        split_bf16(v, h, l);
        outHi[i] = h; outLo[i] = l;
    }
}
static inline void batchnorm(const float* src, float* dst, int n, int d,
                             float* mean, float* rstd,
                             __nv_bfloat16* outHi = nullptr, __nv_bfloat16* outLo = nullptr,
                             int Kpad = 0)
{
    dim3 bt(32, 8);
    bn_stats_kernel<<<(d + 31) / 32, bt>>>(src, n, d, mean, rstd);
    int kp = outHi ? Kpad : d;
    long total = (long)n * kp;
    bn_apply_kernel<<<(int)((total + 255) / 256), 256>>>(src, dst, total, d, kp, mean, rstd, outHi, outLo);
}

// ---------------------------------------------------------------------------
// Gate u, z_in, fused attention, heads
// ---------------------------------------------------------------------------
__device__ __forceinline__ float coms_at(const float* t1, const float* t2,
                                         const float* t3, const float* t4,
                                         int n, int k)
{
    if (k < 500)  return t1[(size_t)n * 500 + k];
    if (k < 1000) return t2[(size_t)n * 500 + (k - 500)];
    if (k < 3000) return t3[(size_t)n * 2000 + (k - 1000)];
    return t4[(size_t)n * 64 + (k - 3000)];
}

__global__ void u_kernel(const float* __restrict__ t1, const float* __restrict__ t2,
                         const float* __restrict__ t3, const float* __restrict__ t4,
                         const float* __restrict__ W, const float* __restrict__ b,
                         float* __restrict__ u)
{
    int warp = (blockIdx.x * blockDim.x + threadIdx.x) >> 5;
    int lane = threadIdx.x & 31;
    if (warp >= NNODES) return;
    float acc[5] = {0.f, 0.f, 0.f, 0.f, 0.f};
    for (int k = lane; k < COMS_D; k += 32) {
        float v = coms_at(t1, t2, t3, t4, warp, k);
        const float* w = &W[(size_t)k * 5];
#pragma unroll
        for (int j = 0; j < 5; j++) acc[j] = fmaf(v, w[j], acc[j]);
    }
#pragma unroll
    for (int j = 0; j < 5; j++) {
        for (int off = 16; off > 0; off >>= 1)
            acc[j] += __shfl_down_sync(0xFFFFFFFF, acc[j], off);
    }
    if (lane == 0) {
        float l[5], m = -1e30f;
#pragma unroll
        for (int j = 0; j < 5; j++) { l[j] = tanhf(acc[j] + b[j]); m = fmaxf(m, l[j]); }
        float s = 0.f;
#pragma unroll
        for (int j = 0; j < 5; j++) { l[j] = expf(l[j] - m); s += l[j]; }
        float nrm = 0.f;
#pragma unroll
        for (int j = 0; j < 5; j++) { l[j] /= s; nrm += l[j] * l[j]; }
        nrm = fmaxf(sqrtf(nrm), 1e-12f);
#pragma unroll
        for (int j = 0; j < 5; j++) u[(size_t)warp * 5 + j] = l[j] / nrm;
    }
}

__global__ void zin_conv_kernel(const float* __restrict__ t1, const float* __restrict__ t2,
                                const float* __restrict__ t3, const float* __restrict__ t4,
                                const float* __restrict__ u,
                                __nv_bfloat16* __restrict__ hi, __nv_bfloat16* __restrict__ lo)
{
    long i = (long)blockIdx.x * blockDim.x + threadIdx.x;
    long total = (long)NNODES * 3072;
    if (i >= total) return;
    int n = (int)(i / 3072);
    int k = (int)(i % 3072);
    float v = 0.f;
    if (k < COMS_D) {
        int seg = (k < 500) ? 0 : (k < 1000) ? 1 : (k < 3000) ? 2 : 3;
        v = u[(size_t)n * 5 + seg] * coms_at(t1, t2, t3, t4, n, k);
    }
    __nv_bfloat16 h, l;
    split_bf16(v, h, l);
    hi[i] = h; lo[i] = l;
}

__global__ __launch_bounds__(256) void att_fused_kernel(
    const float* __restrict__ z, const float* __restrict__ ztopo,
    const float* __restrict__ W1, const float* __restrict__ b1,
    const float* __restrict__ w2, float* __restrict__ embp)
{
    __shared__ float sW1[64 * 128];
    __shared__ float sb1[128];
    __shared__ float sw2[128];
    __shared__ float sS[8][64];
    __shared__ float sc[8];
    int tid = threadIdx.x;
    for (int i = tid; i < 64 * 128; i += 256) sW1[i] = W1[i];
    if (tid < 128) { sb1[tid] = b1[tid]; sw2[tid] = w2[tid]; }

    int wid = tid >> 5, lane = tid & 31;
    int nodeBase = blockIdx.x * 4;
    int n = nodeBase + (wid >> 1);
    int br = wid & 1;
    bool valid = (n < NNODES);
    if (valid) {
        const float* s = br ? &ztopo[(size_t)n * 64] : &z[(size_t)n * 64];
        sS[wid][lane] = s[lane];
        sS[wid][lane + 32] = s[lane + 32];
    }
    __syncthreads();

    float partial = 0.f;
    if (valid) {
#pragma unroll
        for (int jj = 0; jj < 4; jj++) {
            int j = lane + jj * 32;
            float h = sb1[j];
#pragma unroll
            for (int k = 0; k < 64; k++)
                h = fmaf(sS[wid][k], sW1[k * 128 + j], h);
            partial = fmaf(tanhf(h), sw2[j], partial);
        }
    }
    for (int off = 16; off > 0; off >>= 1)
        partial += __shfl_down_sync(0xFFFFFFFF, partial, off);
    if (lane == 0) sc[wid] = partial;
    __syncthreads();

    int nl = tid >> 6;
    int d  = tid & 63;
    int n2 = nodeBase + nl;
    if (n2 < NNODES) {
        float s0 = sc[nl * 2], s1 = sc[nl * 2 + 1];
        float m = fmaxf(s0, s1);
        float e0 = expf(s0 - m), e1 = expf(s1 - m);
        float inv = 1.f / (e0 + e1);
        embp[(size_t)n2 * 64 + d] = (e0 * inv) * z[(size_t)n2 * 64 + d]
                                  + (e1 * inv) * ztopo[(size_t)n2 * 64 + d];
    }
}

__global__ void heads_kernel(const float* __restrict__ emb, const float* __restrict__ z,
                             const float* __restrict__ cluster,
                             float* __restrict__ pred, float* __restrict__ q)
{
    int n = blockIdx.x;
    int t = threadIdx.x;
    __shared__ float sh[64];
    __shared__ float zs[64];

    float v = emb[(size_t)n * 64 + t];
    sh[t] = v;
    __syncthreads();
    for (int s = 32; s > 0; s >>= 1) {
        if (t < s) sh[t] = fmaxf(sh[t], sh[t + s]);
        __syncthreads();
    }
    float m = sh[0];
    __syncthreads();
    float e = expf(v - m);
    sh[t] = e;
    __syncthreads();
    for (int s = 32; s > 0; s >>= 1) {
        if (t < s) sh[t] += sh[t + s];
        __syncthreads();
    }
    pred[(size_t)n * 64 + t] = e / sh[0];
    __syncthreads();

    zs[t] = z[(size_t)n * 64 + t];
    __syncthreads();
    float d2 = 0.f;
    const float* c = &cluster[(size_t)t * 64];
    for (int k = 0; k < 64; k++) {
        float diff = zs[k] - c[k];
        d2 = fmaf(diff, diff, d2);
    }
    float qv = 1.f / (1.f + d2);
    sh[t] = qv;
    __syncthreads();
    for (int s = 32; s > 0; s >>= 1) {
        if (t < s) sh[t] += sh[t + s];
        __syncthreads();
    }
    q[(size_t)n * 64 + t] = qv / sh[0];
}

// ---------------------------------------------------------------------------
// Host-side helpers: weight conversion + GEMM launch (separable so weight
// conversions can be hoisted; wsel picks one of two W buffer regions)
// ---------------------------------------------------------------------------
static inline void conv_w(const float* Bw, int K, int N,
                          __nv_bfloat16* Whi, __nv_bfloat16* Wlo, int wsel)
{
    int Kpad = (K + 31) & ~31;
    dim3 tg((Kpad + 31) / 32, (N + 31) / 32);
    convBT_kernel<<<tg, dim3(32, 8)>>>(Bw, Whi + (size_t)wsel * WOFF, Wlo + (size_t)wsel * WOFF, K, N, Kpad);
}

static inline void gemm_run(const __nv_bfloat16* aHi, const __nv_bfloat16* aLo,
                            const float* bias, float* C,
                            __nv_bfloat16* outHi, __nv_bfloat16* outLo,
                            int M, int N, int K, int mode,
                            __nv_bfloat16* Whi, __nv_bfloat16* Wlo, int wsel)
{
    int Kpad = (K + 31) & ~31;
    int KpadOut = (N + 31) & ~31;
    cudaFuncSetAttribute(mma_gemm_kernel, cudaFuncAttributeMaxDynamicSharedMemorySize, GEMM_DSMEM);
    dim3 grid((N + 127) / 128, (M + 127) / 128);
    mma_gemm_kernel<<<grid, 256, GEMM_DSMEM>>>(aHi, aLo,
                                               Whi + (size_t)wsel * WOFF, Wlo + (size_t)wsel * WOFF,
                                               bias, C, outHi, outLo, KpadOut, M, N, Kpad, mode);
}

static inline void gemm_pre(const __nv_bfloat16* aHi, const __nv_bfloat16* aLo,
                            const float* Bw, const float* bias, float* C,
                            __nv_bfloat16* outHi, __nv_bfloat16* outLo,
                            int M, int N, int K, int mode,
                            __nv_bfloat16* Whi, __nv_bfloat16* Wlo)
{
    conv_w(Bw, K, N, Whi, Wlo, 0);
    gemm_run(aHi, aLo, bias, C, outHi, outLo, M, N, K, mode, Whi, Wlo, 0);
}

// ---------------------------------------------------------------------------
// Launch
// ---------------------------------------------------------------------------
extern "C" void kernel_launch(void* const* d_in, const int* in_sizes, int n_in,
                              void* d_out, int out_size)
{
    const float* x       = (const float*)d_in[0];
    const float* adj_val = (const float*)d_in[1];
    const float* enc1_w  = (const float*)d_in[2];
    const float* enc1_b  = (const float*)d_in[3];
    const float* enc2_w  = (const float*)d_in[4];
    const float* enc2_b  = (const float*)d_in[5];
    const float* enc3_w  = (const float*)d_in[6];
    const float* enc3_b  = (const float*)d_in[7];
    const float* zl_w    = (const float*)d_in[8];
    const float* zl_b    = (const float*)d_in[9];
    const float* dec1_w  = (const float*)d_in[10];
    const float* dec1_b  = (const float*)d_in[11];
    const float* dec2_w  = (const float*)d_in[12];
    const float* dec2_b  = (const float*)d_in[13];
    const float* dec3_w  = (const float*)d_in[14];
    const float* dec3_b  = (const float*)d_in[15];
    const float* xbar_w  = (const float*)d_in[16];
    const float* xbar_b  = (const float*)d_in[17];
    const float* t1_w    = (const float*)d_in[18];
    const float* t2_w    = (const float*)d_in[19];
    const float* t3_w    = (const float*)d_in[20];
    const float* t4_w    = (const float*)d_in[21];
    const float* agcn_w  = (const float*)d_in[22];
    const float* mlpl_w  = (const float*)d_in[23];
    const float* mlpl_b  = (const float*)d_in[24];
    const float* att_w1  = (const float*)d_in[25];
    const float* att_b1  = (const float*)d_in[26];
    const float* att_w2  = (const float*)d_in[27];
    const float* cluster = (const float*)d_in[28];
    const int*   adj_row = (const int*)d_in[29];
    const int*   adj_col = (const int*)d_in[30];
    const int E = in_sizes[1];

    float* out      = (float*)d_out;
    float* out_xbar = out;
    float* out_q    = out + (size_t)NNODES * NIN;
    float* out_pred = out_q + (size_t)NNODES * NZC;
    float* out_emb  = out_pred + (size_t)NNODES * NZC;

    float *z, *g, *traw, *t1, *t2, *t3, *t4, *u, *ztopo, *embp, *mean, *rstd;
    int *cnt, *rowptr, *wp, *scol;
    float *sval;
    __nv_bfloat16 *A0h, *A0l, *A1h, *A1l, *Wh, *Wl;
    cudaGetSymbolAddress((void**)&z,  g_zbuf);
    cudaGetSymbolAddress((void**)&g,  g_gbuf);
    cudaGetSymbolAddress((void**)&traw, g_traw);
    cudaGetSymbolAddress((void**)&t1, g_t1);
    cudaGetSymbolAddress((void**)&t2, g_t2);
    cudaGetSymbolAddress((void**)&t3, g_t3);
    cudaGetSymbolAddress((void**)&t4, g_t4);
    cudaGetSymbolAddress((void**)&u,  g_u);
    cudaGetSymbolAddress((void**)&ztopo, g_ztopo);
    cudaGetSymbolAddress((void**)&embp, g_embp);
    cudaGetSymbolAddress((void**)&mean, g_mean);
    cudaGetSymbolAddress((void**)&rstd, g_rstd);
    cudaGetSymbolAddress((void**)&cnt, g_cnt);
    cudaGetSymbolAddress((void**)&rowptr, g_rowptr);
    cudaGetSymbolAddress((void**)&wp, g_wp);
    cudaGetSymbolAddress((void**)&scol, g_scol);
    cudaGetSymbolAddress((void**)&sval, g_sval);
    cudaGetSymbolAddress((void**)&A0h, g_A0hi);
    cudaGetSymbolAddress((void**)&A0l, g_A0lo);
    cudaGetSymbolAddress((void**)&A1h, g_A1hi);
    cudaGetSymbolAddress((void**)&A1l, g_A1lo);
    cudaGetSymbolAddress((void**)&Wh, g_Whi);
    cudaGetSymbolAddress((void**)&Wl, g_Wlo);

    // ---------------- convert x + first two weights, then GEMMs back-to-back
    //                  (ordering also aims ncu -s 5 at a GEMM launch) --------
    {
        int Kpad = 2016;
        long tA = (long)NNODES * Kpad;
        convA_kernel<<<(int)((tA + 255) / 256), 256>>>(x, A0h, A0l, NIN, Kpad, tA);  // launch 1
    }
    conv_w(t1_w, NIN, 500, Wh, Wl, 0);                                               // launch 2
    conv_w(enc1_w, NIN, D1, Wh, Wl, 1);                                              // launch 3
    gemm_run(A0h, A0l, nullptr, g, nullptr, nullptr, NNODES, 500, NIN, 0, Wh, Wl, 0);   // launch 4 (t1 GEMM)
    gemm_run(A0h, A0l, enc1_b, nullptr, A1h, A1l, NNODES, D1, NIN, 2, Wh, Wl, 1);       // launch 5 (enc1)

    // ---------------- rest of AE chain ----------------
    gemm_pre(A1h, A1l, enc2_w, enc2_b, nullptr, A0h, A0l, NNODES, D2, D1, 2, Wh, Wl);
    gemm_pre(A0h, A0l, enc3_w, enc3_b, nullptr, A1h, A1l, NNODES, D3, D2, 2, Wh, Wl);
    gemm_pre(A1h, A1l, zl_w, zl_b, z, A0h, A0l, NNODES, NZC, D3, 1, Wh, Wl);
    gemm_pre(A0h, A0l, dec1_w, dec1_b, nullptr, A1h, A1l, NNODES, 2000, NZC, 2, Wh, Wl);
    gemm_pre(A1h, A1l, dec2_w, dec2_b, nullptr, A0h, A0l, NNODES, 500, 2000, 2, Wh, Wl);
    gemm_pre(A0h, A0l, dec3_w, dec3_b, nullptr, A1h, A1l, NNODES, 500, 500, 2, Wh, Wl);
    gemm_pre(A1h, A1l, xbar_w, xbar_b, out_xbar, nullptr, nullptr, NNODES, NIN, 500, 1, Wh, Wl);

    // ---------------- CSR build (needed before first spmm) ----------------
    csr_zero_kernel<<<(NNODES + 256) / 256, 256>>>(cnt);
    csr_count_kernel<<<(E + 255) / 256, 256>>>(adj_row, cnt, E);
    csr_scan_kernel<<<1, 1024>>>(cnt, rowptr, wp);
    csr_scatter_kernel<<<(E + 255) / 256, 256>>>(adj_row, adj_col, adj_val, wp, scol, sval, E);

    // ---------------- topo GCN stack ----------------
    spmm_csr(g, traw, 500, 0, rowptr, scol, sval);
    batchnorm(traw, t1, NNODES, 500, mean, rstd, A0h, A0l, 512);
    gemm_pre(A0h, A0l, t2_w, nullptr, g, nullptr, nullptr, NNODES, 500, 500, 0, Wh, Wl);

    spmm_csr(g, traw, 500, 0, rowptr, scol, sval);
    batchnorm(traw, t2, NNODES, 500, mean, rstd, A0h, A0l, 512);
    gemm_pre(A0h, A0l, t3_w, nullptr, g, nullptr, nullptr, NNODES, 2000, 500, 0, Wh, Wl);

    spmm_csr(g, traw, 2000, 0, rowptr, scol, sval);
    batchnorm(traw, t3, NNODES, 2000, mean, rstd, A0h, A0l, 2016);
    gemm_pre(A0h, A0l, t4_w, nullptr, g, nullptr, nullptr, NNODES, NZC, 2000, 0, Wh, Wl);

    spmm_csr(g, traw, NZC, 0, rowptr, scol, sval);
    batchnorm(traw, t4, NNODES, NZC, mean, rstd);

    // ---------------- MLP gate u + z_in + agcn ----------------
    u_kernel<<<(NNODES * 32 + 255) / 256, 256>>>(t1, t2, t3, t4, mlpl_w, mlpl_b, u);
    {
        long total = (long)NNODES * 3072;
        zin_conv_kernel<<<(int)((total + 255) / 256), 256>>>(t1, t2, t3, t4, u, A0h, A0l);
    }
    gemm_pre(A0h, A0l, agcn_w, nullptr, g, nullptr, nullptr, NNODES, NZC, COMS_D, 0, Wh, Wl);
    spmm_csr(g, traw, NZC, 1, rowptr, scol, sval);
    batchnorm(traw, ztopo, NNODES, NZC, mean, rstd);

    // ---------------- fused attention + emb BN ----------------
    att_fused_kernel<<<(NNODES + 3) / 4, 256>>>(z, ztopo, att_w1, att_b1, att_w2, embp);
    batchnorm(embp, out_emb, NNODES, NZC, mean, rstd);

    // ---------------- heads: pred softmax + Student-t q ----------------
    heads_kernel<<<NNODES, 64>>>(out_emb, z, cluster, out_pred, out_q);
}

// round 12
// speedup vs baseline: 1.0399x; 1.0399x over previous
#include <cuda_runtime.h>
#include <cuda_bf16.h>
#include <math.h>
#include <stdint.h>

// ---------------------------------------------------------------------------
// Problem constants
// ---------------------------------------------------------------------------
#define NNODES 10000
#define NIN    2000
#define D1     500
#define D2     500
#define D3     2000
#define NZC    64
#define COMS_D 3064
#define EMAX   131072
#define WOFF   (2u * 1024u * 1024u)

// ---------------------------------------------------------------------------
// Scratch (device globals; no allocations allowed)
// ---------------------------------------------------------------------------
__device__ float g_zbuf [NNODES * NZC];
__device__ float g_gbuf [NNODES * 2000];
__device__ float g_traw [NNODES * 2000];
__device__ float g_t1[NNODES * 500];
__device__ float g_t2[NNODES * 500];
__device__ float g_t3[NNODES * 2000];
__device__ float g_t4[NNODES * NZC];
__device__ float g_u [NNODES * 5];
__device__ float g_ztopo[NNODES * NZC];
__device__ float g_embp[NNODES * NZC];
__device__ float g_mean[4096];
__device__ float g_rstd[4096];

// CSR build
__device__ int   g_cnt[NNODES + 1];
__device__ int   g_rowptr[NNODES + 1];
__device__ int   g_wp[NNODES];
__device__ int   g_scol[EMAX];
__device__ float g_sval[EMAX];

// bf16 split-precision ping-pong A buffers + weight buffers (2 regions)
__device__ __align__(256) __nv_bfloat16 g_A0hi[(size_t)NNODES * 3072];
__device__ __align__(256) __nv_bfloat16 g_A0lo[(size_t)NNODES * 3072];
__device__ __align__(256) __nv_bfloat16 g_A1hi[(size_t)NNODES * 3072];
__device__ __align__(256) __nv_bfloat16 g_A1lo[(size_t)NNODES * 3072];
__device__ __align__(256) __nv_bfloat16 g_Whi[2048 * 3072];
__device__ __align__(256) __nv_bfloat16 g_Wlo[2048 * 3072];

// ---------------------------------------------------------------------------
// PTX helpers
// ---------------------------------------------------------------------------
__device__ __forceinline__ void ldsm4(uint32_t* r, uint32_t addr) {
    asm volatile("ldmatrix.sync.aligned.m8n8.x4.shared.b16 {%0,%1,%2,%3}, [%4];"
                 : "=r"(r[0]), "=r"(r[1]), "=r"(r[2]), "=r"(r[3]) : "r"(addr));
}
__device__ __forceinline__ uint32_t smem_u32(const void* p) {
    uint32_t a;
    asm("{ .reg .u64 t; cvta.to.shared.u64 t, %1; cvt.u32.u64 %0, t; }" : "=r"(a) : "l"(p));
    return a;
}
__device__ __forceinline__ void mma16816(float* c, const uint32_t* a, const uint32_t* b) {
    asm volatile(
        "mma.sync.aligned.m16n8k16.row.col.f32.bf16.bf16.f32 "
        "{%0,%1,%2,%3}, {%4,%5,%6,%7}, {%8,%9}, {%0,%1,%2,%3};"
        : "+f"(c[0]), "+f"(c[1]), "+f"(c[2]), "+f"(c[3])
        : "r"(a[0]), "r"(a[1]), "r"(a[2]), "r"(a[3]), "r"(b[0]), "r"(b[1]));
}
__device__ __forceinline__ void split_bf16(float v, __nv_bfloat16& h, __nv_bfloat16& l) {
    h = __float2bfloat16(v);
    l = __float2bfloat16(v - __bfloat162float(h));
}
__device__ __forceinline__ void cpa16(uint32_t dst, const void* src) {
    asm volatile("cp.async.cg.shared.global [%0], [%1], 16;" :: "r"(dst), "l"(src));
}
__device__ __forceinline__ void cp_commit() {
    asm volatile("cp.async.commit_group;" ::: "memory");
}
template<int N>
__device__ __forceinline__ void cp_wait() {
    asm volatile("cp.async.wait_group %0;" :: "n"(N) : "memory");
}

// ---------------------------------------------------------------------------
// Split-bf16 mma.sync GEMM: BM=128, BN=64, BK=32, 256 threads (4m x 2n warps,
// 32x32 warp tiles). cp.async 2-stage ring. Batched ldsm: all 16 fragment
// loads of a chunk are issued first, then 48 back-to-back mma.
// C may be nullptr. mode: 0 none, 1 +bias, 2 +bias+elu
// ---------------------------------------------------------------------------
#define ROWB 80
#define A_BYTES (128 * ROWB)                      // 10240
#define B_BYTES (64 * ROWB)                       // 5120
#define STAGE_BYTES (2 * A_BYTES + 2 * B_BYTES)   // 30720
#define GEMM_DSMEM (2 * STAGE_BYTES)              // 61440

__device__ __forceinline__ void load_stage_async(
    uint32_t sbase,
    const __nv_bfloat16* __restrict__ Ahi, const __nv_bfloat16* __restrict__ Alo,
    const __nv_bfloat16* __restrict__ Bhi, const __nv_bfloat16* __restrict__ Blo,
    int mBase, int M, int nBase, int N, int Kpad, int k0, int tid)
{
#pragma unroll
    for (int it = 0; it < 2; it++) {
        int t = tid + it * 256;
        int row = t >> 2, seg = t & 3;
        int gr = mBase + row;
        int sr = (gr < M) ? gr : 0;
        size_t aoff = (size_t)sr * Kpad + k0 + seg * 8;
        uint32_t d = sbase + row * ROWB + seg * 16;
        cpa16(d,           Ahi + aoff);
        cpa16(d + A_BYTES, Alo + aoff);
    }
    {
        int row = tid >> 2, seg = tid & 3;
        int gn = nBase + row;
        int sn = (gn < N) ? gn : 0;
        size_t boff = (size_t)sn * Kpad + k0 + seg * 8;
        uint32_t d = sbase + 2 * A_BYTES + row * ROWB + seg * 16;
        cpa16(d,           Bhi + boff);
        cpa16(d + B_BYTES, Blo + boff);
    }
}

__global__ __launch_bounds__(256, 2) void mma_gemm_kernel(
    const __nv_bfloat16* __restrict__ Ahi, const __nv_bfloat16* __restrict__ Alo,
    const __nv_bfloat16* __restrict__ Bhi, const __nv_bfloat16* __restrict__ Blo,
    const float* __restrict__ bias, float* __restrict__ C,
    __nv_bfloat16* __restrict__ outHi, __nv_bfloat16* __restrict__ outLo, int KpadOut,
    int M, int Ncol, int Kpad, int mode)
{
    extern __shared__ __align__(256) char smem[];
    uint32_t sb = smem_u32(smem);
    int tid = threadIdx.x;
    int wid = tid >> 5, lane = tid & 31;
    int wm = wid & 3, wn = wid >> 2;
    int mBase = blockIdx.y * 128;
    int nBase = blockIdx.x * 64;

    float acc[2][4][4];
#pragma unroll
    for (int mt = 0; mt < 2; mt++)
#pragma unroll
        for (int nt = 0; nt < 4; nt++)
#pragma unroll
            for (int r = 0; r < 4; r++) acc[mt][nt][r] = 0.f;

    const int nc = Kpad >> 5;

    load_stage_async(sb, Ahi, Alo, Bhi, Blo, mBase, M, nBase, Ncol, Kpad, 0, tid);
    cp_commit();
    if (nc > 1) {
        load_stage_async(sb + STAGE_BYTES, Ahi, Alo, Bhi, Blo, mBase, M, nBase, Ncol, Kpad, 32, tid);
        cp_commit();
    }

    int lrow = (lane & 7) + ((lane >> 3) & 1) * 8;
    int lcol8 = (lane >> 4) * 8;

    for (int c = 0; c < nc; c++) {
        if (c + 1 < nc) cp_wait<1>(); else cp_wait<0>();
        __syncthreads();

        uint32_t bufU = sb + (c & 1) * STAGE_BYTES;
        uint32_t aHiS = bufU;
        uint32_t aLoS = bufU + A_BYTES;
        uint32_t bHiS = bufU + 2 * A_BYTES;
        uint32_t bLoS = bHiS + B_BYTES;

        // ---- batched fragment loads: all 16 ldsm first ----
        uint32_t ah[2][2][4], al[2][2][4], bh[2][4][2], bl[2][4][2];
#pragma unroll
        for (int ks = 0; ks < 2; ks++) {
            int kc = ks * 16 + lcol8;
#pragma unroll
            for (int mt = 0; mt < 2; mt++) {
                uint32_t o = (wm * 32 + mt * 16 + lrow) * ROWB + kc * 2;
                ldsm4(ah[ks][mt], aHiS + o);
                ldsm4(al[ks][mt], aLoS + o);
            }
#pragma unroll
            for (int ntp = 0; ntp < 2; ntp++) {
                uint32_t o = (wn * 32 + ntp * 16 + lrow) * ROWB + kc * 2;
                uint32_t t[4];
                ldsm4(t, bHiS + o);
                bh[ks][2 * ntp][0] = t[0]; bh[ks][2 * ntp][1] = t[2];
                bh[ks][2 * ntp + 1][0] = t[1]; bh[ks][2 * ntp + 1][1] = t[3];
                ldsm4(t, bLoS + o);
                bl[ks][2 * ntp][0] = t[0]; bl[ks][2 * ntp][1] = t[2];
                bl[ks][2 * ntp + 1][0] = t[1]; bl[ks][2 * ntp + 1][1] = t[3];
            }
        }
        // ---- 48 back-to-back mma ----
#pragma unroll
        for (int ks = 0; ks < 2; ks++)
#pragma unroll
            for (int mt = 0; mt < 2; mt++)
#pragma unroll
                for (int nt = 0; nt < 4; nt++) {
                    mma16816(acc[mt][nt], ah[ks][mt], bh[ks][nt]);
                    mma16816(acc[mt][nt], ah[ks][mt], bl[ks][nt]);
                    mma16816(acc[mt][nt], al[ks][mt], bh[ks][nt]);
                }
        __syncthreads();
        if (c + 2 < nc) {
            load_stage_async(sb + (c & 1) * STAGE_BYTES, Ahi, Alo, Bhi, Blo,
                             mBase, M, nBase, Ncol, Kpad, (c + 2) * 32, tid);
            cp_commit();
        }
    }

    // Epilogue
    int qr = lane >> 2;
    int qc = (lane & 3) * 2;
#pragma unroll
    for (int mt = 0; mt < 2; mt++) {
#pragma unroll
        for (int nt = 0; nt < 4; nt++) {
#pragma unroll
            for (int half = 0; half < 2; half++) {
                int gr = mBase + wm * 32 + mt * 16 + qr + half * 8;
                if (gr >= M) continue;
#pragma unroll
                for (int e = 0; e < 2; e++) {
                    int gc = nBase + wn * 32 + nt * 8 + qc + e;
                    float v = acc[mt][nt][half * 2 + e];
                    if (gc < Ncol) {
                        if (mode >= 1) v += bias[gc];
                        if (mode == 2) v = v > 0.f ? v : expm1f(v);
                        if (C) C[(size_t)gr * Ncol + gc] = v;
                    } else {
                        v = 0.f;
                    }
                    if (outHi && gc < KpadOut) {
                        __nv_bfloat16 h, l;
                        split_bf16(v, h, l);
                        outHi[(size_t)gr * KpadOut + gc] = h;
                        outLo[(size_t)gr * KpadOut + gc] = l;
                    }
                }
            }
        }
    }
}

// ---------------------------------------------------------------------------
// Conversions
// ---------------------------------------------------------------------------
__global__ void convA_kernel(const float* __restrict__ src,
                             __nv_bfloat16* __restrict__ hi, __nv_bfloat16* __restrict__ lo,
                             int K, int Kpad, long total)
{
    long i = (long)blockIdx.x * blockDim.x + threadIdx.x;
    if (i >= total) return;
    long r = i / Kpad;
    int  k = (int)(i - r * Kpad);
    float v = (k < K) ? src[r * K + k] : 0.f;
    __nv_bfloat16 h, l;
    split_bf16(v, h, l);
    hi[i] = h; lo[i] = l;
}

__global__ void convBT_kernel(const float* __restrict__ B,
                              __nv_bfloat16* __restrict__ bhi, __nv_bfloat16* __restrict__ blo,
                              int K, int N, int Kpad)
{
    __shared__ float sm[32][33];
    int k0 = blockIdx.x * 32, n0 = blockIdx.y * 32;
    int tx = threadIdx.x, ty = threadIdx.y;
    for (int i = ty; i < 32; i += 8) {
        int k = k0 + i, n = n0 + tx;
        sm[i][tx] = (k < K && n < N) ? B[(size_t)k * N + n] : 0.f;
    }
    __syncthreads();
    for (int i = ty; i < 32; i += 8) {
        int n = n0 + i, k = k0 + tx;
        if (n < N && k < Kpad) {
            __nv_bfloat16 h, l;
            split_bf16(sm[tx][i], h, l);
            bhi[(size_t)n * Kpad + k] = h;
            blo[(size_t)n * Kpad + k] = l;
        }
    }
}

// ---------------------------------------------------------------------------
// CSR build + CSR SpMM with fused activation
// ---------------------------------------------------------------------------
__global__ void csr_zero_kernel(int* cnt) {
    int i = blockIdx.x * blockDim.x + threadIdx.x;
    if (i <= NNODES) cnt[i] = 0;
}
__global__ void csr_count_kernel(const int* __restrict__ row, int* cnt, int E) {
    int e = blockIdx.x * blockDim.x + threadIdx.x;
    if (e < E) atomicAdd(&cnt[row[e] + 1], 1);
}
#define SCAN_PER 10
__global__ __launch_bounds__(1024) void csr_scan_kernel(const int* __restrict__ cnt,
                                                        int* rowptr, int* wp)
{
    __shared__ int sh[1024];
    int t = threadIdx.x;
    int base = t * SCAN_PER;
    int local[SCAN_PER];
    int s = 0;
#pragma unroll
    for (int i = 0; i < SCAN_PER; i++) {
        int idx = base + i;
        int v = (idx < NNODES) ? cnt[idx + 1] : 0;
        s += v;
        local[i] = s;
    }
    sh[t] = s;
    __syncthreads();
    for (int off = 1; off < 1024; off <<= 1) {
        int v = (t >= off) ? sh[t - off] : 0;
        __syncthreads();
        sh[t] += v;
        __syncthreads();
    }
    int prev = (t > 0) ? sh[t - 1] : 0;
    if (t == 0) rowptr[0] = 0;
#pragma unroll
    for (int i = 0; i < SCAN_PER; i++) {
        int idx = base + i;
        if (idx < NNODES) {
            rowptr[idx + 1] = prev + local[i];
            wp[idx] = (i == 0) ? prev : prev + local[i - 1];
        }
    }
}
__global__ void csr_scatter_kernel(const int* __restrict__ row, const int* __restrict__ col,
                                   const float* __restrict__ val, int* wp,
                                   int* scol, float* sval, int E)
{
    int e = blockIdx.x * blockDim.x + threadIdx.x;
    if (e >= E) return;
    int p = atomicAdd(&wp[row[e]], 1);
    scol[p] = col[e];
    sval[p] = val[e];
}

__global__ void spmm_csr_kernel(const float* __restrict__ H,
                                const int* __restrict__ rowptr,
                                const int* __restrict__ scol, const float* __restrict__ sval,
                                float* __restrict__ out, int D, int actmode)
{
    int r = blockIdx.x;
    int s = rowptr[r], e_end = rowptr[r + 1];
    int nt = blockDim.x;
    float acc[8];
    int nreg = (D + nt - 1) / nt;
#pragma unroll 8
    for (int i = 0; i < 8; i++) acc[i] = 0.f;
    for (int e = s; e < e_end; e++) {
        int c = scol[e];
        float v = sval[e];
        const float* hrow = H + (size_t)c * D;
#pragma unroll 8
        for (int i = 0; i < 8; i++) {
            if (i >= nreg) break;
            int d = threadIdx.x + i * nt;
            if (d < D) acc[i] = fmaf(v, hrow[d], acc[i]);
        }
    }
#pragma unroll 8
    for (int i = 0; i < 8; i++) {
        if (i >= nreg) break;
        int d = threadIdx.x + i * nt;
        if (d < D) {
            float o = acc[i];
            if (actmode == 0) o = o > 0.f ? o : expm1f(0.2f * o);
            else if (actmode == 1) o = o > 0.f ? o : expm1f(o);
            out[(size_t)r * D + d] = o;
        }
    }
}
static inline void spmm_csr(const float* H, float* out, int D, int actmode,
                            const int* rowptr, const int* scol, const float* sval)
{
    int threads = (D >= 256) ? 256 : ((D + 31) & ~31);
    spmm_csr_kernel<<<NNODES, threads>>>(H, rowptr, scol, sval, out, D, actmode);
}

// ---------------------------------------------------------------------------
// BatchNorm
// ---------------------------------------------------------------------------
__global__ void bn_stats_kernel(const float* __restrict__ h, int n, int d,
                                float* __restrict__ mean, float* __restrict__ rstd)
{
    __shared__ float ssum[8][32];
    __shared__ float ssq[8][32];
    int c = blockIdx.x * 32 + threadIdx.x;
    float s = 0.f, q = 0.f;
    if (c < d) {
        for (int r = threadIdx.y; r < n; r += 8) {
            float v = h[(size_t)r * d + c];
            s += v; q += v * v;
        }
    }
    ssum[threadIdx.y][threadIdx.x] = s;
    ssq[threadIdx.y][threadIdx.x] = q;
    __syncthreads();
    if (threadIdx.y == 0 && c < d) {
#pragma unroll
        for (int i = 1; i < 8; i++) { s += ssum[i][threadIdx.x]; q += ssq[i][threadIdx.x]; }
        float m = s / (float)n;
        float var = q / (float)n - m * m;
        if (var < 0.f) var = 0.f;
        mean[c] = m;
        rstd[c] = rsqrtf(var + 1e-5f);
    }
}
__global__ void bn_apply_kernel(const float* __restrict__ src, float* __restrict__ dst,
                                long total, int d, int Kpad,
                                const float* __restrict__ mean, const float* __restrict__ rstd,
                                __nv_bfloat16* __restrict__ outHi, __nv_bfloat16* __restrict__ outLo)
{
    long i = (long)blockIdx.x * blockDim.x + threadIdx.x;
    if (i >= total) return;
    long r = i / Kpad;
    int  c = (int)(i - r * Kpad);
    float v = 0.f;
    if (c < d) {
        v = (src[r * d + c] - mean[c]) * rstd[c];
        dst[r * d + c] = v;
    }
    if (outHi) {
        __nv_bfloat16 h, l;
        split_bf16(v, h, l);
        outHi[i] = h; outLo[i] = l;
    }
}
static inline void batchnorm(const float* src, float* dst, int n, int d,
                             float* mean, float* rstd,
                             __nv_bfloat16* outHi = nullptr, __nv_bfloat16* outLo = nullptr,
                             int Kpad = 0)
{
    dim3 bt(32, 8);
    bn_stats_kernel<<<(d + 31) / 32, bt>>>(src, n, d, mean, rstd);
    int kp = outHi ? Kpad : d;
    long total = (long)n * kp;
    bn_apply_kernel<<<(int)((total + 255) / 256), 256>>>(src, dst, total, d, kp, mean, rstd, outHi, outLo);
}

// ---------------------------------------------------------------------------
// Gate u, z_in, fused attention, heads
// ---------------------------------------------------------------------------
__device__ __forceinline__ float coms_at(const float* t1, const float* t2,
                                         const float* t3, const float* t4,
                                         int n, int k)
{
    if (k < 500)  return t1[(size_t)n * 500 + k];
    if (k < 1000) return t2[(size_t)n * 500 + (k - 500)];
    if (k < 3000) return t3[(size_t)n * 2000 + (k - 1000)];
    return t4[(size_t)n * 64 + (k - 3000)];
}

__global__ void u_kernel(const float* __restrict__ t1, const float* __restrict__ t2,
                         const float* __restrict__ t3, const float* __restrict__ t4,
                         const float* __restrict__ W, const float* __restrict__ b,
                         float* __restrict__ u)
{
    int warp = (blockIdx.x * blockDim.x + threadIdx.x) >> 5;
    int lane = threadIdx.x & 31;
    if (warp >= NNODES) return;
    float acc[5] = {0.f, 0.f, 0.f, 0.f, 0.f};
    for (int k = lane; k < COMS_D; k += 32) {
        float v = coms_at(t1, t2, t3, t4, warp, k);
        const float* w = &W[(size_t)k * 5];
#pragma unroll
        for (int j = 0; j < 5; j++) acc[j] = fmaf(v, w[j], acc[j]);
    }
#pragma unroll
    for (int j = 0; j < 5; j++) {
        for (int off = 16; off > 0; off >>= 1)
            acc[j] += __shfl_down_sync(0xFFFFFFFF, acc[j], off);
    }
    if (lane == 0) {
        float l[5], m = -1e30f;
#pragma unroll
        for (int j = 0; j < 5; j++) { l[j] = tanhf(acc[j] + b[j]); m = fmaxf(m, l[j]); }
        float s = 0.f;
#pragma unroll
        for (int j = 0; j < 5; j++) { l[j] = expf(l[j] - m); s += l[j]; }
        float nrm = 0.f;
#pragma unroll
        for (int j = 0; j < 5; j++) { l[j] /= s; nrm += l[j] * l[j]; }
        nrm = fmaxf(sqrtf(nrm), 1e-12f);
#pragma unroll
        for (int j = 0; j < 5; j++) u[(size_t)warp * 5 + j] = l[j] / nrm;
    }
}

__global__ void zin_conv_kernel(const float* __restrict__ t1, const float* __restrict__ t2,
                                const float* __restrict__ t3, const float* __restrict__ t4,
                                const float* __restrict__ u,
                                __nv_bfloat16* __restrict__ hi, __nv_bfloat16* __restrict__ lo)
{
    long i = (long)blockIdx.x * blockDim.x + threadIdx.x;
    long total = (long)NNODES * 3072;
    if (i >= total) return;
    int n = (int)(i / 3072);
    int k = (int)(i % 3072);
    float v = 0.f;
    if (k < COMS_D) {
        int seg = (k < 500) ? 0 : (k < 1000) ? 1 : (k < 3000) ? 2 : 3;
        v = u[(size_t)n * 5 + seg] * coms_at(t1, t2, t3, t4, n, k);
    }
    __nv_bfloat16 h, l;
    split_bf16(v, h, l);
    hi[i] = h; lo[i] = l;
}

__global__ __launch_bounds__(256) void att_fused_kernel(
    const float* __restrict__ z, const float* __restrict__ ztopo,
    const float* __restrict__ W1, const float* __restrict__ b1,
    const float* __restrict__ w2, float* __restrict__ embp)
{
    __shared__ float sW1[64 * 128];
    __shared__ float sb1[128];
    __shared__ float sw2[128];
    __shared__ float sS[8][64];
    __shared__ float sc[8];
    int tid = threadIdx.x;
    for (int i = tid; i < 64 * 128; i += 256) sW1[i] = W1[i];
    if (tid < 128) { sb1[tid] = b1[tid]; sw2[tid] = w2[tid]; }

    int wid = tid >> 5, lane = tid & 31;
    int nodeBase = blockIdx.x * 4;
    int n = nodeBase + (wid >> 1);
    int br = wid & 1;
    bool valid = (n < NNODES);
    if (valid) {
        const float* s = br ? &ztopo[(size_t)n * 64] : &z[(size_t)n * 64];
        sS[wid][lane] = s[lane];
        sS[wid][lane + 32] = s[lane + 32];
    }
    __syncthreads();

    float partial = 0.f;
    if (valid) {
#pragma unroll
        for (int jj = 0; jj < 4; jj++) {
            int j = lane + jj * 32;
            float h = sb1[j];
#pragma unroll
            for (int k = 0; k < 64; k++)
                h = fmaf(sS[wid][k], sW1[k * 128 + j], h);
            partial = fmaf(tanhf(h), sw2[j], partial);
        }
    }
    for (int off = 16; off > 0; off >>= 1)
        partial += __shfl_down_sync(0xFFFFFFFF, partial, off);
    if (lane == 0) sc[wid] = partial;
    __syncthreads();

    int nl = tid >> 6;
    int d  = tid & 63;
    int n2 = nodeBase + nl;
    if (n2 < NNODES) {
        float s0 = sc[nl * 2], s1 = sc[nl * 2 + 1];
        float m = fmaxf(s0, s1);
        float e0 = expf(s0 - m), e1 = expf(s1 - m);
        float inv = 1.f / (e0 + e1);
        embp[(size_t)n2 * 64 + d] = (e0 * inv) * z[(size_t)n2 * 64 + d]
                                  + (e1 * inv) * ztopo[(size_t)n2 * 64 + d];
    }
}

__global__ void heads_kernel(const float* __restrict__ emb, const float* __restrict__ z,
                             const float* __restrict__ cluster,
                             float* __restrict__ pred, float* __restrict__ q)
{
    int n = blockIdx.x;
    int t = threadIdx.x;
    __shared__ float sh[64];
    __shared__ float zs[64];

    float v = emb[(size_t)n * 64 + t];
    sh[t] = v;
    __syncthreads();
    for (int s = 32; s > 0; s >>= 1) {
        if (t < s) sh[t] = fmaxf(sh[t], sh[t + s]);
        __syncthreads();
    }
    float m = sh[0];
    __syncthreads();
    float e = expf(v - m);
    sh[t] = e;
    __syncthreads();
    for (int s = 32; s > 0; s >>= 1) {
        if (t < s) sh[t] += sh[t + s];
        __syncthreads();
    }
    pred[(size_t)n * 64 + t] = e / sh[0];
    __syncthreads();

    zs[t] = z[(size_t)n * 64 + t];
    __syncthreads();
    float d2 = 0.f;
    const float* c = &cluster[(size_t)t * 64];
    for (int k = 0; k < 64; k++) {
        float diff = zs[k] - c[k];
        d2 = fmaf(diff, diff, d2);
    }
    float qv = 1.f / (1.f + d2);
    sh[t] = qv;
    __syncthreads();
    for (int s = 32; s > 0; s >>= 1) {
        if (t < s) sh[t] += sh[t + s];
        __syncthreads();
    }
    q[(size_t)n * 64 + t] = qv / sh[0];
}

// ---------------------------------------------------------------------------
// Host-side helpers
// ---------------------------------------------------------------------------
static inline void conv_w(const float* Bw, int K, int N,
                          __nv_bfloat16* Whi, __nv_bfloat16* Wlo, int wsel)
{
    int Kpad = (K + 31) & ~31;
    dim3 tg((Kpad + 31) / 32, (N + 31) / 32);
    convBT_kernel<<<tg, dim3(32, 8)>>>(Bw, Whi + (size_t)wsel * WOFF, Wlo + (size_t)wsel * WOFF, K, N, Kpad);
}

static inline void gemm_run(const __nv_bfloat16* aHi, const __nv_bfloat16* aLo,
                            const float* bias, float* C,
                            __nv_bfloat16* outHi, __nv_bfloat16* outLo,
                            int M, int N, int K, int mode,
                            __nv_bfloat16* Whi, __nv_bfloat16* Wlo, int wsel)
{
    int Kpad = (K + 31) & ~31;
    int KpadOut = (N + 31) & ~31;
    cudaFuncSetAttribute(mma_gemm_kernel, cudaFuncAttributeMaxDynamicSharedMemorySize, GEMM_DSMEM);
    dim3 grid((N + 63) / 64, (M + 127) / 128);
    mma_gemm_kernel<<<grid, 256, GEMM_DSMEM>>>(aHi, aLo,
                                               Whi + (size_t)wsel * WOFF, Wlo + (size_t)wsel * WOFF,
                                               bias, C, outHi, outLo, KpadOut, M, N, Kpad, mode);
}

static inline void gemm_pre(const __nv_bfloat16* aHi, const __nv_bfloat16* aLo,
                            const float* Bw, const float* bias, float* C,
                            __nv_bfloat16* outHi, __nv_bfloat16* outLo,
                            int M, int N, int K, int mode,
                            __nv_bfloat16* Whi, __nv_bfloat16* Wlo)
{
    conv_w(Bw, K, N, Whi, Wlo, 0);
    gemm_run(aHi, aLo, bias, C, outHi, outLo, M, N, K, mode, Whi, Wlo, 0);
}

// ---------------------------------------------------------------------------
// Launch
// ---------------------------------------------------------------------------
extern "C" void kernel_launch(void* const* d_in, const int* in_sizes, int n_in,
                              void* d_out, int out_size)
{
    const float* x       = (const float*)d_in[0];
    const float* adj_val = (const float*)d_in[1];
    const float* enc1_w  = (const float*)d_in[2];
    const float* enc1_b  = (const float*)d_in[3];
    const float* enc2_w  = (const float*)d_in[4];
    const float* enc2_b  = (const float*)d_in[5];
    const float* enc3_w  = (const float*)d_in[6];
    const float* enc3_b  = (const float*)d_in[7];
    const float* zl_w    = (const float*)d_in[8];
    const float* zl_b    = (const float*)d_in[9];
    const float* dec1_w  = (const float*)d_in[10];
    const float* dec1_b  = (const float*)d_in[11];
    const float* dec2_w  = (const float*)d_in[12];
    const float* dec2_b  = (const float*)d_in[13];
    const float* dec3_w  = (const float*)d_in[14];
    const float* dec3_b  = (const float*)d_in[15];
    const float* xbar_w  = (const float*)d_in[16];
    const float* xbar_b  = (const float*)d_in[17];
    const float* t1_w    = (const float*)d_in[18];
    const float* t2_w    = (const float*)d_in[19];
    const float* t3_w    = (const float*)d_in[20];
    const float* t4_w    = (const float*)d_in[21];
    const float* agcn_w  = (const float*)d_in[22];
    const float* mlpl_w  = (const float*)d_in[23];
    const float* mlpl_b  = (const float*)d_in[24];
    const float* att_w1  = (const float*)d_in[25];
    const float* att_b1  = (const float*)d_in[26];
    const float* att_w2  = (const float*)d_in[27];
    const float* cluster = (const float*)d_in[28];
    const int*   adj_row = (const int*)d_in[29];
    const int*   adj_col = (const int*)d_in[30];
    const int E = in_sizes[1];

    float* out      = (float*)d_out;
    float* out_xbar = out;
    float* out_q    = out + (size_t)NNODES * NIN;
    float* out_pred = out_q + (size_t)NNODES * NZC;
    float* out_emb  = out_pred + (size_t)NNODES * NZC;

    float *z, *g, *traw, *t1, *t2, *t3, *t4, *u, *ztopo, *embp, *mean, *rstd;
    int *cnt, *rowptr, *wp, *scol;
    float *sval;
    __nv_bfloat16 *A0h, *A0l, *A1h, *A1l, *Wh, *Wl;
    cudaGetSymbolAddress((void**)&z,  g_zbuf);
    cudaGetSymbolAddress((void**)&g,  g_gbuf);
    cudaGetSymbolAddress((void**)&traw, g_traw);
    cudaGetSymbolAddress((void**)&t1, g_t1);
    cudaGetSymbolAddress((void**)&t2, g_t2);
    cudaGetSymbolAddress((void**)&t3, g_t3);
    cudaGetSymbolAddress((void**)&t4, g_t4);
    cudaGetSymbolAddress((void**)&u,  g_u);
    cudaGetSymbolAddress((void**)&ztopo, g_ztopo);
    cudaGetSymbolAddress((void**)&embp, g_embp);
    cudaGetSymbolAddress((void**)&mean, g_mean);
    cudaGetSymbolAddress((void**)&rstd, g_rstd);
    cudaGetSymbolAddress((void**)&cnt, g_cnt);
    cudaGetSymbolAddress((void**)&rowptr, g_rowptr);
    cudaGetSymbolAddress((void**)&wp, g_wp);
    cudaGetSymbolAddress((void**)&scol, g_scol);
    cudaGetSymbolAddress((void**)&sval, g_sval);
    cudaGetSymbolAddress((void**)&A0h, g_A0hi);
    cudaGetSymbolAddress((void**)&A0l, g_A0lo);
    cudaGetSymbolAddress((void**)&A1h, g_A1hi);
    cudaGetSymbolAddress((void**)&A1l, g_A1lo);
    cudaGetSymbolAddress((void**)&Wh, g_Whi);
    cudaGetSymbolAddress((void**)&Wl, g_Wlo);

    // ---------------- convert x + first two weights, then GEMMs back-to-back
    {
        int Kpad = 2016;
        long tA = (long)NNODES * Kpad;
        convA_kernel<<<(int)((tA + 255) / 256), 256>>>(x, A0h, A0l, NIN, Kpad, tA);
    }
    conv_w(t1_w, NIN, 500, Wh, Wl, 0);
    conv_w(enc1_w, NIN, D1, Wh, Wl, 1);
    gemm_run(A0h, A0l, nullptr, g, nullptr, nullptr, NNODES, 500, NIN, 0, Wh, Wl, 0);
    gemm_run(A0h, A0l, enc1_b, nullptr, A1h, A1l, NNODES, D1, NIN, 2, Wh, Wl, 1);

    // ---------------- rest of AE chain ----------------
    gemm_pre(A1h, A1l, enc2_w, enc2_b, nullptr, A0h, A0l, NNODES, D2, D1, 2, Wh, Wl);
    gemm_pre(A0h, A0l, enc3_w, enc3_b, nullptr, A1h, A1l, NNODES, D3, D2, 2, Wh, Wl);
    gemm_pre(A1h, A1l, zl_w, zl_b, z, A0h, A0l, NNODES, NZC, D3, 1, Wh, Wl);
    gemm_pre(A0h, A0l, dec1_w, dec1_b, nullptr, A1h, A1l, NNODES, 2000, NZC, 2, Wh, Wl);
    gemm_pre(A1h, A1l, dec2_w, dec2_b, nullptr, A0h, A0l, NNODES, 500, 2000, 2, Wh, Wl);
    gemm_pre(A0h, A0l, dec3_w, dec3_b, nullptr, A1h, A1l, NNODES, 500, 500, 2, Wh, Wl);
    gemm_pre(A1h, A1l, xbar_w, xbar_b, out_xbar, nullptr, nullptr, NNODES, NIN, 500, 1, Wh, Wl);

    // ---------------- CSR build ----------------
    csr_zero_kernel<<<(NNODES + 256) / 256, 256>>>(cnt);
    csr_count_kernel<<<(E + 255) / 256, 256>>>(adj_row, cnt, E);
    csr_scan_kernel<<<1, 1024>>>(cnt, rowptr, wp);
    csr_scatter_kernel<<<(E + 255) / 256, 256>>>(adj_row, adj_col, adj_val, wp, scol, sval, E);

    // ---------------- topo GCN stack ----------------
    spmm_csr(g, traw, 500, 0, rowptr, scol, sval);
    batchnorm(traw, t1, NNODES, 500, mean, rstd, A0h, A0l, 512);
    gemm_pre(A0h, A0l, t2_w, nullptr, g, nullptr, nullptr, NNODES, 500, 500, 0, Wh, Wl);

    spmm_csr(g, traw, 500, 0, rowptr, scol, sval);
    batchnorm(traw, t2, NNODES, 500, mean, rstd, A0h, A0l, 512);
    gemm_pre(A0h, A0l, t3_w, nullptr, g, nullptr, nullptr, NNODES, 2000, 500, 0, Wh, Wl);

    spmm_csr(g, traw, 2000, 0, rowptr, scol, sval);
    batchnorm(traw, t3, NNODES, 2000, mean, rstd, A0h, A0l, 2016);
    gemm_pre(A0h, A0l, t4_w, nullptr, g, nullptr, nullptr, NNODES, NZC, 2000, 0, Wh, Wl);

    spmm_csr(g, traw, NZC, 0, rowptr, scol, sval);
    batchnorm(traw, t4, NNODES, NZC, mean, rstd);

    // ---------------- MLP gate u + z_in + agcn ----------------
    u_kernel<<<(NNODES * 32 + 255) / 256, 256>>>(t1, t2, t3, t4, mlpl_w, mlpl_b, u);
    {
        long total = (long)NNODES * 3072;
        zin_conv_kernel<<<(int)((total + 255) / 256), 256>>>(t1, t2, t3, t4, u, A0h, A0l);
    }
    gemm_pre(A0h, A0l, agcn_w, nullptr, g, nullptr, nullptr, NNODES, NZC, COMS_D, 0, Wh, Wl);
    spmm_csr(g, traw, NZC, 1, rowptr, scol, sval);
    batchnorm(traw, ztopo, NNODES, NZC, mean, rstd);

    // ---------------- fused attention + emb BN ----------------
    att_fused_kernel<<<(NNODES + 3) / 4, 256>>>(z, ztopo, att_w1, att_b1, att_w2, embp);
    batchnorm(embp, out_emb, NNODES, NZC, mean, rstd);

    // ---------------- heads ----------------
    heads_kernel<<<NNODES, 64>>>(out_emb, z, cluster, out_pred, out_q);
}

// round 13
// speedup vs baseline: 1.0682x; 1.0273x over previous
#include <cuda_runtime.h>
#include <cuda_bf16.h>
#include <math.h>
#include <stdint.h>

// ---------------------------------------------------------------------------
// Problem constants
// ---------------------------------------------------------------------------
#define NNODES 10000
#define NIN    2000
#define D1     500
#define D2     500
#define D3     2000
#define NZC    64
#define COMS_D 3064
#define EMAX   131072
#define WOFF   (2u * 1024u * 1024u)

// ---------------------------------------------------------------------------
// Scratch (device globals; no allocations allowed)
// ---------------------------------------------------------------------------
__device__ float g_zbuf [NNODES * NZC];
__device__ float g_gbuf [NNODES * 2000];
__device__ float g_traw [NNODES * 2000];
__device__ float g_t1[NNODES * 500];
__device__ float g_t2[NNODES * 500];
__device__ float g_t3[NNODES * 2000];
__device__ float g_t4[NNODES * NZC];
__device__ float g_u [NNODES * 5];
__device__ float g_ztopo[NNODES * NZC];
__device__ float g_embp[NNODES * NZC];
__device__ float g_mean[4096];
__device__ float g_rstd[4096];

// CSR build
__device__ int   g_cnt[NNODES + 1];
__device__ int   g_rowptr[NNODES + 1];
__device__ int   g_wp[NNODES];
__device__ int   g_scol[EMAX];
__device__ float g_sval[EMAX];

// bf16 split-precision ping-pong A buffers + weight buffers (2 regions)
__device__ __align__(256) __nv_bfloat16 g_A0hi[(size_t)NNODES * 3072];
__device__ __align__(256) __nv_bfloat16 g_A0lo[(size_t)NNODES * 3072];
__device__ __align__(256) __nv_bfloat16 g_A1hi[(size_t)NNODES * 3072];
__device__ __align__(256) __nv_bfloat16 g_A1lo[(size_t)NNODES * 3072];
__device__ __align__(256) __nv_bfloat16 g_Whi[2048 * 3072];
__device__ __align__(256) __nv_bfloat16 g_Wlo[2048 * 3072];

// ---------------------------------------------------------------------------
// PTX helpers
// ---------------------------------------------------------------------------
__device__ __forceinline__ void ldsm4(uint32_t* r, uint32_t addr) {
    asm volatile("ldmatrix.sync.aligned.m8n8.x4.shared.b16 {%0,%1,%2,%3}, [%4];"
                 : "=r"(r[0]), "=r"(r[1]), "=r"(r[2]), "=r"(r[3]) : "r"(addr));
}
__device__ __forceinline__ uint32_t smem_u32(const void* p) {
    uint32_t a;
    asm("{ .reg .u64 t; cvta.to.shared.u64 t, %1; cvt.u32.u64 %0, t; }" : "=r"(a) : "l"(p));
    return a;
}
__device__ __forceinline__ void mma16816(float* c, const uint32_t* a, const uint32_t* b) {
    asm volatile(
        "mma.sync.aligned.m16n8k16.row.col.f32.bf16.bf16.f32 "
        "{%0,%1,%2,%3}, {%4,%5,%6,%7}, {%8,%9}, {%0,%1,%2,%3};"
        : "+f"(c[0]), "+f"(c[1]), "+f"(c[2]), "+f"(c[3])
        : "r"(a[0]), "r"(a[1]), "r"(a[2]), "r"(a[3]), "r"(b[0]), "r"(b[1]));
}
__device__ __forceinline__ void split_bf16(float v, __nv_bfloat16& h, __nv_bfloat16& l) {
    h = __float2bfloat16(v);
    l = __float2bfloat16(v - __bfloat162float(h));
}
__device__ __forceinline__ void cpa16(uint32_t dst, const void* src) {
    asm volatile("cp.async.cg.shared.global [%0], [%1], 16;" :: "r"(dst), "l"(src));
}
__device__ __forceinline__ void cp_commit() {
    asm volatile("cp.async.commit_group;" ::: "memory");
}
template<int N>
__device__ __forceinline__ void cp_wait() {
    asm volatile("cp.async.wait_group %0;" :: "n"(N) : "memory");
}

// ---------------------------------------------------------------------------
// Split-bf16 mma.sync GEMM: BM=128, BN=64, BK=32, 256 threads (4m x 2n warps,
// 32x32 warp tiles). cp.async 2-stage ring. Batched ldsm (16 loads) then
// 48 back-to-back mma. 3 CTAs/SM target.
// C may be nullptr. mode: 0 none, 1 +bias, 2 +bias+elu
// ---------------------------------------------------------------------------
#define ROWB 80
#define A_BYTES (128 * ROWB)                      // 10240
#define B_BYTES (64 * ROWB)                       // 5120
#define STAGE_BYTES (2 * A_BYTES + 2 * B_BYTES)   // 30720
#define GEMM_DSMEM (2 * STAGE_BYTES)              // 61440

__device__ __forceinline__ void load_stage_async(
    uint32_t sbase,
    const __nv_bfloat16* __restrict__ Ahi, const __nv_bfloat16* __restrict__ Alo,
    const __nv_bfloat16* __restrict__ Bhi, const __nv_bfloat16* __restrict__ Blo,
    int mBase, int M, int nBase, int N, int Kpad, int k0, int tid)
{
#pragma unroll
    for (int it = 0; it < 2; it++) {
        int t = tid + it * 256;
        int row = t >> 2, seg = t & 3;
        int gr = mBase + row;
        int sr = (gr < M) ? gr : 0;
        size_t aoff = (size_t)sr * Kpad + k0 + seg * 8;
        uint32_t d = sbase + row * ROWB + seg * 16;
        cpa16(d,           Ahi + aoff);
        cpa16(d + A_BYTES, Alo + aoff);
    }
    {
        int row = tid >> 2, seg = tid & 3;
        int gn = nBase + row;
        int sn = (gn < N) ? gn : 0;
        size_t boff = (size_t)sn * Kpad + k0 + seg * 8;
        uint32_t d = sbase + 2 * A_BYTES + row * ROWB + seg * 16;
        cpa16(d,           Bhi + boff);
        cpa16(d + B_BYTES, Blo + boff);
    }
}

__global__ __launch_bounds__(256, 3) void mma_gemm_kernel(
    const __nv_bfloat16* __restrict__ Ahi, const __nv_bfloat16* __restrict__ Alo,
    const __nv_bfloat16* __restrict__ Bhi, const __nv_bfloat16* __restrict__ Blo,
    const float* __restrict__ bias, float* __restrict__ C,
    __nv_bfloat16* __restrict__ outHi, __nv_bfloat16* __restrict__ outLo, int KpadOut,
    int M, int Ncol, int Kpad, int mode)
{
    extern __shared__ __align__(256) char smem[];
    uint32_t sb = smem_u32(smem);
    int tid = threadIdx.x;
    int wid = tid >> 5, lane = tid & 31;
    int wm = wid & 3, wn = wid >> 2;
    int mBase = blockIdx.y * 128;
    int nBase = blockIdx.x * 64;

    float acc[2][4][4];
#pragma unroll
    for (int mt = 0; mt < 2; mt++)
#pragma unroll
        for (int nt = 0; nt < 4; nt++)
#pragma unroll
            for (int r = 0; r < 4; r++) acc[mt][nt][r] = 0.f;

    const int nc = Kpad >> 5;

    load_stage_async(sb, Ahi, Alo, Bhi, Blo, mBase, M, nBase, Ncol, Kpad, 0, tid);
    cp_commit();
    if (nc > 1) {
        load_stage_async(sb + STAGE_BYTES, Ahi, Alo, Bhi, Blo, mBase, M, nBase, Ncol, Kpad, 32, tid);
        cp_commit();
    }

    int lrow = (lane & 7) + ((lane >> 3) & 1) * 8;
    int lcol8 = (lane >> 4) * 8;

    for (int c = 0; c < nc; c++) {
        if (c + 1 < nc) cp_wait<1>(); else cp_wait<0>();
        __syncthreads();

        uint32_t bufU = sb + (c & 1) * STAGE_BYTES;
        uint32_t aHiS = bufU;
        uint32_t aLoS = bufU + A_BYTES;
        uint32_t bHiS = bufU + 2 * A_BYTES;
        uint32_t bLoS = bHiS + B_BYTES;

        // ---- batched fragment loads: all 16 ldsm first ----
        uint32_t ah[2][2][4], al[2][2][4], bh[2][4][2], bl[2][4][2];
#pragma unroll
        for (int ks = 0; ks < 2; ks++) {
            int kc = ks * 16 + lcol8;
#pragma unroll
            for (int mt = 0; mt < 2; mt++) {
                uint32_t o = (wm * 32 + mt * 16 + lrow) * ROWB + kc * 2;
                ldsm4(ah[ks][mt], aHiS + o);
                ldsm4(al[ks][mt], aLoS + o);
            }
#pragma unroll
            for (int ntp = 0; ntp < 2; ntp++) {
                uint32_t o = (wn * 32 + ntp * 16 + lrow) * ROWB + kc * 2;
                uint32_t t[4];
                ldsm4(t, bHiS + o);
                bh[ks][2 * ntp][0] = t[0]; bh[ks][2 * ntp][1] = t[2];
                bh[ks][2 * ntp + 1][0] = t[1]; bh[ks][2 * ntp + 1][1] = t[3];
                ldsm4(t, bLoS + o);
                bl[ks][2 * ntp][0] = t[0]; bl[ks][2 * ntp][1] = t[2];
                bl[ks][2 * ntp + 1][0] = t[1]; bl[ks][2 * ntp + 1][1] = t[3];
            }
        }
        // ---- 48 back-to-back mma ----
#pragma unroll
        for (int ks = 0; ks < 2; ks++)
#pragma unroll
            for (int mt = 0; mt < 2; mt++)
#pragma unroll
                for (int nt = 0; nt < 4; nt++) {
                    mma16816(acc[mt][nt], ah[ks][mt], bh[ks][nt]);
                    mma16816(acc[mt][nt], ah[ks][mt], bl[ks][nt]);
                    mma16816(acc[mt][nt], al[ks][mt], bh[ks][nt]);
                }
        __syncthreads();
        if (c + 2 < nc) {
            load_stage_async(sb + (c & 1) * STAGE_BYTES, Ahi, Alo, Bhi, Blo,
                             mBase, M, nBase, Ncol, Kpad, (c + 2) * 32, tid);
            cp_commit();
        }
    }

    // Epilogue
    int qr = lane >> 2;
    int qc = (lane & 3) * 2;
#pragma unroll
    for (int mt = 0; mt < 2; mt++) {
#pragma unroll
        for (int nt = 0; nt < 4; nt++) {
#pragma unroll
            for (int half = 0; half < 2; half++) {
                int gr = mBase + wm * 32 + mt * 16 + qr + half * 8;
                if (gr >= M) continue;
#pragma unroll
                for (int e = 0; e < 2; e++) {
                    int gc = nBase + wn * 32 + nt * 8 + qc + e;
                    float v = acc[mt][nt][half * 2 + e];
                    if (gc < Ncol) {
                        if (mode >= 1) v += bias[gc];
                        if (mode == 2) v = v > 0.f ? v : expm1f(v);
                        if (C) C[(size_t)gr * Ncol + gc] = v;
                    } else {
                        v = 0.f;
                    }
                    if (outHi && gc < KpadOut) {
                        __nv_bfloat16 h, l;
                        split_bf16(v, h, l);
                        outHi[(size_t)gr * KpadOut + gc] = h;
                        outLo[(size_t)gr * KpadOut + gc] = l;
                    }
                }
            }
        }
    }
}

// ---------------------------------------------------------------------------
// Conversions
// ---------------------------------------------------------------------------
__global__ void convA_kernel(const float* __restrict__ src,
                             __nv_bfloat16* __restrict__ hi, __nv_bfloat16* __restrict__ lo,
                             int K, int Kpad, long total)
{
    long i = (long)blockIdx.x * blockDim.x + threadIdx.x;
    if (i >= total) return;
    long r = i / Kpad;
    int  k = (int)(i - r * Kpad);
    float v = (k < K) ? src[r * K + k] : 0.f;
    __nv_bfloat16 h, l;
    split_bf16(v, h, l);
    hi[i] = h; lo[i] = l;
}

__global__ void convBT_kernel(const float* __restrict__ B,
                              __nv_bfloat16* __restrict__ bhi, __nv_bfloat16* __restrict__ blo,
                              int K, int N, int Kpad)
{
    __shared__ float sm[32][33];
    int k0 = blockIdx.x * 32, n0 = blockIdx.y * 32;
    int tx = threadIdx.x, ty = threadIdx.y;
    for (int i = ty; i < 32; i += 8) {
        int k = k0 + i, n = n0 + tx;
        sm[i][tx] = (k < K && n < N) ? B[(size_t)k * N + n] : 0.f;
    }
    __syncthreads();
    for (int i = ty; i < 32; i += 8) {
        int n = n0 + i, k = k0 + tx;
        if (n < N && k < Kpad) {
            __nv_bfloat16 h, l;
            split_bf16(sm[tx][i], h, l);
            bhi[(size_t)n * Kpad + k] = h;
            blo[(size_t)n * Kpad + k] = l;
        }
    }
}

// ---------------------------------------------------------------------------
// CSR build + CSR SpMM with fused activation
// ---------------------------------------------------------------------------
__global__ void csr_zero_kernel(int* cnt) {
    int i = blockIdx.x * blockDim.x + threadIdx.x;
    if (i <= NNODES) cnt[i] = 0;
}
__global__ void csr_count_kernel(const int* __restrict__ row, int* cnt, int E) {
    int e = blockIdx.x * blockDim.x + threadIdx.x;
    if (e < E) atomicAdd(&cnt[row[e] + 1], 1);
}
#define SCAN_PER 10
__global__ __launch_bounds__(1024) void csr_scan_kernel(const int* __restrict__ cnt,
                                                        int* rowptr, int* wp)
{
    __shared__ int sh[1024];
    int t = threadIdx.x;
    int base = t * SCAN_PER;
    int local[SCAN_PER];
    int s = 0;
#pragma unroll
    for (int i = 0; i < SCAN_PER; i++) {
        int idx = base + i;
        int v = (idx < NNODES) ? cnt[idx + 1] : 0;
        s += v;
        local[i] = s;
    }
    sh[t] = s;
    __syncthreads();
    for (int off = 1; off < 1024; off <<= 1) {
        int v = (t >= off) ? sh[t - off] : 0;
        __syncthreads();
        sh[t] += v;
        __syncthreads();
    }
    int prev = (t > 0) ? sh[t - 1] : 0;
    if (t == 0) rowptr[0] = 0;
#pragma unroll
    for (int i = 0; i < SCAN_PER; i++) {
        int idx = base + i;
        if (idx < NNODES) {
            rowptr[idx + 1] = prev + local[i];
            wp[idx] = (i == 0) ? prev : prev + local[i - 1];
        }
    }
}
__global__ void csr_scatter_kernel(const int* __restrict__ row, const int* __restrict__ col,
                                   const float* __restrict__ val, int* wp,
                                   int* scol, float* sval, int E)
{
    int e = blockIdx.x * blockDim.x + threadIdx.x;
    if (e >= E) return;
    int p = atomicAdd(&wp[row[e]], 1);
    scol[p] = col[e];
    sval[p] = val[e];
}

__global__ void spmm_csr_kernel(const float* __restrict__ H,
                                const int* __restrict__ rowptr,
                                const int* __restrict__ scol, const float* __restrict__ sval,
                                float* __restrict__ out, int D, int actmode)
{
    int r = blockIdx.x;
    int s = rowptr[r], e_end = rowptr[r + 1];
    int nt = blockDim.x;
    float acc[8];
    int nreg = (D + nt - 1) / nt;
#pragma unroll 8
    for (int i = 0; i < 8; i++) acc[i] = 0.f;
    for (int e = s; e < e_end; e++) {
        int c = scol[e];
        float v = sval[e];
        const float* hrow = H + (size_t)c * D;
#pragma unroll 8
        for (int i = 0; i < 8; i++) {
            if (i >= nreg) break;
            int d = threadIdx.x + i * nt;
            if (d < D) acc[i] = fmaf(v, hrow[d], acc[i]);
        }
    }
#pragma unroll 8
    for (int i = 0; i < 8; i++) {
        if (i >= nreg) break;
        int d = threadIdx.x + i * nt;
        if (d < D) {
            float o = acc[i];
            if (actmode == 0) o = o > 0.f ? o : expm1f(0.2f * o);
            else if (actmode == 1) o = o > 0.f ? o : expm1f(o);
            out[(size_t)r * D + d] = o;
        }
    }
}
static inline void spmm_csr(const float* H, float* out, int D, int actmode,
                            const int* rowptr, const int* scol, const float* sval)
{
    int threads = (D >= 256) ? 256 : ((D + 31) & ~31);
    spmm_csr_kernel<<<NNODES, threads>>>(H, rowptr, scol, sval, out, D, actmode);
}

// ---------------------------------------------------------------------------
// BatchNorm
// ---------------------------------------------------------------------------
__global__ void bn_stats_kernel(const float* __restrict__ h, int n, int d,
                                float* __restrict__ mean, float* __restrict__ rstd)
{
    __shared__ float ssum[8][32];
    __shared__ float ssq[8][32];
    int c = blockIdx.x * 32 + threadIdx.x;
    float s = 0.f, q = 0.f;
    if (c < d) {
        for (int r = threadIdx.y; r < n; r += 8) {
            float v = h[(size_t)r * d + c];
            s += v; q += v * v;
        }
    }
    ssum[threadIdx.y][threadIdx.x] = s;
    ssq[threadIdx.y][threadIdx.x] = q;
    __syncthreads();
    if (threadIdx.y == 0 && c < d) {
#pragma unroll
        for (int i = 1; i < 8; i++) { s += ssum[i][threadIdx.x]; q += ssq[i][threadIdx.x]; }
        float m = s / (float)n;
        float var = q / (float)n - m * m;
        if (var < 0.f) var = 0.f;
        mean[c] = m;
        rstd[c] = rsqrtf(var + 1e-5f);
    }
}
__global__ void bn_apply_kernel(const float* __restrict__ src, float* __restrict__ dst,
                                long total, int d, int Kpad,
                                const float* __restrict__ mean, const float* __restrict__ rstd,
                                __nv_bfloat16* __restrict__ outHi, __nv_bfloat16* __restrict__ outLo)
{
    long i = (long)blockIdx.x * blockDim.x + threadIdx.x;
    if (i >= total) return;
    long r = i / Kpad;
    int  c = (int)(i - r * Kpad);
    float v = 0.f;
    if (c < d) {
        v = (src[r * d + c] - mean[c]) * rstd[c];
        dst[r * d + c] = v;
    }
    if (outHi) {
        __nv_bfloat16 h, l;
        split_bf16(v, h, l);
        outHi[i] = h; outLo[i] = l;
    }
}
static inline void batchnorm(const float* src, float* dst, int n, int d,
                             float* mean, float* rstd,
                             __nv_bfloat16* outHi = nullptr, __nv_bfloat16* outLo = nullptr,
                             int Kpad = 0)
{
    dim3 bt(32, 8);
    bn_stats_kernel<<<(d + 31) / 32, bt>>>(src, n, d, mean, rstd);
    int kp = outHi ? Kpad : d;
    long total = (long)n * kp;
    bn_apply_kernel<<<(int)((total + 255) / 256), 256>>>(src, dst, total, d, kp, mean, rstd, outHi, outLo);
}

// ---------------------------------------------------------------------------
// Gate u, z_in, fused attention, heads
// ---------------------------------------------------------------------------
__device__ __forceinline__ float coms_at(const float* t1, const float* t2,
                                         const float* t3, const float* t4,
                                         int n, int k)
{
    if (k < 500)  return t1[(size_t)n * 500 + k];
    if (k < 1000) return t2[(size_t)n * 500 + (k - 500)];
    if (k < 3000) return t3[(size_t)n * 2000 + (k - 1000)];
    return t4[(size_t)n * 64 + (k - 3000)];
}

__global__ void u_kernel(const float* __restrict__ t1, const float* __restrict__ t2,
                         const float* __restrict__ t3, const float* __restrict__ t4,
                         const float* __restrict__ W, const float* __restrict__ b,
                         float* __restrict__ u)
{
    int warp = (blockIdx.x * blockDim.x + threadIdx.x) >> 5;
    int lane = threadIdx.x & 31;
    if (warp >= NNODES) return;
    float acc[5] = {0.f, 0.f, 0.f, 0.f, 0.f};
    for (int k = lane; k < COMS_D; k += 32) {
        float v = coms_at(t1, t2, t3, t4, warp, k);
        const float* w = &W[(size_t)k * 5];
#pragma unroll
        for (int j = 0; j < 5; j++) acc[j] = fmaf(v, w[j], acc[j]);
    }
#pragma unroll
    for (int j = 0; j < 5; j++) {
        for (int off = 16; off > 0; off >>= 1)
            acc[j] += __shfl_down_sync(0xFFFFFFFF, acc[j], off);
    }
    if (lane == 0) {
        float l[5], m = -1e30f;
#pragma unroll
        for (int j = 0; j < 5; j++) { l[j] = tanhf(acc[j] + b[j]); m = fmaxf(m, l[j]); }
        float s = 0.f;
#pragma unroll
        for (int j = 0; j < 5; j++) { l[j] = expf(l[j] - m); s += l[j]; }
        float nrm = 0.f;
#pragma unroll
        for (int j = 0; j < 5; j++) { l[j] /= s; nrm += l[j] * l[j]; }
        nrm = fmaxf(sqrtf(nrm), 1e-12f);
#pragma unroll
        for (int j = 0; j < 5; j++) u[(size_t)warp * 5 + j] = l[j] / nrm;
    }
}

__global__ void zin_conv_kernel(const float* __restrict__ t1, const float* __restrict__ t2,
                                const float* __restrict__ t3, const float* __restrict__ t4,
                                const float* __restrict__ u,
                                __nv_bfloat16* __restrict__ hi, __nv_bfloat16* __restrict__ lo)
{
    long i = (long)blockIdx.x * blockDim.x + threadIdx.x;
    long total = (long)NNODES * 3072;
    if (i >= total) return;
    int n = (int)(i / 3072);
    int k = (int)(i % 3072);
    float v = 0.f;
    if (k < COMS_D) {
        int seg = (k < 500) ? 0 : (k < 1000) ? 1 : (k < 3000) ? 2 : 3;
        v = u[(size_t)n * 5 + seg] * coms_at(t1, t2, t3, t4, n, k);
    }
    __nv_bfloat16 h, l;
    split_bf16(v, h, l);
    hi[i] = h; lo[i] = l;
}

__global__ __launch_bounds__(256) void att_fused_kernel(
    const float* __restrict__ z, const float* __restrict__ ztopo,
    const float* __restrict__ W1, const float* __restrict__ b1,
    const float* __restrict__ w2, float* __restrict__ embp)
{
    __shared__ float sW1[64 * 128];
    __shared__ float sb1[128];
    __shared__ float sw2[128];
    __shared__ float sS[8][64];
    __shared__ float sc[8];
    int tid = threadIdx.x;
    for (int i = tid; i < 64 * 128; i += 256) sW1[i] = W1[i];
    if (tid < 128) { sb1[tid] = b1[tid]; sw2[tid] = w2[tid]; }

    int wid = tid >> 5, lane = tid & 31;
    int nodeBase = blockIdx.x * 4;
    int n = nodeBase + (wid >> 1);
    int br = wid & 1;
    bool valid = (n < NNODES);
    if (valid) {
        const float* s = br ? &ztopo[(size_t)n * 64] : &z[(size_t)n * 64];
        sS[wid][lane] = s[lane];
        sS[wid][lane + 32] = s[lane + 32];
    }
    __syncthreads();

    float partial = 0.f;
    if (valid) {
#pragma unroll
        for (int jj = 0; jj < 4; jj++) {
            int j = lane + jj * 32;
            float h = sb1[j];
#pragma unroll
            for (int k = 0; k < 64; k++)
                h = fmaf(sS[wid][k], sW1[k * 128 + j], h);
            partial = fmaf(tanhf(h), sw2[j], partial);
        }
    }
    for (int off = 16; off > 0; off >>= 1)
        partial += __shfl_down_sync(0xFFFFFFFF, partial, off);
    if (lane == 0) sc[wid] = partial;
    __syncthreads();

    int nl = tid >> 6;
    int d  = tid & 63;
    int n2 = nodeBase + nl;
    if (n2 < NNODES) {
        float s0 = sc[nl * 2], s1 = sc[nl * 2 + 1];
        float m = fmaxf(s0, s1);
        float e0 = expf(s0 - m), e1 = expf(s1 - m);
        float inv = 1.f / (e0 + e1);
        embp[(size_t)n2 * 64 + d] = (e0 * inv) * z[(size_t)n2 * 64 + d]
                                  + (e1 * inv) * ztopo[(size_t)n2 * 64 + d];
    }
}

__global__ void heads_kernel(const float* __restrict__ emb, const float* __restrict__ z,
                             const float* __restrict__ cluster,
                             float* __restrict__ pred, float* __restrict__ q)
{
    int n = blockIdx.x;
    int t = threadIdx.x;
    __shared__ float sh[64];
    __shared__ float zs[64];

    float v = emb[(size_t)n * 64 + t];
    sh[t] = v;
    __syncthreads();
    for (int s = 32; s > 0; s >>= 1) {
        if (t < s) sh[t] = fmaxf(sh[t], sh[t + s]);
        __syncthreads();
    }
    float m = sh[0];
    __syncthreads();
    float e = expf(v - m);
    sh[t] = e;
    __syncthreads();
    for (int s = 32; s > 0; s >>= 1) {
        if (t < s) sh[t] += sh[t + s];
        __syncthreads();
    }
    pred[(size_t)n * 64 + t] = e / sh[0];
    __syncthreads();

    zs[t] = z[(size_t)n * 64 + t];
    __syncthreads();
    float d2 = 0.f;
    const float* c = &cluster[(size_t)t * 64];
    for (int k = 0; k < 64; k++) {
        float diff = zs[k] - c[k];
        d2 = fmaf(diff, diff, d2);
    }
    float qv = 1.f / (1.f + d2);
    sh[t] = qv;
    __syncthreads();
    for (int s = 32; s > 0; s >>= 1) {
        if (t < s) sh[t] += sh[t + s];
        __syncthreads();
    }
    q[(size_t)n * 64 + t] = qv / sh[0];
}

// ---------------------------------------------------------------------------
// Host-side helpers
// ---------------------------------------------------------------------------
static inline void conv_w(const float* Bw, int K, int N,
                          __nv_bfloat16* Whi, __nv_bfloat16* Wlo, int wsel)
{
    int Kpad = (K + 31) & ~31;
    dim3 tg((Kpad + 31) / 32, (N + 31) / 32);
    convBT_kernel<<<tg, dim3(32, 8)>>>(Bw, Whi + (size_t)wsel * WOFF, Wlo + (size_t)wsel * WOFF, K, N, Kpad);
}

static inline void gemm_run(const __nv_bfloat16* aHi, const __nv_bfloat16* aLo,
                            const float* bias, float* C,
                            __nv_bfloat16* outHi, __nv_bfloat16* outLo,
                            int M, int N, int K, int mode,
                            __nv_bfloat16* Whi, __nv_bfloat16* Wlo, int wsel)
{
    int Kpad = (K + 31) & ~31;
    int KpadOut = (N + 31) & ~31;
    cudaFuncSetAttribute(mma_gemm_kernel, cudaFuncAttributeMaxDynamicSharedMemorySize, GEMM_DSMEM);
    dim3 grid((N + 63) / 64, (M + 127) / 128);
    mma_gemm_kernel<<<grid, 256, GEMM_DSMEM>>>(aHi, aLo,
                                               Whi + (size_t)wsel * WOFF, Wlo + (size_t)wsel * WOFF,
                                               bias, C, outHi, outLo, KpadOut, M, N, Kpad, mode);
}

static inline void gemm_pre(const __nv_bfloat16* aHi, const __nv_bfloat16* aLo,
                            const float* Bw, const float* bias, float* C,
                            __nv_bfloat16* outHi, __nv_bfloat16* outLo,
                            int M, int N, int K, int mode,
                            __nv_bfloat16* Whi, __nv_bfloat16* Wlo)
{
    conv_w(Bw, K, N, Whi, Wlo, 0);
    gemm_run(aHi, aLo, bias, C, outHi, outLo, M, N, K, mode, Whi, Wlo, 0);
}

// ---------------------------------------------------------------------------
// Launch
// ---------------------------------------------------------------------------
extern "C" void kernel_launch(void* const* d_in, const int* in_sizes, int n_in,
                              void* d_out, int out_size)
{
    const float* x       = (const float*)d_in[0];
    const float* adj_val = (const float*)d_in[1];
    const float* enc1_w  = (const float*)d_in[2];
    const float* enc1_b  = (const float*)d_in[3];
    const float* enc2_w  = (const float*)d_in[4];
    const float* enc2_b  = (const float*)d_in[5];
    const float* enc3_w  = (const float*)d_in[6];
    const float* enc3_b  = (const float*)d_in[7];
    const float* zl_w    = (const float*)d_in[8];
    const float* zl_b    = (const float*)d_in[9];
    const float* dec1_w  = (const float*)d_in[10];
    const float* dec1_b  = (const float*)d_in[11];
    const float* dec2_w  = (const float*)d_in[12];
    const float* dec2_b  = (const float*)d_in[13];
    const float* dec3_w  = (const float*)d_in[14];
    const float* dec3_b  = (const float*)d_in[15];
    const float* xbar_w  = (const float*)d_in[16];
    const float* xbar_b  = (const float*)d_in[17];
    const float* t1_w    = (const float*)d_in[18];
    const float* t2_w    = (const float*)d_in[19];
    const float* t3_w    = (const float*)d_in[20];
    const float* t4_w    = (const float*)d_in[21];
    const float* agcn_w  = (const float*)d_in[22];
    const float* mlpl_w  = (const float*)d_in[23];
    const float* mlpl_b  = (const float*)d_in[24];
    const float* att_w1  = (const float*)d_in[25];
    const float* att_b1  = (const float*)d_in[26];
    const float* att_w2  = (const float*)d_in[27];
    const float* cluster = (const float*)d_in[28];
    const int*   adj_row = (const int*)d_in[29];
    const int*   adj_col = (const int*)d_in[30];
    const int E = in_sizes[1];

    float* out      = (float*)d_out;
    float* out_xbar = out;
    float* out_q    = out + (size_t)NNODES * NIN;
    float* out_pred = out_q + (size_t)NNODES * NZC;
    float* out_emb  = out_pred + (size_t)NNODES * NZC;

    float *z, *g, *traw, *t1, *t2, *t3, *t4, *u, *ztopo, *embp, *mean, *rstd;
    int *cnt, *rowptr, *wp, *scol;
    float *sval;
    __nv_bfloat16 *A0h, *A0l, *A1h, *A1l, *Wh, *Wl;
    cudaGetSymbolAddress((void**)&z,  g_zbuf);
    cudaGetSymbolAddress((void**)&g,  g_gbuf);
    cudaGetSymbolAddress((void**)&traw, g_traw);
    cudaGetSymbolAddress((void**)&t1, g_t1);
    cudaGetSymbolAddress((void**)&t2, g_t2);
    cudaGetSymbolAddress((void**)&t3, g_t3);
    cudaGetSymbolAddress((void**)&t4, g_t4);
    cudaGetSymbolAddress((void**)&u,  g_u);
    cudaGetSymbolAddress((void**)&ztopo, g_ztopo);
    cudaGetSymbolAddress((void**)&embp, g_embp);
    cudaGetSymbolAddress((void**)&mean, g_mean);
    cudaGetSymbolAddress((void**)&rstd, g_rstd);
    cudaGetSymbolAddress((void**)&cnt, g_cnt);
    cudaGetSymbolAddress((void**)&rowptr, g_rowptr);
    cudaGetSymbolAddress((void**)&wp, g_wp);
    cudaGetSymbolAddress((void**)&scol, g_scol);
    cudaGetSymbolAddress((void**)&sval, g_sval);
    cudaGetSymbolAddress((void**)&A0h, g_A0hi);
    cudaGetSymbolAddress((void**)&A0l, g_A0lo);
    cudaGetSymbolAddress((void**)&A1h, g_A1hi);
    cudaGetSymbolAddress((void**)&A1l, g_A1lo);
    cudaGetSymbolAddress((void**)&Wh, g_Whi);
    cudaGetSymbolAddress((void**)&Wl, g_Wlo);

    // ---------------- convert x + first two weights, then GEMMs back-to-back
    {
        int Kpad = 2016;
        long tA = (long)NNODES * Kpad;
        convA_kernel<<<(int)((tA + 255) / 256), 256>>>(x, A0h, A0l, NIN, Kpad, tA);
    }
    conv_w(t1_w, NIN, 500, Wh, Wl, 0);
    conv_w(enc1_w, NIN, D1, Wh, Wl, 1);
    gemm_run(A0h, A0l, nullptr, g, nullptr, nullptr, NNODES, 500, NIN, 0, Wh, Wl, 0);
    gemm_run(A0h, A0l, enc1_b, nullptr, A1h, A1l, NNODES, D1, NIN, 2, Wh, Wl, 1);

    // ---------------- rest of AE chain ----------------
    gemm_pre(A1h, A1l, enc2_w, enc2_b, nullptr, A0h, A0l, NNODES, D2, D1, 2, Wh, Wl);
    gemm_pre(A0h, A0l, enc3_w, enc3_b, nullptr, A1h, A1l, NNODES, D3, D2, 2, Wh, Wl);
    gemm_pre(A1h, A1l, zl_w, zl_b, z, A0h, A0l, NNODES, NZC, D3, 1, Wh, Wl);
    gemm_pre(A0h, A0l, dec1_w, dec1_b, nullptr, A1h, A1l, NNODES, 2000, NZC, 2, Wh, Wl);
    gemm_pre(A1h, A1l, dec2_w, dec2_b, nullptr, A0h, A0l, NNODES, 500, 2000, 2, Wh, Wl);
    gemm_pre(A0h, A0l, dec3_w, dec3_b, nullptr, A1h, A1l, NNODES, 500, 500, 2, Wh, Wl);
    gemm_pre(A1h, A1l, xbar_w, xbar_b, out_xbar, nullptr, nullptr, NNODES, NIN, 500, 1, Wh, Wl);

    // ---------------- CSR build ----------------
    csr_zero_kernel<<<(NNODES + 256) / 256, 256>>>(cnt);
    csr_count_kernel<<<(E + 255) / 256, 256>>>(adj_row, cnt, E);
    csr_scan_kernel<<<1, 1024>>>(cnt, rowptr, wp);
    csr_scatter_kernel<<<(E + 255) / 256, 256>>>(adj_row, adj_col, adj_val, wp, scol, sval, E);

    // ---------------- topo GCN stack ----------------
    spmm_csr(g, traw, 500, 0, rowptr, scol, sval);
    batchnorm(traw, t1, NNODES, 500, mean, rstd, A0h, A0l, 512);
    gemm_pre(A0h, A0l, t2_w, nullptr, g, nullptr, nullptr, NNODES, 500, 500, 0, Wh, Wl);

    spmm_csr(g, traw, 500, 0, rowptr, scol, sval);
    batchnorm(traw, t2, NNODES, 500, mean, rstd, A0h, A0l, 512);
    gemm_pre(A0h, A0l, t3_w, nullptr, g, nullptr, nullptr, NNODES, 2000, 500, 0, Wh, Wl);

    spmm_csr(g, traw, 2000, 0, rowptr, scol, sval);
    batchnorm(traw, t3, NNODES, 2000, mean, rstd, A0h, A0l, 2016);
    gemm_pre(A0h, A0l, t4_w, nullptr, g, nullptr, nullptr, NNODES, NZC, 2000, 0, Wh, Wl);

    spmm_csr(g, traw, NZC, 0, rowptr, scol, sval);
    batchnorm(traw, t4, NNODES, NZC, mean, rstd);

    // ---------------- MLP gate u + z_in + agcn ----------------
    u_kernel<<<(NNODES * 32 + 255) / 256, 256>>>(t1, t2, t3, t4, mlpl_w, mlpl_b, u);
    {
        long total = (long)NNODES * 3072;
        zin_conv_kernel<<<(int)((total + 255) / 256), 256>>>(t1, t2, t3, t4, u, A0h, A0l);
    }
    gemm_pre(A0h, A0l, agcn_w, nullptr, g, nullptr, nullptr, NNODES, NZC, COMS_D, 0, Wh, Wl);
    spmm_csr(g, traw, NZC, 1, rowptr, scol, sval);
    batchnorm(traw, ztopo, NNODES, NZC, mean, rstd);

    // ---------------- fused attention + emb BN ----------------
    att_fused_kernel<<<(NNODES + 3) / 4, 256>>>(z, ztopo, att_w1, att_b1, att_w2, embp);
    batchnorm(embp, out_emb, NNODES, NZC, mean, rstd);

    // ---------------- heads ----------------
    heads_kernel<<<NNODES, 64>>>(out_emb, z, cluster, out_pred, out_q);
}

// round 14
// speedup vs baseline: 1.1482x; 1.0749x over previous
#include <cuda_runtime.h>
#include <cuda_bf16.h>
#include <math.h>
#include <stdint.h>

// ---------------------------------------------------------------------------
// Problem constants
// ---------------------------------------------------------------------------
#define NNODES 10000
#define NIN    2000
#define D1     500
#define D2     500
#define D3     2000
#define NZC    64
#define COMS_D 3064
#define EMAX   131072
#define WOFF   (2u * 1024u * 1024u)

// ---------------------------------------------------------------------------
// Scratch (device globals; no allocations allowed)
// ---------------------------------------------------------------------------
__device__ float g_zbuf [NNODES * NZC];
__device__ float g_gbuf [NNODES * 2000];
__device__ float g_traw [NNODES * 2000];
__device__ float g_t1[NNODES * 500];
__device__ float g_t2[NNODES * 500];
__device__ float g_t3[NNODES * 2000];
__device__ float g_t4[NNODES * NZC];
__device__ float g_u [NNODES * 5];
__device__ float g_ztopo[NNODES * NZC];
__device__ float g_embp[NNODES * NZC];
__device__ float g_mean[4096];
__device__ float g_rstd[4096];

// CSR build
__device__ int   g_cnt[NNODES + 1];
__device__ int   g_rowptr[NNODES + 1];
__device__ int   g_wp[NNODES];
__device__ int   g_scol[EMAX];
__device__ float g_sval[EMAX];

// bf16 split-precision ping-pong A buffers + weight buffers (2 regions)
__device__ __align__(256) __nv_bfloat16 g_A0hi[(size_t)NNODES * 3072];
__device__ __align__(256) __nv_bfloat16 g_A0lo[(size_t)NNODES * 3072];
__device__ __align__(256) __nv_bfloat16 g_A1hi[(size_t)NNODES * 3072];
__device__ __align__(256) __nv_bfloat16 g_A1lo[(size_t)NNODES * 3072];
__device__ __align__(256) __nv_bfloat16 g_Whi[2048 * 3072];
__device__ __align__(256) __nv_bfloat16 g_Wlo[2048 * 3072];

// ---------------------------------------------------------------------------
// PTX helpers
// ---------------------------------------------------------------------------
__device__ __forceinline__ void ldsm4(uint32_t* r, uint32_t addr) {
    asm volatile("ldmatrix.sync.aligned.m8n8.x4.shared.b16 {%0,%1,%2,%3}, [%4];"
                 : "=r"(r[0]), "=r"(r[1]), "=r"(r[2]), "=r"(r[3]) : "r"(addr));
}
__device__ __forceinline__ uint32_t smem_u32(const void* p) {
    uint32_t a;
    asm("{ .reg .u64 t; cvta.to.shared.u64 t, %1; cvt.u32.u64 %0, t; }" : "=r"(a) : "l"(p));
    return a;
}
__device__ __forceinline__ void mma16816(float* c, const uint32_t* a, const uint32_t* b) {
    asm volatile(
        "mma.sync.aligned.m16n8k16.row.col.f32.bf16.bf16.f32 "
        "{%0,%1,%2,%3}, {%4,%5,%6,%7}, {%8,%9}, {%0,%1,%2,%3};"
        : "+f"(c[0]), "+f"(c[1]), "+f"(c[2]), "+f"(c[3])
        : "r"(a[0]), "r"(a[1]), "r"(a[2]), "r"(a[3]), "r"(b[0]), "r"(b[1]));
}
__device__ __forceinline__ void split_bf16(float v, __nv_bfloat16& h, __nv_bfloat16& l) {
    h = __float2bfloat16(v);
    l = __float2bfloat16(v - __bfloat162float(h));
}
__device__ __forceinline__ void cpa16(uint32_t dst, const void* src) {
    asm volatile("cp.async.cg.shared.global [%0], [%1], 16;" :: "r"(dst), "l"(src));
}
__device__ __forceinline__ void cp_commit() {
    asm volatile("cp.async.commit_group;" ::: "memory");
}
template<int N>
__device__ __forceinline__ void cp_wait() {
    asm volatile("cp.async.wait_group %0;" :: "n"(N) : "memory");
}

// ---------------------------------------------------------------------------
// Split-bf16 mma.sync GEMM (R13 winner, unchanged): BM=128, BN=64, BK=32,
// 256 threads (4m x 2n warps, 32x32 warp tiles). cp.async 2-stage ring.
// Batched ldsm (16 loads) then 48 back-to-back mma. 3 CTAs/SM.
// C may be nullptr. mode: 0 none, 1 +bias, 2 +bias+elu
// ---------------------------------------------------------------------------
#define ROWB 80
#define A_BYTES (128 * ROWB)                      // 10240
#define B_BYTES (64 * ROWB)                       // 5120
#define STAGE_BYTES (2 * A_BYTES + 2 * B_BYTES)   // 30720
#define GEMM_DSMEM (2 * STAGE_BYTES)              // 61440

__device__ __forceinline__ void load_stage_async(
    uint32_t sbase,
    const __nv_bfloat16* __restrict__ Ahi, const __nv_bfloat16* __restrict__ Alo,
    const __nv_bfloat16* __restrict__ Bhi, const __nv_bfloat16* __restrict__ Blo,
    int mBase, int M, int nBase, int N, int Kpad, int k0, int tid)
{
#pragma unroll
    for (int it = 0; it < 2; it++) {
        int t = tid + it * 256;
        int row = t >> 2, seg = t & 3;
        int gr = mBase + row;
        int sr = (gr < M) ? gr : 0;
        size_t aoff = (size_t)sr * Kpad + k0 + seg * 8;
        uint32_t d = sbase + row * ROWB + seg * 16;
        cpa16(d,           Ahi + aoff);
        cpa16(d + A_BYTES, Alo + aoff);
    }
    {
        int row = tid >> 2, seg = tid & 3;
        int gn = nBase + row;
        int sn = (gn < N) ? gn : 0;
        size_t boff = (size_t)sn * Kpad + k0 + seg * 8;
        uint32_t d = sbase + 2 * A_BYTES + row * ROWB + seg * 16;
        cpa16(d,           Bhi + boff);
        cpa16(d + B_BYTES, Blo + boff);
    }
}

__global__ __launch_bounds__(256, 3) void mma_gemm_kernel(
    const __nv_bfloat16* __restrict__ Ahi, const __nv_bfloat16* __restrict__ Alo,
    const __nv_bfloat16* __restrict__ Bhi, const __nv_bfloat16* __restrict__ Blo,
    const float* __restrict__ bias, float* __restrict__ C,
    __nv_bfloat16* __restrict__ outHi, __nv_bfloat16* __restrict__ outLo, int KpadOut,
    int M, int Ncol, int Kpad, int mode)
{
    extern __shared__ __align__(256) char smem[];
    uint32_t sb = smem_u32(smem);
    int tid = threadIdx.x;
    int wid = tid >> 5, lane = tid & 31;
    int wm = wid & 3, wn = wid >> 2;
    int mBase = blockIdx.y * 128;
    int nBase = blockIdx.x * 64;

    float acc[2][4][4];
#pragma unroll
    for (int mt = 0; mt < 2; mt++)
#pragma unroll
        for (int nt = 0; nt < 4; nt++)
#pragma unroll
            for (int r = 0; r < 4; r++) acc[mt][nt][r] = 0.f;

    const int nc = Kpad >> 5;

    load_stage_async(sb, Ahi, Alo, Bhi, Blo, mBase, M, nBase, Ncol, Kpad, 0, tid);
    cp_commit();
    if (nc > 1) {
        load_stage_async(sb + STAGE_BYTES, Ahi, Alo, Bhi, Blo, mBase, M, nBase, Ncol, Kpad, 32, tid);
        cp_commit();
    }

    int lrow = (lane & 7) + ((lane >> 3) & 1) * 8;
    int lcol8 = (lane >> 4) * 8;

    for (int c = 0; c < nc; c++) {
        if (c + 1 < nc) cp_wait<1>(); else cp_wait<0>();
        __syncthreads();

        uint32_t bufU = sb + (c & 1) * STAGE_BYTES;
        uint32_t aHiS = bufU;
        uint32_t aLoS = bufU + A_BYTES;
        uint32_t bHiS = bufU + 2 * A_BYTES;
        uint32_t bLoS = bHiS + B_BYTES;

        uint32_t ah[2][2][4], al[2][2][4], bh[2][4][2], bl[2][4][2];
#pragma unroll
        for (int ks = 0; ks < 2; ks++) {
            int kc = ks * 16 + lcol8;
#pragma unroll
            for (int mt = 0; mt < 2; mt++) {
                uint32_t o = (wm * 32 + mt * 16 + lrow) * ROWB + kc * 2;
                ldsm4(ah[ks][mt], aHiS + o);
                ldsm4(al[ks][mt], aLoS + o);
            }
#pragma unroll
            for (int ntp = 0; ntp < 2; ntp++) {
                uint32_t o = (wn * 32 + ntp * 16 + lrow) * ROWB + kc * 2;
                uint32_t t[4];
                ldsm4(t, bHiS + o);
                bh[ks][2 * ntp][0] = t[0]; bh[ks][2 * ntp][1] = t[2];
                bh[ks][2 * ntp + 1][0] = t[1]; bh[ks][2 * ntp + 1][1] = t[3];
                ldsm4(t, bLoS + o);
                bl[ks][2 * ntp][0] = t[0]; bl[ks][2 * ntp][1] = t[2];
                bl[ks][2 * ntp + 1][0] = t[1]; bl[ks][2 * ntp + 1][1] = t[3];
            }
        }
#pragma unroll
        for (int ks = 0; ks < 2; ks++)
#pragma unroll
            for (int mt = 0; mt < 2; mt++)
#pragma unroll
                for (int nt = 0; nt < 4; nt++) {
                    mma16816(acc[mt][nt], ah[ks][mt], bh[ks][nt]);
                    mma16816(acc[mt][nt], ah[ks][mt], bl[ks][nt]);
                    mma16816(acc[mt][nt], al[ks][mt], bh[ks][nt]);
                }
        __syncthreads();
        if (c + 2 < nc) {
            load_stage_async(sb + (c & 1) * STAGE_BYTES, Ahi, Alo, Bhi, Blo,
                             mBase, M, nBase, Ncol, Kpad, (c + 2) * 32, tid);
            cp_commit();
        }
    }

    int qr = lane >> 2;
    int qc = (lane & 3) * 2;
#pragma unroll
    for (int mt = 0; mt < 2; mt++) {
#pragma unroll
        for (int nt = 0; nt < 4; nt++) {
#pragma unroll
            for (int half = 0; half < 2; half++) {
                int gr = mBase + wm * 32 + mt * 16 + qr + half * 8;
                if (gr >= M) continue;
#pragma unroll
                for (int e = 0; e < 2; e++) {
                    int gc = nBase + wn * 32 + nt * 8 + qc + e;
                    float v = acc[mt][nt][half * 2 + e];
                    if (gc < Ncol) {
                        if (mode >= 1) v += bias[gc];
                        if (mode == 2) v = v > 0.f ? v : expm1f(v);
                        if (C) C[(size_t)gr * Ncol + gc] = v;
                    } else {
                        v = 0.f;
                    }
                    if (outHi && gc < KpadOut) {
                        __nv_bfloat16 h, l;
                        split_bf16(v, h, l);
                        outHi[(size_t)gr * KpadOut + gc] = h;
                        outLo[(size_t)gr * KpadOut + gc] = l;
                    }
                }
            }
        }
    }
}

// ---------------------------------------------------------------------------
// Conversions
// ---------------------------------------------------------------------------
__global__ void convA_kernel(const float* __restrict__ src,
                             __nv_bfloat16* __restrict__ hi, __nv_bfloat16* __restrict__ lo,
                             int K, int Kpad, long total)
{
    long i = (long)blockIdx.x * blockDim.x + threadIdx.x;
    if (i >= total) return;
    long r = i / Kpad;
    int  k = (int)(i - r * Kpad);
    float v = (k < K) ? src[r * K + k] : 0.f;
    __nv_bfloat16 h, l;
    split_bf16(v, h, l);
    hi[i] = h; lo[i] = l;
}

__global__ void convBT_kernel(const float* __restrict__ B,
                              __nv_bfloat16* __restrict__ bhi, __nv_bfloat16* __restrict__ blo,
                              int K, int N, int Kpad)
{
    __shared__ float sm[32][33];
    int k0 = blockIdx.x * 32, n0 = blockIdx.y * 32;
    int tx = threadIdx.x, ty = threadIdx.y;
    for (int i = ty; i < 32; i += 8) {
        int k = k0 + i, n = n0 + tx;
        sm[i][tx] = (k < K && n < N) ? B[(size_t)k * N + n] : 0.f;
    }
    __syncthreads();
    for (int i = ty; i < 32; i += 8) {
        int n = n0 + i, k = k0 + tx;
        if (n < N && k < Kpad) {
            __nv_bfloat16 h, l;
            split_bf16(sm[tx][i], h, l);
            bhi[(size_t)n * Kpad + k] = h;
            blo[(size_t)n * Kpad + k] = l;
        }
    }
}

// ---------------------------------------------------------------------------
// CSR build + CSR SpMM (float4-vectorized) with fused activation
// ---------------------------------------------------------------------------
__global__ void csr_zero_kernel(int* cnt) {
    int i = blockIdx.x * blockDim.x + threadIdx.x;
    if (i <= NNODES) cnt[i] = 0;
}
__global__ void csr_count_kernel(const int* __restrict__ row, int* cnt, int E) {
    int e = blockIdx.x * blockDim.x + threadIdx.x;
    if (e < E) atomicAdd(&cnt[row[e] + 1], 1);
}
#define SCAN_PER 10
__global__ __launch_bounds__(1024) void csr_scan_kernel(const int* __restrict__ cnt,
                                                        int* rowptr, int* wp)
{
    __shared__ int sh[1024];
    int t = threadIdx.x;
    int base = t * SCAN_PER;
    int local[SCAN_PER];
    int s = 0;
#pragma unroll
    for (int i = 0; i < SCAN_PER; i++) {
        int idx = base + i;
        int v = (idx < NNODES) ? cnt[idx + 1] : 0;
        s += v;
        local[i] = s;
    }
    sh[t] = s;
    __syncthreads();
    for (int off = 1; off < 1024; off <<= 1) {
        int v = (t >= off) ? sh[t - off] : 0;
        __syncthreads();
        sh[t] += v;
        __syncthreads();
    }
    int prev = (t > 0) ? sh[t - 1] : 0;
    if (t == 0) rowptr[0] = 0;
#pragma unroll
    for (int i = 0; i < SCAN_PER; i++) {
        int idx = base + i;
        if (idx < NNODES) {
            rowptr[idx + 1] = prev + local[i];
            wp[idx] = (i == 0) ? prev : prev + local[i - 1];
        }
    }
}
__global__ void csr_scatter_kernel(const int* __restrict__ row, const int* __restrict__ col,
                                   const float* __restrict__ val, int* wp,
                                   int* scol, float* sval, int E)
{
    int e = blockIdx.x * blockDim.x + threadIdx.x;
    if (e >= E) return;
    int p = atomicAdd(&wp[row[e]], 1);
    scol[p] = col[e];
    sval[p] = val[e];
}

// float4-vectorized SpMM: one block per row, D4 = D/4 vector elements.
// act mode: 0 = elu(leaky_relu(x,0.2)), 1 = elu(x)
__global__ void spmm_csr_kernel(const float4* __restrict__ H4,
                                const int* __restrict__ rowptr,
                                const int* __restrict__ scol, const float* __restrict__ sval,
                                float4* __restrict__ out4, int D4, int actmode)
{
    int r = blockIdx.x;
    int s = rowptr[r], e_end = rowptr[r + 1];
    int nt = blockDim.x;
    float4 acc[2];
    acc[0] = make_float4(0.f, 0.f, 0.f, 0.f);
    acc[1] = make_float4(0.f, 0.f, 0.f, 0.f);
    int nreg = (D4 + nt - 1) / nt;
    for (int e = s; e < e_end; e++) {
        int c = scol[e];
        float v = sval[e];
        const float4* hrow = H4 + (size_t)c * D4;
#pragma unroll 2
        for (int i = 0; i < 2; i++) {
            if (i >= nreg) break;
            int d = threadIdx.x + i * nt;
            if (d < D4) {
                float4 h = hrow[d];
                acc[i].x = fmaf(v, h.x, acc[i].x);
                acc[i].y = fmaf(v, h.y, acc[i].y);
                acc[i].z = fmaf(v, h.z, acc[i].z);
                acc[i].w = fmaf(v, h.w, acc[i].w);
            }
        }
    }
#pragma unroll 2
    for (int i = 0; i < 2; i++) {
        if (i >= nreg) break;
        int d = threadIdx.x + i * nt;
        if (d < D4) {
            float4 o = acc[i];
            if (actmode == 0) {
                o.x = o.x > 0.f ? o.x : expm1f(0.2f * o.x);
                o.y = o.y > 0.f ? o.y : expm1f(0.2f * o.y);
                o.z = o.z > 0.f ? o.z : expm1f(0.2f * o.z);
                o.w = o.w > 0.f ? o.w : expm1f(0.2f * o.w);
            } else if (actmode == 1) {
                o.x = o.x > 0.f ? o.x : expm1f(o.x);
                o.y = o.y > 0.f ? o.y : expm1f(o.y);
                o.z = o.z > 0.f ? o.z : expm1f(o.z);
                o.w = o.w > 0.f ? o.w : expm1f(o.w);
            }
            out4[(size_t)r * D4 + d] = o;
        }
    }
}
static inline void spmm_csr(const float* H, float* out, int D, int actmode,
                            const int* rowptr, const int* scol, const float* sval)
{
    int D4 = D / 4;
    int threads = (D4 >= 256) ? 256 : ((D4 + 31) & ~31);
    spmm_csr_kernel<<<NNODES, threads>>>((const float4*)H, rowptr, scol, sval,
                                         (float4*)out, D4, actmode);
}

// ---------------------------------------------------------------------------
// BatchNorm
// ---------------------------------------------------------------------------
__global__ void bn_stats_kernel(const float* __restrict__ h, int n, int d,
                                float* __restrict__ mean, float* __restrict__ rstd)
{
    __shared__ float ssum[8][32];
    __shared__ float ssq[8][32];
    int c = blockIdx.x * 32 + threadIdx.x;
    float s = 0.f, q = 0.f;
    if (c < d) {
        for (int r = threadIdx.y; r < n; r += 8) {
            float v = h[(size_t)r * d + c];
            s += v; q += v * v;
        }
    }
    ssum[threadIdx.y][threadIdx.x] = s;
    ssq[threadIdx.y][threadIdx.x] = q;
    __syncthreads();
    if (threadIdx.y == 0 && c < d) {
#pragma unroll
        for (int i = 1; i < 8; i++) { s += ssum[i][threadIdx.x]; q += ssq[i][threadIdx.x]; }
        float m = s / (float)n;
        float var = q / (float)n - m * m;
        if (var < 0.f) var = 0.f;
        mean[c] = m;
        rstd[c] = rsqrtf(var + 1e-5f);
    }
}
__global__ void bn_apply_kernel(const float* __restrict__ src, float* __restrict__ dst,
                                long total, int d, int Kpad,
                                const float* __restrict__ mean, const float* __restrict__ rstd,
                                __nv_bfloat16* __restrict__ outHi, __nv_bfloat16* __restrict__ outLo)
{
    long i = (long)blockIdx.x * blockDim.x + threadIdx.x;
    if (i >= total) return;
    long r = i / Kpad;
    int  c = (int)(i - r * Kpad);
    float v = 0.f;
    if (c < d) {
        v = (src[r * d + c] - mean[c]) * rstd[c];
        dst[r * d + c] = v;
    }
    if (outHi) {
        __nv_bfloat16 h, l;
        split_bf16(v, h, l);
        outHi[i] = h; outLo[i] = l;
    }
}
static inline void batchnorm(const float* src, float* dst, int n, int d,
                             float* mean, float* rstd,
                             __nv_bfloat16* outHi = nullptr, __nv_bfloat16* outLo = nullptr,
                             int Kpad = 0)
{
    dim3 bt(32, 8);
    bn_stats_kernel<<<(d + 31) / 32, bt>>>(src, n, d, mean, rstd);
    int kp = outHi ? Kpad : d;
    long total = (long)n * kp;
    bn_apply_kernel<<<(int)((total + 255) / 256), 256>>>(src, dst, total, d, kp, mean, rstd, outHi, outLo);
}

// ---------------------------------------------------------------------------
// Gate u, z_in, fused attention, heads
// ---------------------------------------------------------------------------
__device__ __forceinline__ float coms_at(const float* t1, const float* t2,
                                         const float* t3, const float* t4,
                                         int n, int k)
{
    if (k < 500)  return t1[(size_t)n * 500 + k];
    if (k < 1000) return t2[(size_t)n * 500 + (k - 500)];
    if (k < 3000) return t3[(size_t)n * 2000 + (k - 1000)];
    return t4[(size_t)n * 64 + (k - 3000)];
}

__global__ void u_kernel(const float* __restrict__ t1, const float* __restrict__ t2,
                         const float* __restrict__ t3, const float* __restrict__ t4,
                         const float* __restrict__ W, const float* __restrict__ b,
                         float* __restrict__ u)
{
    int warp = (blockIdx.x * blockDim.x + threadIdx.x) >> 5;
    int lane = threadIdx.x & 31;
    if (warp >= NNODES) return;
    float acc[5] = {0.f, 0.f, 0.f, 0.f, 0.f};
    for (int k = lane; k < COMS_D; k += 32) {
        float v = coms_at(t1, t2, t3, t4, warp, k);
        const float* w = &W[(size_t)k * 5];
#pragma unroll
        for (int j = 0; j < 5; j++) acc[j] = fmaf(v, w[j], acc[j]);
    }
#pragma unroll
    for (int j = 0; j < 5; j++) {
        for (int off = 16; off > 0; off >>= 1)
            acc[j] += __shfl_down_sync(0xFFFFFFFF, acc[j], off);
    }
    if (lane == 0) {
        float l[5], m = -1e30f;
#pragma unroll
        for (int j = 0; j < 5; j++) { l[j] = tanhf(acc[j] + b[j]); m = fmaxf(m, l[j]); }
        float s = 0.f;
#pragma unroll
        for (int j = 0; j < 5; j++) { l[j] = expf(l[j] - m); s += l[j]; }
        float nrm = 0.f;
#pragma unroll
        for (int j = 0; j < 5; j++) { l[j] /= s; nrm += l[j] * l[j]; }
        nrm = fmaxf(sqrtf(nrm), 1e-12f);
#pragma unroll
        for (int j = 0; j < 5; j++) u[(size_t)warp * 5 + j] = l[j] / nrm;
    }
}

__global__ void zin_conv_kernel(const float* __restrict__ t1, const float* __restrict__ t2,
                                const float* __restrict__ t3, const float* __restrict__ t4,
                                const float* __restrict__ u,
                                __nv_bfloat16* __restrict__ hi, __nv_bfloat16* __restrict__ lo)
{
    long i = (long)blockIdx.x * blockDim.x + threadIdx.x;
    long total = (long)NNODES * 3072;
    if (i >= total) return;
    int n = (int)(i / 3072);
    int k = (int)(i % 3072);
    float v = 0.f;
    if (k < COMS_D) {
        int seg = (k < 500) ? 0 : (k < 1000) ? 1 : (k < 3000) ? 2 : 3;
        v = u[(size_t)n * 5 + seg] * coms_at(t1, t2, t3, t4, n, k);
    }
    __nv_bfloat16 h, l;
    split_bf16(v, h, l);
    hi[i] = h; lo[i] = l;
}

__global__ __launch_bounds__(256) void att_fused_kernel(
    const float* __restrict__ z, const float* __restrict__ ztopo,
    const float* __restrict__ W1, const float* __restrict__ b1,
    const float* __restrict__ w2, float* __restrict__ embp)
{
    __shared__ float sW1[64 * 128];
    __shared__ float sb1[128];
    __shared__ float sw2[128];
    __shared__ float sS[8][64];
    __shared__ float sc[8];
    int tid = threadIdx.x;
    for (int i = tid; i < 64 * 128; i += 256) sW1[i] = W1[i];
    if (tid < 128) { sb1[tid] = b1[tid]; sw2[tid] = w2[tid]; }

    int wid = tid >> 5, lane = tid & 31;
    int nodeBase = blockIdx.x * 4;
    int n = nodeBase + (wid >> 1);
    int br = wid & 1;
    bool valid = (n < NNODES);
    if (valid) {
        const float* s = br ? &ztopo[(size_t)n * 64] : &z[(size_t)n * 64];
        sS[wid][lane] = s[lane];
        sS[wid][lane + 32] = s[lane + 32];
    }
    __syncthreads();

    float partial = 0.f;
    if (valid) {
#pragma unroll
        for (int jj = 0; jj < 4; jj++) {
            int j = lane + jj * 32;
            float h = sb1[j];
#pragma unroll
            for (int k = 0; k < 64; k++)
                h = fmaf(sS[wid][k], sW1[k * 128 + j], h);
            partial = fmaf(tanhf(h), sw2[j], partial);
        }
    }
    for (int off = 16; off > 0; off >>= 1)
        partial += __shfl_down_sync(0xFFFFFFFF, partial, off);
    if (lane == 0) sc[wid] = partial;
    __syncthreads();

    int nl = tid >> 6;
    int d  = tid & 63;
    int n2 = nodeBase + nl;
    if (n2 < NNODES) {
        float s0 = sc[nl * 2], s1 = sc[nl * 2 + 1];
        float m = fmaxf(s0, s1);
        float e0 = expf(s0 - m), e1 = expf(s1 - m);
        float inv = 1.f / (e0 + e1);
        embp[(size_t)n2 * 64 + d] = (e0 * inv) * z[(size_t)n2 * 64 + d]
                                  + (e1 * inv) * ztopo[(size_t)n2 * 64 + d];
    }
}

__global__ void heads_kernel(const float* __restrict__ emb, const float* __restrict__ z,
                             const float* __restrict__ cluster,
                             float* __restrict__ pred, float* __restrict__ q)
{
    int n = blockIdx.x;
    int t = threadIdx.x;
    __shared__ float sh[64];
    __shared__ float zs[64];

    float v = emb[(size_t)n * 64 + t];
    sh[t] = v;
    __syncthreads();
    for (int s = 32; s > 0; s >>= 1) {
        if (t < s) sh[t] = fmaxf(sh[t], sh[t + s]);
        __syncthreads();
    }
    float m = sh[0];
    __syncthreads();
    float e = expf(v - m);
    sh[t] = e;
    __syncthreads();
    for (int s = 32; s > 0; s >>= 1) {
        if (t < s) sh[t] += sh[t + s];
        __syncthreads();
    }
    pred[(size_t)n * 64 + t] = e / sh[0];
    __syncthreads();

    zs[t] = z[(size_t)n * 64 + t];
    __syncthreads();
    float d2 = 0.f;
    const float* c = &cluster[(size_t)t * 64];
    for (int k = 0; k < 64; k++) {
        float diff = zs[k] - c[k];
        d2 = fmaf(diff, diff, d2);
    }
    float qv = 1.f / (1.f + d2);
    sh[t] = qv;
    __syncthreads();
    for (int s = 32; s > 0; s >>= 1) {
        if (t < s) sh[t] += sh[t + s];
        __syncthreads();
    }
    q[(size_t)n * 64 + t] = qv / sh[0];
}

// ---------------------------------------------------------------------------
// Host-side helpers
// ---------------------------------------------------------------------------
static inline void conv_w(const float* Bw, int K, int N,
                          __nv_bfloat16* Whi, __nv_bfloat16* Wlo, int wsel)
{
    int Kpad = (K + 31) & ~31;
    dim3 tg((Kpad + 31) / 32, (N + 31) / 32);
    convBT_kernel<<<tg, dim3(32, 8)>>>(Bw, Whi + (size_t)wsel * WOFF, Wlo + (size_t)wsel * WOFF, K, N, Kpad);
}

static inline void gemm_run(const __nv_bfloat16* aHi, const __nv_bfloat16* aLo,
                            const float* bias, float* C,
                            __nv_bfloat16* outHi, __nv_bfloat16* outLo,
                            int M, int N, int K, int mode,
                            __nv_bfloat16* Whi, __nv_bfloat16* Wlo, int wsel)
{
    int Kpad = (K + 31) & ~31;
    int KpadOut = (N + 31) & ~31;
    cudaFuncSetAttribute(mma_gemm_kernel, cudaFuncAttributeMaxDynamicSharedMemorySize, GEMM_DSMEM);
    dim3 grid((N + 63) / 64, (M + 127) / 128);
    mma_gemm_kernel<<<grid, 256, GEMM_DSMEM>>>(aHi, aLo,
                                               Whi + (size_t)wsel * WOFF, Wlo + (size_t)wsel * WOFF,
                                               bias, C, outHi, outLo, KpadOut, M, N, Kpad, mode);
}

static inline void gemm_pre(const __nv_bfloat16* aHi, const __nv_bfloat16* aLo,
                            const float* Bw, const float* bias, float* C,
                            __nv_bfloat16* outHi, __nv_bfloat16* outLo,
                            int M, int N, int K, int mode,
                            __nv_bfloat16* Whi, __nv_bfloat16* Wlo)
{
    conv_w(Bw, K, N, Whi, Wlo, 0);
    gemm_run(aHi, aLo, bias, C, outHi, outLo, M, N, K, mode, Whi, Wlo, 0);
}

// ---------------------------------------------------------------------------
// Launch
// ---------------------------------------------------------------------------
extern "C" void kernel_launch(void* const* d_in, const int* in_sizes, int n_in,
                              void* d_out, int out_size)
{
    const float* x       = (const float*)d_in[0];
    const float* adj_val = (const float*)d_in[1];
    const float* enc1_w  = (const float*)d_in[2];
    const float* enc1_b  = (const float*)d_in[3];
    const float* enc2_w  = (const float*)d_in[4];
    const float* enc2_b  = (const float*)d_in[5];
    const float* enc3_w  = (const float*)d_in[6];
    const float* enc3_b  = (const float*)d_in[7];
    const float* zl_w    = (const float*)d_in[8];
    const float* zl_b    = (const float*)d_in[9];
    const float* dec1_w  = (const float*)d_in[10];
    const float* dec1_b  = (const float*)d_in[11];
    const float* dec2_w  = (const float*)d_in[12];
    const float* dec2_b  = (const float*)d_in[13];
    const float* dec3_w  = (const float*)d_in[14];
    const float* dec3_b  = (const float*)d_in[15];
    const float* xbar_w  = (const float*)d_in[16];
    const float* xbar_b  = (const float*)d_in[17];
    const float* t1_w    = (const float*)d_in[18];
    const float* t2_w    = (const float*)d_in[19];
    const float* t3_w    = (const float*)d_in[20];
    const float* t4_w    = (const float*)d_in[21];
    const float* agcn_w  = (const float*)d_in[22];
    const float* mlpl_w  = (const float*)d_in[23];
    const float* mlpl_b  = (const float*)d_in[24];
    const float* att_w1  = (const float*)d_in[25];
    const float* att_b1  = (const float*)d_in[26];
    const float* att_w2  = (const float*)d_in[27];
    const float* cluster = (const float*)d_in[28];
    const int*   adj_row = (const int*)d_in[29];
    const int*   adj_col = (const int*)d_in[30];
    const int E = in_sizes[1];

    float* out      = (float*)d_out;
    float* out_xbar = out;
    float* out_q    = out + (size_t)NNODES * NIN;
    float* out_pred = out_q + (size_t)NNODES * NZC;
    float* out_emb  = out_pred + (size_t)NNODES * NZC;

    float *z, *g, *traw, *t1, *t2, *t3, *t4, *u, *ztopo, *embp, *mean, *rstd;
    int *cnt, *rowptr, *wp, *scol;
    float *sval;
    __nv_bfloat16 *A0h, *A0l, *A1h, *A1l, *Wh, *Wl;
    cudaGetSymbolAddress((void**)&z,  g_zbuf);
    cudaGetSymbolAddress((void**)&g,  g_gbuf);
    cudaGetSymbolAddress((void**)&traw, g_traw);
    cudaGetSymbolAddress((void**)&t1, g_t1);
    cudaGetSymbolAddress((void**)&t2, g_t2);
    cudaGetSymbolAddress((void**)&t3, g_t3);
    cudaGetSymbolAddress((void**)&t4, g_t4);
    cudaGetSymbolAddress((void**)&u,  g_u);
    cudaGetSymbolAddress((void**)&ztopo, g_ztopo);
    cudaGetSymbolAddress((void**)&embp, g_embp);
    cudaGetSymbolAddress((void**)&mean, g_mean);
    cudaGetSymbolAddress((void**)&rstd, g_rstd);
    cudaGetSymbolAddress((void**)&cnt, g_cnt);
    cudaGetSymbolAddress((void**)&rowptr, g_rowptr);
    cudaGetSymbolAddress((void**)&wp, g_wp);
    cudaGetSymbolAddress((void**)&scol, g_scol);
    cudaGetSymbolAddress((void**)&sval, g_sval);
    cudaGetSymbolAddress((void**)&A0h, g_A0hi);
    cudaGetSymbolAddress((void**)&A0l, g_A0lo);
    cudaGetSymbolAddress((void**)&A1h, g_A1hi);
    cudaGetSymbolAddress((void**)&A1l, g_A1lo);
    cudaGetSymbolAddress((void**)&Wh, g_Whi);
    cudaGetSymbolAddress((void**)&Wl, g_Wlo);

    // ---------------- convert x + first two weights, then GEMMs back-to-back
    {
        int Kpad = 2016;
        long tA = (long)NNODES * Kpad;
        convA_kernel<<<(int)((tA + 255) / 256), 256>>>(x, A0h, A0l, NIN, Kpad, tA);
    }
    conv_w(t1_w, NIN, 500, Wh, Wl, 0);
    conv_w(enc1_w, NIN, D1, Wh, Wl, 1);
    gemm_run(A0h, A0l, nullptr, g, nullptr, nullptr, NNODES, 500, NIN, 0, Wh, Wl, 0);
    gemm_run(A0h, A0l, enc1_b, nullptr, A1h, A1l, NNODES, D1, NIN, 2, Wh, Wl, 1);

    // ---------------- rest of AE chain ----------------
    gemm_pre(A1h, A1l, enc2_w, enc2_b, nullptr, A0h, A0l, NNODES, D2, D1, 2, Wh, Wl);
    gemm_pre(A0h, A0l, enc3_w, enc3_b, nullptr, A1h, A1l, NNODES, D3, D2, 2, Wh, Wl);
    gemm_pre(A1h, A1l, zl_w, zl_b, z, A0h, A0l, NNODES, NZC, D3, 1, Wh, Wl);
    gemm_pre(A0h, A0l, dec1_w, dec1_b, nullptr, A1h, A1l, NNODES, 2000, NZC, 2, Wh, Wl);
    gemm_pre(A1h, A1l, dec2_w, dec2_b, nullptr, A0h, A0l, NNODES, 500, 2000, 2, Wh, Wl);
    gemm_pre(A0h, A0l, dec3_w, dec3_b, nullptr, A1h, A1l, NNODES, 500, 500, 2, Wh, Wl);
    gemm_pre(A1h, A1l, xbar_w, xbar_b, out_xbar, nullptr, nullptr, NNODES, NIN, 500, 1, Wh, Wl);

    // ---------------- CSR build ----------------
    csr_zero_kernel<<<(NNODES + 256) / 256, 256>>>(cnt);
    csr_count_kernel<<<(E + 255) / 256, 256>>>(adj_row, cnt, E);
    csr_scan_kernel<<<1, 1024>>>(cnt, rowptr, wp);
    csr_scatter_kernel<<<(E + 255) / 256, 256>>>(adj_row, adj_col, adj_val, wp, scol, sval, E);

    // ---------------- topo GCN stack ----------------
    spmm_csr(g, traw, 500, 0, rowptr, scol, sval);
    batchnorm(traw, t1, NNODES, 500, mean, rstd, A0h, A0l, 512);
    gemm_pre(A0h, A0l, t2_w, nullptr, g, nullptr, nullptr, NNODES, 500, 500, 0, Wh, Wl);

    spmm_csr(g, traw, 500, 0, rowptr, scol, sval);
    batchnorm(traw, t2, NNODES, 500, mean, rstd, A0h, A0l, 512);
    gemm_pre(A0h, A0l, t3_w, nullptr, g, nullptr, nullptr, NNODES, 2000, 500, 0, Wh, Wl);

    spmm_csr(g, traw, 2000, 0, rowptr, scol, sval);
    batchnorm(traw, t3, NNODES, 2000, mean, rstd, A0h, A0l, 2016);
    gemm_pre(A0h, A0l, t4_w, nullptr, g, nullptr, nullptr, NNODES, NZC, 2000, 0, Wh, Wl);

    spmm_csr(g, traw, NZC, 0, rowptr, scol, sval);
    batchnorm(traw, t4, NNODES, NZC, mean, rstd);

    // ---------------- MLP gate u + z_in + agcn ----------------
    u_kernel<<<(NNODES * 32 + 255) / 256, 256>>>(t1, t2, t3, t4, mlpl_w, mlpl_b, u);
    {
        long total = (long)NNODES * 3072;
        zin_conv_kernel<<<(int)((total + 255) / 256), 256>>>(t1, t2, t3, t4, u, A0h, A0l);
    }
    gemm_pre(A0h, A0l, agcn_w, nullptr, g, nullptr, nullptr, NNODES, NZC, COMS_D, 0, Wh, Wl);
    spmm_csr(g, traw, NZC, 1, rowptr, scol, sval);
    batchnorm(traw, ztopo, NNODES, NZC, mean, rstd);

    // ---------------- fused attention + emb BN ----------------
    att_fused_kernel<<<(NNODES + 3) / 4, 256>>>(z, ztopo, att_w1, att_b1, att_w2, embp);
    batchnorm(embp, out_emb, NNODES, NZC, mean, rstd);

    // ---------------- heads ----------------
    heads_kernel<<<NNODES, 64>>>(out_emb, z, cluster, out_pred, out_q);
}

// round 16
// speedup vs baseline: 1.2957x; 1.1284x over previous
#include <cuda_runtime.h>
#include <cuda_bf16.h>
#include <math.h>
#include <stdint.h>

// ---------------------------------------------------------------------------
// Problem constants
// ---------------------------------------------------------------------------
#define NNODES 10000
#define NIN    2000
#define D1     500
#define D2     500
#define D3     2000
#define NZC    64
#define COMS_D 3064
#define EMAX   131072
#define WOFF   (2u * 1024u * 1024u)
#define BN_SLICES 32

// ---------------------------------------------------------------------------
// Scratch (device globals; no allocations allowed)
// ---------------------------------------------------------------------------
__device__ float g_zbuf [NNODES * NZC];
__device__ float g_gbuf [NNODES * 2000];
__device__ float g_traw [NNODES * 2000];
__device__ float g_t1[NNODES * 500];
__device__ float g_t2[NNODES * 500];
__device__ float g_t3[NNODES * 2000];
__device__ float g_t4[NNODES * NZC];
__device__ float g_u [NNODES * 5];
__device__ float g_ztopo[NNODES * NZC];
__device__ float g_embp[NNODES * NZC];
__device__ float g_mean[4096];
__device__ float g_rstd[4096];
__device__ float g_psum[4096];
__device__ float g_psq [4096];

// CSR build
__device__ int   g_cnt[NNODES + 1];
__device__ int   g_rowptr[NNODES + 1];
__device__ int   g_wp[NNODES];
__device__ int   g_scol[EMAX];
__device__ float g_sval[EMAX];

// bf16 split-precision ping-pong A buffers + weight buffers (2 regions)
__device__ __align__(256) __nv_bfloat16 g_A0hi[(size_t)NNODES * 3072];
__device__ __align__(256) __nv_bfloat16 g_A0lo[(size_t)NNODES * 3072];
__device__ __align__(256) __nv_bfloat16 g_A1hi[(size_t)NNODES * 3072];
__device__ __align__(256) __nv_bfloat16 g_A1lo[(size_t)NNODES * 3072];
__device__ __align__(256) __nv_bfloat16 g_Whi[2048 * 3072];
__device__ __align__(256) __nv_bfloat16 g_Wlo[2048 * 3072];

// ---------------------------------------------------------------------------
// PTX helpers
// ---------------------------------------------------------------------------
__device__ __forceinline__ void ldsm4(uint32_t* r, uint32_t addr) {
    asm volatile("ldmatrix.sync.aligned.m8n8.x4.shared.b16 {%0,%1,%2,%3}, [%4];"
                 : "=r"(r[0]), "=r"(r[1]), "=r"(r[2]), "=r"(r[3]) : "r"(addr));
}
__device__ __forceinline__ uint32_t smem_u32(const void* p) {
    uint32_t a;
    asm("{ .reg .u64 t; cvta.to.shared.u64 t, %1; cvt.u32.u64 %0, t; }" : "=r"(a) : "l"(p));
    return a;
}
__device__ __forceinline__ void mma16816(float* c, const uint32_t* a, const uint32_t* b) {
    asm volatile(
        "mma.sync.aligned.m16n8k16.row.col.f32.bf16.bf16.f32 "
        "{%0,%1,%2,%3}, {%4,%5,%6,%7}, {%8,%9}, {%0,%1,%2,%3};"
        : "+f"(c[0]), "+f"(c[1]), "+f"(c[2]), "+f"(c[3])
        : "r"(a[0]), "r"(a[1]), "r"(a[2]), "r"(a[3]), "r"(b[0]), "r"(b[1]));
}
__device__ __forceinline__ void split_bf16(float v, __nv_bfloat16& h, __nv_bfloat16& l) {
    h = __float2bfloat16(v);
    l = __float2bfloat16(v - __bfloat162float(h));
}
__device__ __forceinline__ void cpa16(uint32_t dst, const void* src) {
    asm volatile("cp.async.cg.shared.global [%0], [%1], 16;" :: "r"(dst), "l"(src));
}
__device__ __forceinline__ void cp_commit() {
    asm volatile("cp.async.commit_group;" ::: "memory");
}
template<int N>
__device__ __forceinline__ void cp_wait() {
    asm volatile("cp.async.wait_group %0;" :: "n"(N) : "memory");
}

// ---------------------------------------------------------------------------
// Split-bf16 mma.sync GEMM (R13/R14 winner, unchanged)
// ---------------------------------------------------------------------------
#define ROWB 80
#define A_BYTES (128 * ROWB)
#define B_BYTES (64 * ROWB)
#define STAGE_BYTES (2 * A_BYTES + 2 * B_BYTES)   // 30720
#define GEMM_DSMEM (2 * STAGE_BYTES)              // 61440

__device__ __forceinline__ void load_stage_async(
    uint32_t sbase,
    const __nv_bfloat16* __restrict__ Ahi, const __nv_bfloat16* __restrict__ Alo,
    const __nv_bfloat16* __restrict__ Bhi, const __nv_bfloat16* __restrict__ Blo,
    int mBase, int M, int nBase, int N, int Kpad, int k0, int tid)
{
#pragma unroll
    for (int it = 0; it < 2; it++) {
        int t = tid + it * 256;
        int row = t >> 2, seg = t & 3;
        int gr = mBase + row;
        int sr = (gr < M) ? gr : 0;
        size_t aoff = (size_t)sr * Kpad + k0 + seg * 8;
        uint32_t d = sbase + row * ROWB + seg * 16;
        cpa16(d,           Ahi + aoff);
        cpa16(d + A_BYTES, Alo + aoff);
    }
    {
        int row = tid >> 2, seg = tid & 3;
        int gn = nBase + row;
        int sn = (gn < N) ? gn : 0;
        size_t boff = (size_t)sn * Kpad + k0 + seg * 8;
        uint32_t d = sbase + 2 * A_BYTES + row * ROWB + seg * 16;
        cpa16(d,           Bhi + boff);
        cpa16(d + B_BYTES, Blo + boff);
    }
}

__global__ __launch_bounds__(256, 3) void mma_gemm_kernel(
    const __nv_bfloat16* __restrict__ Ahi, const __nv_bfloat16* __restrict__ Alo,
    const __nv_bfloat16* __restrict__ Bhi, const __nv_bfloat16* __restrict__ Blo,
    const float* __restrict__ bias, float* __restrict__ C,
    __nv_bfloat16* __restrict__ outHi, __nv_bfloat16* __restrict__ outLo, int KpadOut,
    int M, int Ncol, int Kpad, int mode)
{
    extern __shared__ __align__(256) char smem[];
    uint32_t sb = smem_u32(smem);
    int tid = threadIdx.x;
    int wid = tid >> 5, lane = tid & 31;
    int wm = wid & 3, wn = wid >> 2;
    int mBase = blockIdx.y * 128;
    int nBase = blockIdx.x * 64;

    float acc[2][4][4];
#pragma unroll
    for (int mt = 0; mt < 2; mt++)
#pragma unroll
        for (int nt = 0; nt < 4; nt++)
#pragma unroll
            for (int r = 0; r < 4; r++) acc[mt][nt][r] = 0.f;

    const int nc = Kpad >> 5;

    load_stage_async(sb, Ahi, Alo, Bhi, Blo, mBase, M, nBase, Ncol, Kpad, 0, tid);
    cp_commit();
    if (nc > 1) {
        load_stage_async(sb + STAGE_BYTES, Ahi, Alo, Bhi, Blo, mBase, M, nBase, Ncol, Kpad, 32, tid);
        cp_commit();
    }

    int lrow = (lane & 7) + ((lane >> 3) & 1) * 8;
    int lcol8 = (lane >> 4) * 8;

    for (int c = 0; c < nc; c++) {
        if (c + 1 < nc) cp_wait<1>(); else cp_wait<0>();
        __syncthreads();

        uint32_t bufU = sb + (c & 1) * STAGE_BYTES;
        uint32_t aHiS = bufU;
        uint32_t aLoS = bufU + A_BYTES;
        uint32_t bHiS = bufU + 2 * A_BYTES;
        uint32_t bLoS = bHiS + B_BYTES;

        uint32_t ah[2][2][4], al[2][2][4], bh[2][4][2], bl[2][4][2];
#pragma unroll
        for (int ks = 0; ks < 2; ks++) {
            int kc = ks * 16 + lcol8;
#pragma unroll
            for (int mt = 0; mt < 2; mt++) {
                uint32_t o = (wm * 32 + mt * 16 + lrow) * ROWB + kc * 2;
                ldsm4(ah[ks][mt], aHiS + o);
                ldsm4(al[ks][mt], aLoS + o);
            }
#pragma unroll
            for (int ntp = 0; ntp < 2; ntp++) {
                uint32_t o = (wn * 32 + ntp * 16 + lrow) * ROWB + kc * 2;
                uint32_t t[4];
                ldsm4(t, bHiS + o);
                bh[ks][2 * ntp][0] = t[0]; bh[ks][2 * ntp][1] = t[2];
                bh[ks][2 * ntp + 1][0] = t[1]; bh[ks][2 * ntp + 1][1] = t[3];
                ldsm4(t, bLoS + o);
                bl[ks][2 * ntp][0] = t[0]; bl[ks][2 * ntp][1] = t[2];
                bl[ks][2 * ntp + 1][0] = t[1]; bl[ks][2 * ntp + 1][1] = t[3];
            }
        }
#pragma unroll
        for (int ks = 0; ks < 2; ks++)
#pragma unroll
            for (int mt = 0; mt < 2; mt++)
#pragma unroll
                for (int nt = 0; nt < 4; nt++) {
                    mma16816(acc[mt][nt], ah[ks][mt], bh[ks][nt]);
                    mma16816(acc[mt][nt], ah[ks][mt], bl[ks][nt]);
                    mma16816(acc[mt][nt], al[ks][mt], bh[ks][nt]);
                }
        __syncthreads();
        if (c + 2 < nc) {
            load_stage_async(sb + (c & 1) * STAGE_BYTES, Ahi, Alo, Bhi, Blo,
                             mBase, M, nBase, Ncol, Kpad, (c + 2) * 32, tid);
            cp_commit();
        }
    }

    int qr = lane >> 2;
    int qc = (lane & 3) * 2;
#pragma unroll
    for (int mt = 0; mt < 2; mt++) {
#pragma unroll
        for (int nt = 0; nt < 4; nt++) {
#pragma unroll
            for (int half = 0; half < 2; half++) {
                int gr = mBase + wm * 32 + mt * 16 + qr + half * 8;
                if (gr >= M) continue;
#pragma unroll
                for (int e = 0; e < 2; e++) {
                    int gc = nBase + wn * 32 + nt * 8 + qc + e;
                    float v = acc[mt][nt][half * 2 + e];
                    if (gc < Ncol) {
                        if (mode >= 1) v += bias[gc];
                        if (mode == 2) v = v > 0.f ? v : expm1f(v);
                        if (C) C[(size_t)gr * Ncol + gc] = v;
                    } else {
                        v = 0.f;
                    }
                    if (outHi && gc < KpadOut) {
                        __nv_bfloat16 h, l;
                        split_bf16(v, h, l);
                        outHi[(size_t)gr * KpadOut + gc] = h;
                        outLo[(size_t)gr * KpadOut + gc] = l;
                    }
                }
            }
        }
    }
}

// ---------------------------------------------------------------------------
// Conversions
// ---------------------------------------------------------------------------
__global__ void convA_kernel(const float* __restrict__ src,
                             __nv_bfloat16* __restrict__ hi, __nv_bfloat16* __restrict__ lo,
                             int K, int Kpad, long total)
{
    long i = (long)blockIdx.x * blockDim.x + threadIdx.x;
    if (i >= total) return;
    long r = i / Kpad;
    int  k = (int)(i - r * Kpad);
    float v = (k < K) ? src[r * K + k] : 0.f;
    __nv_bfloat16 h, l;
    split_bf16(v, h, l);
    hi[i] = h; lo[i] = l;
}

__global__ void convBT_kernel(const float* __restrict__ B,
                              __nv_bfloat16* __restrict__ bhi, __nv_bfloat16* __restrict__ blo,
                              int K, int N, int Kpad)
{
    __shared__ float sm[32][33];
    int k0 = blockIdx.x * 32, n0 = blockIdx.y * 32;
    int tx = threadIdx.x, ty = threadIdx.y;
    for (int i = ty; i < 32; i += 8) {
        int k = k0 + i, n = n0 + tx;
        sm[i][tx] = (k < K && n < N) ? B[(size_t)k * N + n] : 0.f;
    }
    __syncthreads();
    for (int i = ty; i < 32; i += 8) {
        int n = n0 + i, k = k0 + tx;
        if (n < N && k < Kpad) {
            __nv_bfloat16 h, l;
            split_bf16(sm[tx][i], h, l);
            bhi[(size_t)n * Kpad + k] = h;
            blo[(size_t)n * Kpad + k] = l;
        }
    }
}

// ---------------------------------------------------------------------------
// CSR build + CSR SpMM (float4) with fused activation
// ---------------------------------------------------------------------------
__global__ void csr_zero_kernel(int* cnt) {
    int i = blockIdx.x * blockDim.x + threadIdx.x;
    if (i <= NNODES) cnt[i] = 0;
}
__global__ void csr_count_kernel(const int* __restrict__ row, int* cnt, int E) {
    int e = blockIdx.x * blockDim.x + threadIdx.x;
    if (e < E) atomicAdd(&cnt[row[e] + 1], 1);
}
#define SCAN_PER 10
__global__ __launch_bounds__(1024) void csr_scan_kernel(const int* __restrict__ cnt,
                                                        int* rowptr, int* wp)
{
    __shared__ int sh[1024];
    int t = threadIdx.x;
    int base = t * SCAN_PER;
    int local[SCAN_PER];
    int s = 0;
#pragma unroll
    for (int i = 0; i < SCAN_PER; i++) {
        int idx = base + i;
        int v = (idx < NNODES) ? cnt[idx + 1] : 0;
        s += v;
        local[i] = s;
    }
    sh[t] = s;
    __syncthreads();
    for (int off = 1; off < 1024; off <<= 1) {
        int v = (t >= off) ? sh[t - off] : 0;
        __syncthreads();
        sh[t] += v;
        __syncthreads();
    }
    int prev = (t > 0) ? sh[t - 1] : 0;
    if (t == 0) rowptr[0] = 0;
#pragma unroll
    for (int i = 0; i < SCAN_PER; i++) {
        int idx = base + i;
        if (idx < NNODES) {
            rowptr[idx + 1] = prev + local[i];
            wp[idx] = (i == 0) ? prev : prev + local[i - 1];
        }
    }
}
__global__ void csr_scatter_kernel(const int* __restrict__ row, const int* __restrict__ col,
                                   const float* __restrict__ val, int* wp,
                                   int* scol, float* sval, int E)
{
    int e = blockIdx.x * blockDim.x + threadIdx.x;
    if (e >= E) return;
    int p = atomicAdd(&wp[row[e]], 1);
    scol[p] = col[e];
    sval[p] = val[e];
}

__global__ void spmm_csr_kernel(const float4* __restrict__ H4,
                                const int* __restrict__ rowptr,
                                const int* __restrict__ scol, const float* __restrict__ sval,
                                float4* __restrict__ out4, int D4, int actmode)
{
    int r = blockIdx.x;
    int s = rowptr[r], e_end = rowptr[r + 1];
    int nt = blockDim.x;
    float4 acc[2];
    acc[0] = make_float4(0.f, 0.f, 0.f, 0.f);
    acc[1] = make_float4(0.f, 0.f, 0.f, 0.f);
    int nreg = (D4 + nt - 1) / nt;
    for (int e = s; e < e_end; e++) {
        int c = scol[e];
        float v = sval[e];
        const float4* hrow = H4 + (size_t)c * D4;
#pragma unroll 2
        for (int i = 0; i < 2; i++) {
            if (i >= nreg) break;
            int d = threadIdx.x + i * nt;
            if (d < D4) {
                float4 h = hrow[d];
                acc[i].x = fmaf(v, h.x, acc[i].x);
                acc[i].y = fmaf(v, h.y, acc[i].y);
                acc[i].z = fmaf(v, h.z, acc[i].z);
                acc[i].w = fmaf(v, h.w, acc[i].w);
            }
        }
    }
#pragma unroll 2
    for (int i = 0; i < 2; i++) {
        if (i >= nreg) break;
        int d = threadIdx.x + i * nt;
        if (d < D4) {
            float4 o = acc[i];
            if (actmode == 0) {
                o.x = o.x > 0.f ? o.x : expm1f(0.2f * o.x);
                o.y = o.y > 0.f ? o.y : expm1f(0.2f * o.y);
                o.z = o.z > 0.f ? o.z : expm1f(0.2f * o.z);
                o.w = o.w > 0.f ? o.w : expm1f(0.2f * o.w);
            } else if (actmode == 1) {
                o.x = o.x > 0.f ? o.x : expm1f(o.x);
                o.y = o.y > 0.f ? o.y : expm1f(o.y);
                o.z = o.z > 0.f ? o.z : expm1f(o.z);
                o.w = o.w > 0.f ? o.w : expm1f(o.w);
            }
            out4[(size_t)r * D4 + d] = o;
        }
    }
}
static inline void spmm_csr(const float* H, float* out, int D, int actmode,
                            const int* rowptr, const int* scol, const float* sval)
{
    int D4 = D / 4;
    int threads = (D4 >= 256) ? 256 : ((D4 + 31) & ~31);
    spmm_csr_kernel<<<NNODES, threads>>>((const float4*)H, rowptr, scol, sval,
                                         (float4*)out, D4, actmode);
}

// ---------------------------------------------------------------------------
// BatchNorm: 2-phase parallel stats (atomics over 32 row-slices) + float4 apply
// ---------------------------------------------------------------------------
__global__ void bn_partial_kernel(const float* __restrict__ h, int n, int d,
                                  float* __restrict__ psum, float* __restrict__ psq)
{
    __shared__ float ssum[8][32];
    __shared__ float ssq[8][32];
    int c = blockIdx.x * 32 + threadIdx.x;
    int rows = (n + BN_SLICES - 1) / BN_SLICES;
    int r0 = blockIdx.y * rows;
    int r1 = min(r0 + rows, n);
    float s = 0.f, q = 0.f;
    if (c < d) {
        for (int r = r0 + threadIdx.y; r < r1; r += 8) {
            float v = h[(size_t)r * d + c];
            s += v; q += v * v;
        }
    }
    ssum[threadIdx.y][threadIdx.x] = s;
    ssq[threadIdx.y][threadIdx.x] = q;
    __syncthreads();
    if (threadIdx.y == 0 && c < d) {
#pragma unroll
        for (int i = 1; i < 8; i++) { s += ssum[i][threadIdx.x]; q += ssq[i][threadIdx.x]; }
        atomicAdd(&psum[c], s);
        atomicAdd(&psq[c], q);
    }
}
__global__ void bn_final_kernel(const float* __restrict__ psum, const float* __restrict__ psq,
                                int n, int d, float* __restrict__ mean, float* __restrict__ rstd)
{
    int c = blockIdx.x * blockDim.x + threadIdx.x;
    if (c >= d) return;
    float m = psum[c] / (float)n;
    float var = psq[c] / (float)n - m * m;
    if (var < 0.f) var = 0.f;
    mean[c] = m;
    rstd[c] = rsqrtf(var + 1e-5f);
}
// float4 apply: i indexes float4s over [n, Kpad/4]; d%4==0 so each float4 is
// fully in-data or fully in-pad.
__global__ void bn_apply_kernel(const float4* __restrict__ src4, float4* __restrict__ dst4,
                                long total4, int d4, int kp4,
                                const float* __restrict__ mean, const float* __restrict__ rstd,
                                __nv_bfloat162* __restrict__ outHi, __nv_bfloat162* __restrict__ outLo)
{
    long i = (long)blockIdx.x * blockDim.x + threadIdx.x;
    if (i >= total4) return;
    long r = i / kp4;
    int  c4 = (int)(i - r * kp4);
    float4 v = make_float4(0.f, 0.f, 0.f, 0.f);
    if (c4 < d4) {
        int c = c4 * 4;
        float4 sv = src4[r * d4 + c4];
        v.x = (sv.x - mean[c + 0]) * rstd[c + 0];
        v.y = (sv.y - mean[c + 1]) * rstd[c + 1];
        v.z = (sv.z - mean[c + 2]) * rstd[c + 2];
        v.w = (sv.w - mean[c + 3]) * rstd[c + 3];
        if (dst4) dst4[r * d4 + c4] = v;
    }
    if (outHi) {
        __nv_bfloat16 hx, lx, hy, ly, hz, lz, hw, lw;
        split_bf16(v.x, hx, lx); split_bf16(v.y, hy, ly);
        split_bf16(v.z, hz, lz); split_bf16(v.w, hw, lw);
        outHi[i * 2 + 0] = __nv_bfloat162(hx, hy);
        outHi[i * 2 + 1] = __nv_bfloat162(hz, hw);
        outLo[i * 2 + 0] = __nv_bfloat162(lx, ly);
        outLo[i * 2 + 1] = __nv_bfloat162(lz, lw);
    }
}
static inline void batchnorm(const float* src, float* dst, int n, int d,
                             float* mean, float* rstd, float* psum, float* psq,
                             __nv_bfloat16* outHi = nullptr, __nv_bfloat16* outLo = nullptr,
                             int Kpad = 0)
{
    cudaMemsetAsync(psum, 0, d * sizeof(float), 0);
    cudaMemsetAsync(psq,  0, d * sizeof(float), 0);
    dim3 bt(32, 8);
    dim3 bg((d + 31) / 32, BN_SLICES);
    bn_partial_kernel<<<bg, bt>>>(src, n, d, psum, psq);
    bn_final_kernel<<<(d + 255) / 256, 256>>>(psum, psq, n, d, mean, rstd);
    int kp = outHi ? Kpad : d;
    long total4 = (long)n * (kp / 4);
    bn_apply_kernel<<<(int)((total4 + 255) / 256), 256>>>(
        (const float4*)src, (float4*)dst, total4, d / 4, kp / 4, mean, rstd,
        (__nv_bfloat162*)outHi, (__nv_bfloat162*)outLo);
}

// ---------------------------------------------------------------------------
// Gate u, z_in, fused attention, heads
// ---------------------------------------------------------------------------
__device__ __forceinline__ float coms_at(const float* t1, const float* t2,
                                         const float* t3, const float* t4,
                                         int n, int k)
{
    if (k < 500)  return t1[(size_t)n * 500 + k];
    if (k < 1000) return t2[(size_t)n * 500 + (k - 500)];
    if (k < 3000) return t3[(size_t)n * 2000 + (k - 1000)];
    return t4[(size_t)n * 64 + (k - 3000)];
}

__global__ void u_kernel(const float* __restrict__ t1, const float* __restrict__ t2,
                         const float* __restrict__ t3, const float* __restrict__ t4,
                         const float* __restrict__ W, const float* __restrict__ b,
                         float* __restrict__ u)
{
    int warp = (blockIdx.x * blockDim.x + threadIdx.x) >> 5;
    int lane = threadIdx.x & 31;
    if (warp >= NNODES) return;
    float acc[5] = {0.f, 0.f, 0.f, 0.f, 0.f};
    for (int k = lane; k < COMS_D; k += 32) {
        float v = coms_at(t1, t2, t3, t4, warp, k);
        const float* w = &W[(size_t)k * 5];
#pragma unroll
        for (int j = 0; j < 5; j++) acc[j] = fmaf(v, w[j], acc[j]);
    }
#pragma unroll
    for (int j = 0; j < 5; j++) {
        for (int off = 16; off > 0; off >>= 1)
            acc[j] += __shfl_down_sync(0xFFFFFFFF, acc[j], off);
    }
    if (lane == 0) {
        float l[5], m = -1e30f;
#pragma unroll
        for (int j = 0; j < 5; j++) { l[j] = tanhf(acc[j] + b[j]); m = fmaxf(m, l[j]); }
        float s = 0.f;
#pragma unroll
        for (int j = 0; j < 5; j++) { l[j] = expf(l[j] - m); s += l[j]; }
        float nrm = 0.f;
#pragma unroll
        for (int j = 0; j < 5; j++) { l[j] /= s; nrm += l[j] * l[j]; }
        nrm = fmaxf(sqrtf(nrm), 1e-12f);
#pragma unroll
        for (int j = 0; j < 5; j++) u[(size_t)warp * 5 + j] = l[j] / nrm;
    }
}

__global__ void zin_conv_kernel(const float* __restrict__ t1, const float* __restrict__ t2,
                                const float* __restrict__ t3, const float* __restrict__ t4,
                                const float* __restrict__ u,
                                __nv_bfloat16* __restrict__ hi, __nv_bfloat16* __restrict__ lo)
{
    long i = (long)blockIdx.x * blockDim.x + threadIdx.x;
    long total = (long)NNODES * 3072;
    if (i >= total) return;
    int n = (int)(i / 3072);
    int k = (int)(i % 3072);
    float v = 0.f;
    if (k < COMS_D) {
        int seg = (k < 500) ? 0 : (k < 1000) ? 1 : (k < 3000) ? 2 : 3;
        v = u[(size_t)n * 5 + seg] * coms_at(t1, t2, t3, t4, n, k);
    }
    __nv_bfloat16 h, l;
    split_bf16(v, h, l);
    hi[i] = h; lo[i] = l;
}

__global__ __launch_bounds__(256) void att_fused_kernel(
    const float* __restrict__ z, const float* __restrict__ ztopo,
    const float* __restrict__ W1, const float* __restrict__ b1,
    const float* __restrict__ w2, float* __restrict__ embp)
{
    __shared__ float sW1[64 * 128];
    __shared__ float sb1[128];
    __shared__ float sw2[128];
    __shared__ float sS[8][64];
    __shared__ float sc[8];
    int tid = threadIdx.x;
    for (int i = tid; i < 64 * 128; i += 256) sW1[i] = W1[i];
    if (tid < 128) { sb1[tid] = b1[tid]; sw2[tid] = w2[tid]; }

    int wid = tid >> 5, lane = tid & 31;
    int nodeBase = blockIdx.x * 4;
    int n = nodeBase + (wid >> 1);
    int br = wid & 1;
    bool valid = (n < NNODES);
    if (valid) {
        const float* s = br ? &ztopo[(size_t)n * 64] : &z[(size_t)n * 64];
        sS[wid][lane] = s[lane];
        sS[wid][lane + 32] = s[lane + 32];
    }
    __syncthreads();

    float partial = 0.f;
    if (valid) {
#pragma unroll
        for (int jj = 0; jj < 4; jj++) {
            int j = lane + jj * 32;
            float h = sb1[j];
#pragma unroll
            for (int k = 0; k < 64; k++)
                h = fmaf(sS[wid][k], sW1[k * 128 + j], h);
            partial = fmaf(tanhf(h), sw2[j], partial);
        }
    }
    for (int off = 16; off > 0; off >>= 1)
        partial += __shfl_down_sync(0xFFFFFFFF, partial, off);
    if (lane == 0) sc[wid] = partial;
    __syncthreads();

    int nl = tid >> 6;
    int d  = tid & 63;
    int n2 = nodeBase + nl;
    if (n2 < NNODES) {
        float s0 = sc[nl * 2], s1 = sc[nl * 2 + 1];
        float m = fmaxf(s0, s1);
        float e0 = expf(s0 - m), e1 = expf(s1 - m);
        float inv = 1.f / (e0 + e1);
        embp[(size_t)n2 * 64 + d] = (e0 * inv) * z[(size_t)n2 * 64 + d]
                                  + (e1 * inv) * ztopo[(size_t)n2 * 64 + d];
    }
}

__global__ void heads_kernel(const float* __restrict__ emb, const float* __restrict__ z,
                             const float* __restrict__ cluster,
                             float* __restrict__ pred, float* __restrict__ q)
{
    int n = blockIdx.x;
    int t = threadIdx.x;
    __shared__ float sh[64];
    __shared__ float zs[64];

    float v = emb[(size_t)n * 64 + t];
    sh[t] = v;
    __syncthreads();
    for (int s = 32; s > 0; s >>= 1) {
        if (t < s) sh[t] = fmaxf(sh[t], sh[t + s]);
        __syncthreads();
    }
    float m = sh[0];
    __syncthreads();
    float e = expf(v - m);
    sh[t] = e;
    __syncthreads();
    for (int s = 32; s > 0; s >>= 1) {
        if (t < s) sh[t] += sh[t + s];
        __syncthreads();
    }
    pred[(size_t)n * 64 + t] = e / sh[0];
    __syncthreads();

    zs[t] = z[(size_t)n * 64 + t];
    __syncthreads();
    float d2 = 0.f;
    const float* c = &cluster[(size_t)t * 64];
    for (int k = 0; k < 64; k++) {
        float diff = zs[k] - c[k];
        d2 = fmaf(diff, diff, d2);
    }
    float qv = 1.f / (1.f + d2);
    sh[t] = qv;
    __syncthreads();
    for (int s = 32; s > 0; s >>= 1) {
        if (t < s) sh[t] += sh[t + s];
        __syncthreads();
    }
    q[(size_t)n * 64 + t] = qv / sh[0];
}

// ---------------------------------------------------------------------------
// Host-side helpers
// ---------------------------------------------------------------------------
static inline void conv_w(const float* Bw, int K, int N,
                          __nv_bfloat16* Whi, __nv_bfloat16* Wlo, int wsel)
{
    int Kpad = (K + 31) & ~31;
    dim3 tg((Kpad + 31) / 32, (N + 31) / 32);
    convBT_kernel<<<tg, dim3(32, 8)>>>(Bw, Whi + (size_t)wsel * WOFF, Wlo + (size_t)wsel * WOFF, K, N, Kpad);
}

static inline void gemm_run(const __nv_bfloat16* aHi, const __nv_bfloat16* aLo,
                            const float* bias, float* C,
                            __nv_bfloat16* outHi, __nv_bfloat16* outLo,
                            int M, int N, int K, int mode,
                            __nv_bfloat16* Whi, __nv_bfloat16* Wlo, int wsel)
{
    int Kpad = (K + 31) & ~31;
    int KpadOut = (N + 31) & ~31;
    cudaFuncSetAttribute(mma_gemm_kernel, cudaFuncAttributeMaxDynamicSharedMemorySize, GEMM_DSMEM);
    dim3 grid((N + 63) / 64, (M + 127) / 128);
    mma_gemm_kernel<<<grid, 256, GEMM_DSMEM>>>(aHi, aLo,
                                               Whi + (size_t)wsel * WOFF, Wlo + (size_t)wsel * WOFF,
                                               bias, C, outHi, outLo, KpadOut, M, N, Kpad, mode);
}

static inline void gemm_pre(const __nv_bfloat16* aHi, const __nv_bfloat16* aLo,
                            const float* Bw, const float* bias, float* C,
                            __nv_bfloat16* outHi, __nv_bfloat16* outLo,
                            int M, int N, int K, int mode,
                            __nv_bfloat16* Whi, __nv_bfloat16* Wlo)
{
    conv_w(Bw, K, N, Whi, Wlo, 0);
    gemm_run(aHi, aLo, bias, C, outHi, outLo, M, N, K, mode, Whi, Wlo, 0);
}

// ---------------------------------------------------------------------------
// Launch
// ---------------------------------------------------------------------------
extern "C" void kernel_launch(void* const* d_in, const int* in_sizes, int n_in,
                              void* d_out, int out_size)
{
    const float* x       = (const float*)d_in[0];
    const float* adj_val = (const float*)d_in[1];
    const float* enc1_w  = (const float*)d_in[2];
    const float* enc1_b  = (const float*)d_in[3];
    const float* enc2_w  = (const float*)d_in[4];
    const float* enc2_b  = (const float*)d_in[5];
    const float* enc3_w  = (const float*)d_in[6];
    const float* enc3_b  = (const float*)d_in[7];
    const float* zl_w    = (const float*)d_in[8];
    const float* zl_b    = (const float*)d_in[9];
    const float* dec1_w  = (const float*)d_in[10];
    const float* dec1_b  = (const float*)d_in[11];
    const float* dec2_w  = (const float*)d_in[12];
    const float* dec2_b  = (const float*)d_in[13];
    const float* dec3_w  = (const float*)d_in[14];
    const float* dec3_b  = (const float*)d_in[15];
    const float* xbar_w  = (const float*)d_in[16];
    const float* xbar_b  = (const float*)d_in[17];
    const float* t1_w    = (const float*)d_in[18];
    const float* t2_w    = (const float*)d_in[19];
    const float* t3_w    = (const float*)d_in[20];
    const float* t4_w    = (const float*)d_in[21];
    const float* agcn_w  = (const float*)d_in[22];
    const float* mlpl_w  = (const float*)d_in[23];
    const float* mlpl_b  = (const float*)d_in[24];
    const float* att_w1  = (const float*)d_in[25];
    const float* att_b1  = (const float*)d_in[26];
    const float* att_w2  = (const float*)d_in[27];
    const float* cluster = (const float*)d_in[28];
    const int*   adj_row = (const int*)d_in[29];
    const int*   adj_col = (const int*)d_in[30];
    const int E = in_sizes[1];

    float* out      = (float*)d_out;
    float* out_xbar = out;
    float* out_q    = out + (size_t)NNODES * NIN;
    float* out_pred = out_q + (size_t)NNODES * NZC;
    float* out_emb  = out_pred + (size_t)NNODES * NZC;

    float *z, *g, *traw, *t1, *t2, *t3, *t4, *u, *ztopo, *embp, *mean, *rstd, *psum, *psq;
    int *cnt, *rowptr, *wp, *scol;
    float *sval;
    __nv_bfloat16 *A0h, *A0l, *A1h, *A1l, *Wh, *Wl;
    cudaGetSymbolAddress((void**)&z,  g_zbuf);
    cudaGetSymbolAddress((void**)&g,  g_gbuf);
    cudaGetSymbolAddress((void**)&traw, g_traw);
    cudaGetSymbolAddress((void**)&t1, g_t1);
    cudaGetSymbolAddress((void**)&t2, g_t2);
    cudaGetSymbolAddress((void**)&t3, g_t3);
    cudaGetSymbolAddress((void**)&t4, g_t4);
    cudaGetSymbolAddress((void**)&u,  g_u);
    cudaGetSymbolAddress((void**)&ztopo, g_ztopo);
    cudaGetSymbolAddress((void**)&embp, g_embp);
    cudaGetSymbolAddress((void**)&mean, g_mean);
    cudaGetSymbolAddress((void**)&rstd, g_rstd);
    cudaGetSymbolAddress((void**)&psum, g_psum);
    cudaGetSymbolAddress((void**)&psq,  g_psq);
    cudaGetSymbolAddress((void**)&cnt, g_cnt);
    cudaGetSymbolAddress((void**)&rowptr, g_rowptr);
    cudaGetSymbolAddress((void**)&wp, g_wp);
    cudaGetSymbolAddress((void**)&scol, g_scol);
    cudaGetSymbolAddress((void**)&sval, g_sval);
    cudaGetSymbolAddress((void**)&A0h, g_A0hi);
    cudaGetSymbolAddress((void**)&A0l, g_A0lo);
    cudaGetSymbolAddress((void**)&A1h, g_A1hi);
    cudaGetSymbolAddress((void**)&A1l, g_A1lo);
    cudaGetSymbolAddress((void**)&Wh, g_Whi);
    cudaGetSymbolAddress((void**)&Wl, g_Wlo);

    // ---------------- convert x + first two weights, then GEMMs back-to-back
    {
        int Kpad = 2016;
        long tA = (long)NNODES * Kpad;
        convA_kernel<<<(int)((tA + 255) / 256), 256>>>(x, A0h, A0l, NIN, Kpad, tA);
    }
    conv_w(t1_w, NIN, 500, Wh, Wl, 0);
    conv_w(enc1_w, NIN, D1, Wh, Wl, 1);
    gemm_run(A0h, A0l, nullptr, g, nullptr, nullptr, NNODES, 500, NIN, 0, Wh, Wl, 0);
    gemm_run(A0h, A0l, enc1_b, nullptr, A1h, A1l, NNODES, D1, NIN, 2, Wh, Wl, 1);

    // ---------------- rest of AE chain ----------------
    gemm_pre(A1h, A1l, enc2_w, enc2_b, nullptr, A0h, A0l, NNODES, D2, D1, 2, Wh, Wl);
    gemm_pre(A0h, A0l, enc3_w, enc3_b, nullptr, A1h, A1l, NNODES, D3, D2, 2, Wh, Wl);
    gemm_pre(A1h, A1l, zl_w, zl_b, z, A0h, A0l, NNODES, NZC, D3, 1, Wh, Wl);
    gemm_pre(A0h, A0l, dec1_w, dec1_b, nullptr, A1h, A1l, NNODES, 2000, NZC, 2, Wh, Wl);
    gemm_pre(A1h, A1l, dec2_w, dec2_b, nullptr, A0h, A0l, NNODES, 500, 2000, 2, Wh, Wl);
    gemm_pre(A0h, A0l, dec3_w, dec3_b, nullptr, A1h, A1l, NNODES, 500, 500, 2, Wh, Wl);
    gemm_pre(A1h, A1l, xbar_w, xbar_b, out_xbar, nullptr, nullptr, NNODES, NIN, 500, 1, Wh, Wl);

    // ---------------- CSR build ----------------
    csr_zero_kernel<<<(NNODES + 256) / 256, 256>>>(cnt);
    csr_count_kernel<<<(E + 255) / 256, 256>>>(adj_row, cnt, E);
    csr_scan_kernel<<<1, 1024>>>(cnt, rowptr, wp);
    csr_scatter_kernel<<<(E + 255) / 256, 256>>>(adj_row, adj_col, adj_val, wp, scol, sval, E);

    // ---------------- topo GCN stack ----------------
    spmm_csr(g, traw, 500, 0, rowptr, scol, sval);
    batchnorm(traw, t1, NNODES, 500, mean, rstd, psum, psq, A0h, A0l, 512);
    gemm_pre(A0h, A0l, t2_w, nullptr, g, nullptr, nullptr, NNODES, 500, 500, 0, Wh, Wl);

    spmm_csr(g, traw, 500, 0, rowptr, scol, sval);
    batchnorm(traw, t2, NNODES, 500, mean, rstd, psum, psq, A0h, A0l, 512);
    gemm_pre(A0h, A0l, t3_w, nullptr, g, nullptr, nullptr, NNODES, 2000, 500, 0, Wh, Wl);

    spmm_csr(g, traw, 2000, 0, rowptr, scol, sval);
    batchnorm(traw, t3, NNODES, 2000, mean, rstd, psum, psq, A0h, A0l, 2016);
    gemm_pre(A0h, A0l, t4_w, nullptr, g, nullptr, nullptr, NNODES, NZC, 2000, 0, Wh, Wl);

    spmm_csr(g, traw, NZC, 0, rowptr, scol, sval);
    batchnorm(traw, t4, NNODES, NZC, mean, rstd, psum, psq);

    // ---------------- MLP gate u + z_in + agcn ----------------
    u_kernel<<<(NNODES * 32 + 255) / 256, 256>>>(t1, t2, t3, t4, mlpl_w, mlpl_b, u);
    {
        long total = (long)NNODES * 3072;
        zin_conv_kernel<<<(int)((total + 255) / 256), 256>>>(t1, t2, t3, t4, u, A0h, A0l);
    }
    gemm_pre(A0h, A0l, agcn_w, nullptr, g, nullptr, nullptr, NNODES, NZC, COMS_D, 0, Wh, Wl);
    spmm_csr(g, traw, NZC, 1, rowptr, scol, sval);
    batchnorm(traw, ztopo, NNODES, NZC, mean, rstd, psum, psq);

    // ---------------- fused attention + emb BN ----------------
    att_fused_kernel<<<(NNODES + 3) / 4, 256>>>(z, ztopo, att_w1, att_b1, att_w2, embp);
    batchnorm(embp, out_emb, NNODES, NZC, mean, rstd, psum, psq);

    // ---------------- heads ----------------
    heads_kernel<<<NNODES, 64>>>(out_emb, z, cluster, out_pred, out_q);
}

// round 17
// speedup vs baseline: 1.4910x; 1.1507x over previous
#include <cuda_runtime.h>
#include <cuda_bf16.h>
#include <math.h>
#include <stdint.h>

// ---------------------------------------------------------------------------
// Problem constants
// ---------------------------------------------------------------------------
#define NNODES 10000
#define NIN    2000
#define D1     500
#define D2     500
#define D3     2000
#define NZC    64
#define COMS_D 3064
#define EMAX   131072
#define WOFF   (2u * 1024u * 1024u)
#define BN_SLICES 32

// ---------------------------------------------------------------------------
// Scratch (device globals; no allocations allowed)
// ---------------------------------------------------------------------------
__device__ float g_zbuf [NNODES * NZC];
__device__ float g_gbuf [NNODES * 2000];
__device__ float g_traw [NNODES * 2000];
__device__ float g_t1[NNODES * 500];
__device__ float g_t2[NNODES * 500];
__device__ float g_t3[NNODES * 2000];
__device__ float g_t4[NNODES * NZC];
__device__ float g_u [NNODES * 5];
__device__ float g_ztopo[NNODES * NZC];
__device__ float g_embp[NNODES * NZC];
__device__ float g_mean[4096];
__device__ float g_rstd[4096];
__device__ float g_psum[4096];
__device__ float g_psq [4096];

// CSR build
__device__ int   g_cnt[NNODES + 1];
__device__ int   g_rowptr[NNODES + 1];
__device__ int   g_wp[NNODES];
__device__ int   g_scol[EMAX];
__device__ float g_sval[EMAX];

// bf16 split-precision buffers: A0 = x (read-only after conv);
// A1/A3 = AE ping-pong; A2 = topo chain. W regions: 0 = AE, 1 = topo.
__device__ __align__(256) __nv_bfloat16 g_A0hi[(size_t)NNODES * 3072];
__device__ __align__(256) __nv_bfloat16 g_A0lo[(size_t)NNODES * 3072];
__device__ __align__(256) __nv_bfloat16 g_A1hi[(size_t)NNODES * 3072];
__device__ __align__(256) __nv_bfloat16 g_A1lo[(size_t)NNODES * 3072];
__device__ __align__(256) __nv_bfloat16 g_A2hi[(size_t)NNODES * 3072];
__device__ __align__(256) __nv_bfloat16 g_A2lo[(size_t)NNODES * 3072];
__device__ __align__(256) __nv_bfloat16 g_A3hi[(size_t)NNODES * 3072];
__device__ __align__(256) __nv_bfloat16 g_A3lo[(size_t)NNODES * 3072];
__device__ __align__(256) __nv_bfloat16 g_Whi[2048 * 3072];
__device__ __align__(256) __nv_bfloat16 g_Wlo[2048 * 3072];

// ---------------------------------------------------------------------------
// PTX helpers
// ---------------------------------------------------------------------------
__device__ __forceinline__ void ldsm4(uint32_t* r, uint32_t addr) {
    asm volatile("ldmatrix.sync.aligned.m8n8.x4.shared.b16 {%0,%1,%2,%3}, [%4];"
                 : "=r"(r[0]), "=r"(r[1]), "=r"(r[2]), "=r"(r[3]) : "r"(addr));
}
__device__ __forceinline__ uint32_t smem_u32(const void* p) {
    uint32_t a;
    asm("{ .reg .u64 t; cvta.to.shared.u64 t, %1; cvt.u32.u64 %0, t; }" : "=r"(a) : "l"(p));
    return a;
}
__device__ __forceinline__ void mma16816(float* c, const uint32_t* a, const uint32_t* b) {
    asm volatile(
        "mma.sync.aligned.m16n8k16.row.col.f32.bf16.bf16.f32 "
        "{%0,%1,%2,%3}, {%4,%5,%6,%7}, {%8,%9}, {%0,%1,%2,%3};"
        : "+f"(c[0]), "+f"(c[1]), "+f"(c[2]), "+f"(c[3])
        : "r"(a[0]), "r"(a[1]), "r"(a[2]), "r"(a[3]), "r"(b[0]), "r"(b[1]));
}
__device__ __forceinline__ void split_bf16(float v, __nv_bfloat16& h, __nv_bfloat16& l) {
    h = __float2bfloat16(v);
    l = __float2bfloat16(v - __bfloat162float(h));
}
__device__ __forceinline__ void cpa16(uint32_t dst, const void* src) {
    asm volatile("cp.async.cg.shared.global [%0], [%1], 16;" :: "r"(dst), "l"(src));
}
__device__ __forceinline__ void cp_commit() {
    asm volatile("cp.async.commit_group;" ::: "memory");
}
template<int N>
__device__ __forceinline__ void cp_wait() {
    asm volatile("cp.async.wait_group %0;" :: "n"(N) : "memory");
}

// ---------------------------------------------------------------------------
// Split-bf16 mma.sync GEMM (R13/R14/R16 winner, unchanged)
// ---------------------------------------------------------------------------
#define ROWB 80
#define A_BYTES (128 * ROWB)
#define B_BYTES (64 * ROWB)
#define STAGE_BYTES (2 * A_BYTES + 2 * B_BYTES)   // 30720
#define GEMM_DSMEM (2 * STAGE_BYTES)              // 61440

__device__ __forceinline__ void load_stage_async(
    uint32_t sbase,
    const __nv_bfloat16* __restrict__ Ahi, const __nv_bfloat16* __restrict__ Alo,
    const __nv_bfloat16* __restrict__ Bhi, const __nv_bfloat16* __restrict__ Blo,
    int mBase, int M, int nBase, int N, int Kpad, int k0, int tid)
{
#pragma unroll
    for (int it = 0; it < 2; it++) {
        int t = tid + it * 256;
        int row = t >> 2, seg = t & 3;
        int gr = mBase + row;
        int sr = (gr < M) ? gr : 0;
        size_t aoff = (size_t)sr * Kpad + k0 + seg * 8;
        uint32_t d = sbase + row * ROWB + seg * 16;
        cpa16(d,           Ahi + aoff);
        cpa16(d + A_BYTES, Alo + aoff);
    }
    {
        int row = tid >> 2, seg = tid & 3;
        int gn = nBase + row;
        int sn = (gn < N) ? gn : 0;
        size_t boff = (size_t)sn * Kpad + k0 + seg * 8;
        uint32_t d = sbase + 2 * A_BYTES + row * ROWB + seg * 16;
        cpa16(d,           Bhi + boff);
        cpa16(d + B_BYTES, Blo + boff);
    }
}

__global__ __launch_bounds__(256, 3) void mma_gemm_kernel(
    const __nv_bfloat16* __restrict__ Ahi, const __nv_bfloat16* __restrict__ Alo,
    const __nv_bfloat16* __restrict__ Bhi, const __nv_bfloat16* __restrict__ Blo,
    const float* __restrict__ bias, float* __restrict__ C,
    __nv_bfloat16* __restrict__ outHi, __nv_bfloat16* __restrict__ outLo, int KpadOut,
    int M, int Ncol, int Kpad, int mode)
{
    extern __shared__ __align__(256) char smem[];
    uint32_t sb = smem_u32(smem);
    int tid = threadIdx.x;
    int wid = tid >> 5, lane = tid & 31;
    int wm = wid & 3, wn = wid >> 2;
    int mBase = blockIdx.y * 128;
    int nBase = blockIdx.x * 64;

    float acc[2][4][4];
#pragma unroll
    for (int mt = 0; mt < 2; mt++)
#pragma unroll
        for (int nt = 0; nt < 4; nt++)
#pragma unroll
            for (int r = 0; r < 4; r++) acc[mt][nt][r] = 0.f;

    const int nc = Kpad >> 5;

    load_stage_async(sb, Ahi, Alo, Bhi, Blo, mBase, M, nBase, Ncol, Kpad, 0, tid);
    cp_commit();
    if (nc > 1) {
        load_stage_async(sb + STAGE_BYTES, Ahi, Alo, Bhi, Blo, mBase, M, nBase, Ncol, Kpad, 32, tid);
        cp_commit();
    }

    int lrow = (lane & 7) + ((lane >> 3) & 1) * 8;
    int lcol8 = (lane >> 4) * 8;

    for (int c = 0; c < nc; c++) {
        if (c + 1 < nc) cp_wait<1>(); else cp_wait<0>();
        __syncthreads();

        uint32_t bufU = sb + (c & 1) * STAGE_BYTES;
        uint32_t aHiS = bufU;
        uint32_t aLoS = bufU + A_BYTES;
        uint32_t bHiS = bufU + 2 * A_BYTES;
        uint32_t bLoS = bHiS + B_BYTES;

        uint32_t ah[2][2][4], al[2][2][4], bh[2][4][2], bl[2][4][2];
#pragma unroll
        for (int ks = 0; ks < 2; ks++) {
            int kc = ks * 16 + lcol8;
#pragma unroll
            for (int mt = 0; mt < 2; mt++) {
                uint32_t o = (wm * 32 + mt * 16 + lrow) * ROWB + kc * 2;
                ldsm4(ah[ks][mt], aHiS + o);
                ldsm4(al[ks][mt], aLoS + o);
            }
#pragma unroll
            for (int ntp = 0; ntp < 2; ntp++) {
                uint32_t o = (wn * 32 + ntp * 16 + lrow) * ROWB + kc * 2;
                uint32_t t[4];
                ldsm4(t, bHiS + o);
                bh[ks][2 * ntp][0] = t[0]; bh[ks][2 * ntp][1] = t[2];
                bh[ks][2 * ntp + 1][0] = t[1]; bh[ks][2 * ntp + 1][1] = t[3];
                ldsm4(t, bLoS + o);
                bl[ks][2 * ntp][0] = t[0]; bl[ks][2 * ntp][1] = t[2];
                bl[ks][2 * ntp + 1][0] = t[1]; bl[ks][2 * ntp + 1][1] = t[3];
            }
        }
#pragma unroll
        for (int ks = 0; ks < 2; ks++)
#pragma unroll
            for (int mt = 0; mt < 2; mt++)
#pragma unroll
                for (int nt = 0; nt < 4; nt++) {
                    mma16816(acc[mt][nt], ah[ks][mt], bh[ks][nt]);
                    mma16816(acc[mt][nt], ah[ks][mt], bl[ks][nt]);
                    mma16816(acc[mt][nt], al[ks][mt], bh[ks][nt]);
                }
        __syncthreads();
        if (c + 2 < nc) {
            load_stage_async(sb + (c & 1) * STAGE_BYTES, Ahi, Alo, Bhi, Blo,
                             mBase, M, nBase, Ncol, Kpad, (c + 2) * 32, tid);
            cp_commit();
        }
    }

    int qr = lane >> 2;
    int qc = (lane & 3) * 2;
#pragma unroll
    for (int mt = 0; mt < 2; mt++) {
#pragma unroll
        for (int nt = 0; nt < 4; nt++) {
#pragma unroll
            for (int half = 0; half < 2; half++) {
                int gr = mBase + wm * 32 + mt * 16 + qr + half * 8;
                if (gr >= M) continue;
#pragma unroll
                for (int e = 0; e < 2; e++) {
                    int gc = nBase + wn * 32 + nt * 8 + qc + e;
                    float v = acc[mt][nt][half * 2 + e];
                    if (gc < Ncol) {
                        if (mode >= 1) v += bias[gc];
                        if (mode == 2) v = v > 0.f ? v : expm1f(v);
                        if (C) C[(size_t)gr * Ncol + gc] = v;
                    } else {
                        v = 0.f;
                    }
                    if (outHi && gc < KpadOut) {
                        __nv_bfloat16 h, l;
                        split_bf16(v, h, l);
                        outHi[(size_t)gr * KpadOut + gc] = h;
                        outLo[(size_t)gr * KpadOut + gc] = l;
                    }
                }
            }
        }
    }
}

// ---------------------------------------------------------------------------
// Conversions
// ---------------------------------------------------------------------------
__global__ void convA_kernel(const float* __restrict__ src,
                             __nv_bfloat16* __restrict__ hi, __nv_bfloat16* __restrict__ lo,
                             int K, int Kpad, long total)
{
    long i = (long)blockIdx.x * blockDim.x + threadIdx.x;
    if (i >= total) return;
    long r = i / Kpad;
    int  k = (int)(i - r * Kpad);
    float v = (k < K) ? src[r * K + k] : 0.f;
    __nv_bfloat16 h, l;
    split_bf16(v, h, l);
    hi[i] = h; lo[i] = l;
}

__global__ void convBT_kernel(const float* __restrict__ B,
                              __nv_bfloat16* __restrict__ bhi, __nv_bfloat16* __restrict__ blo,
                              int K, int N, int Kpad)
{
    __shared__ float sm[32][33];
    int k0 = blockIdx.x * 32, n0 = blockIdx.y * 32;
    int tx = threadIdx.x, ty = threadIdx.y;
    for (int i = ty; i < 32; i += 8) {
        int k = k0 + i, n = n0 + tx;
        sm[i][tx] = (k < K && n < N) ? B[(size_t)k * N + n] : 0.f;
    }
    __syncthreads();
    for (int i = ty; i < 32; i += 8) {
        int n = n0 + i, k = k0 + tx;
        if (n < N && k < Kpad) {
            __nv_bfloat16 h, l;
            split_bf16(sm[tx][i], h, l);
            bhi[(size_t)n * Kpad + k] = h;
            blo[(size_t)n * Kpad + k] = l;
        }
    }
}

// ---------------------------------------------------------------------------
// CSR build + CSR SpMM (float4) with fused activation
// ---------------------------------------------------------------------------
__global__ void csr_zero_kernel(int* cnt) {
    int i = blockIdx.x * blockDim.x + threadIdx.x;
    if (i <= NNODES) cnt[i] = 0;
}
__global__ void csr_count_kernel(const int* __restrict__ row, int* cnt, int E) {
    int e = blockIdx.x * blockDim.x + threadIdx.x;
    if (e < E) atomicAdd(&cnt[row[e] + 1], 1);
}
#define SCAN_PER 10
__global__ __launch_bounds__(1024) void csr_scan_kernel(const int* __restrict__ cnt,
                                                        int* rowptr, int* wp)
{
    __shared__ int sh[1024];
    int t = threadIdx.x;
    int base = t * SCAN_PER;
    int local[SCAN_PER];
    int s = 0;
#pragma unroll
    for (int i = 0; i < SCAN_PER; i++) {
        int idx = base + i;
        int v = (idx < NNODES) ? cnt[idx + 1] : 0;
        s += v;
        local[i] = s;
    }
    sh[t] = s;
    __syncthreads();
    for (int off = 1; off < 1024; off <<= 1) {
        int v = (t >= off) ? sh[t - off] : 0;
        __syncthreads();
        sh[t] += v;
        __syncthreads();
    }
    int prev = (t > 0) ? sh[t - 1] : 0;
    if (t == 0) rowptr[0] = 0;
#pragma unroll
    for (int i = 0; i < SCAN_PER; i++) {
        int idx = base + i;
        if (idx < NNODES) {
            rowptr[idx + 1] = prev + local[i];
            wp[idx] = (i == 0) ? prev : prev + local[i - 1];
        }
    }
}
__global__ void csr_scatter_kernel(const int* __restrict__ row, const int* __restrict__ col,
                                   const float* __restrict__ val, int* wp,
                                   int* scol, float* sval, int E)
{
    int e = blockIdx.x * blockDim.x + threadIdx.x;
    if (e >= E) return;
    int p = atomicAdd(&wp[row[e]], 1);
    scol[p] = col[e];
    sval[p] = val[e];
}

__global__ void spmm_csr_kernel(const float4* __restrict__ H4,
                                const int* __restrict__ rowptr,
                                const int* __restrict__ scol, const float* __restrict__ sval,
                                float4* __restrict__ out4, int D4, int actmode)
{
    int r = blockIdx.x;
    int s = rowptr[r], e_end = rowptr[r + 1];
    int nt = blockDim.x;
    float4 acc[2];
    acc[0] = make_float4(0.f, 0.f, 0.f, 0.f);
    acc[1] = make_float4(0.f, 0.f, 0.f, 0.f);
    int nreg = (D4 + nt - 1) / nt;
    for (int e = s; e < e_end; e++) {
        int c = scol[e];
        float v = sval[e];
        const float4* hrow = H4 + (size_t)c * D4;
#pragma unroll 2
        for (int i = 0; i < 2; i++) {
            if (i >= nreg) break;
            int d = threadIdx.x + i * nt;
            if (d < D4) {
                float4 h = hrow[d];
                acc[i].x = fmaf(v, h.x, acc[i].x);
                acc[i].y = fmaf(v, h.y, acc[i].y);
                acc[i].z = fmaf(v, h.z, acc[i].z);
                acc[i].w = fmaf(v, h.w, acc[i].w);
            }
        }
    }
#pragma unroll 2
    for (int i = 0; i < 2; i++) {
        if (i >= nreg) break;
        int d = threadIdx.x + i * nt;
        if (d < D4) {
            float4 o = acc[i];
            if (actmode == 0) {
                o.x = o.x > 0.f ? o.x : expm1f(0.2f * o.x);
                o.y = o.y > 0.f ? o.y : expm1f(0.2f * o.y);
                o.z = o.z > 0.f ? o.z : expm1f(0.2f * o.z);
                o.w = o.w > 0.f ? o.w : expm1f(0.2f * o.w);
            } else if (actmode == 1) {
                o.x = o.x > 0.f ? o.x : expm1f(o.x);
                o.y = o.y > 0.f ? o.y : expm1f(o.y);
                o.z = o.z > 0.f ? o.z : expm1f(o.z);
                o.w = o.w > 0.f ? o.w : expm1f(o.w);
            }
            out4[(size_t)r * D4 + d] = o;
        }
    }
}
static inline void spmm_csr(const float* H, float* out, int D, int actmode,
                            const int* rowptr, const int* scol, const float* sval,
                            cudaStream_t st)
{
    int D4 = D / 4;
    int threads = (D4 >= 256) ? 256 : ((D4 + 31) & ~31);
    spmm_csr_kernel<<<NNODES, threads, 0, st>>>((const float4*)H, rowptr, scol, sval,
                                                (float4*)out, D4, actmode);
}

// ---------------------------------------------------------------------------
// BatchNorm: 2-phase parallel stats + float4 apply
// ---------------------------------------------------------------------------
__global__ void bn_partial_kernel(const float* __restrict__ h, int n, int d,
                                  float* __restrict__ psum, float* __restrict__ psq)
{
    __shared__ float ssum[8][32];
    __shared__ float ssq[8][32];
    int c = blockIdx.x * 32 + threadIdx.x;
    int rows = (n + BN_SLICES - 1) / BN_SLICES;
    int r0 = blockIdx.y * rows;
    int r1 = min(r0 + rows, n);
    float s = 0.f, q = 0.f;
    if (c < d) {
        for (int r = r0 + threadIdx.y; r < r1; r += 8) {
            float v = h[(size_t)r * d + c];
            s += v; q += v * v;
        }
    }
    ssum[threadIdx.y][threadIdx.x] = s;
    ssq[threadIdx.y][threadIdx.x] = q;
    __syncthreads();
    if (threadIdx.y == 0 && c < d) {
#pragma unroll
        for (int i = 1; i < 8; i++) { s += ssum[i][threadIdx.x]; q += ssq[i][threadIdx.x]; }
        atomicAdd(&psum[c], s);
        atomicAdd(&psq[c], q);
    }
}
__global__ void bn_final_kernel(const float* __restrict__ psum, const float* __restrict__ psq,
                                int n, int d, float* __restrict__ mean, float* __restrict__ rstd)
{
    int c = blockIdx.x * blockDim.x + threadIdx.x;
    if (c >= d) return;
    float m = psum[c] / (float)n;
    float var = psq[c] / (float)n - m * m;
    if (var < 0.f) var = 0.f;
    mean[c] = m;
    rstd[c] = rsqrtf(var + 1e-5f);
}
__global__ void bn_apply_kernel(const float4* __restrict__ src4, float4* __restrict__ dst4,
                                long total4, int d4, int kp4,
                                const float* __restrict__ mean, const float* __restrict__ rstd,
                                __nv_bfloat162* __restrict__ outHi, __nv_bfloat162* __restrict__ outLo)
{
    long i = (long)blockIdx.x * blockDim.x + threadIdx.x;
    if (i >= total4) return;
    long r = i / kp4;
    int  c4 = (int)(i - r * kp4);
    float4 v = make_float4(0.f, 0.f, 0.f, 0.f);
    if (c4 < d4) {
        int c = c4 * 4;
        float4 sv = src4[r * d4 + c4];
        v.x = (sv.x - mean[c + 0]) * rstd[c + 0];
        v.y = (sv.y - mean[c + 1]) * rstd[c + 1];
        v.z = (sv.z - mean[c + 2]) * rstd[c + 2];
        v.w = (sv.w - mean[c + 3]) * rstd[c + 3];
        if (dst4) dst4[r * d4 + c4] = v;
    }
    if (outHi) {
        __nv_bfloat16 hx, lx, hy, ly, hz, lz, hw, lw;
        split_bf16(v.x, hx, lx); split_bf16(v.y, hy, ly);
        split_bf16(v.z, hz, lz); split_bf16(v.w, hw, lw);
        outHi[i * 2 + 0] = __nv_bfloat162(hx, hy);
        outHi[i * 2 + 1] = __nv_bfloat162(hz, hw);
        outLo[i * 2 + 0] = __nv_bfloat162(lx, ly);
        outLo[i * 2 + 1] = __nv_bfloat162(lz, lw);
    }
}
static inline void batchnorm(const float* src, float* dst, int n, int d,
                             float* mean, float* rstd, float* psum, float* psq,
                             cudaStream_t st,
                             __nv_bfloat16* outHi = nullptr, __nv_bfloat16* outLo = nullptr,
                             int Kpad = 0)
{
    cudaMemsetAsync(psum, 0, d * sizeof(float), st);
    cudaMemsetAsync(psq,  0, d * sizeof(float), st);
    dim3 bt(32, 8);
    dim3 bg((d + 31) / 32, BN_SLICES);
    bn_partial_kernel<<<bg, bt, 0, st>>>(src, n, d, psum, psq);
    bn_final_kernel<<<(d + 255) / 256, 256, 0, st>>>(psum, psq, n, d, mean, rstd);
    int kp = outHi ? Kpad : d;
    long total4 = (long)n * (kp / 4);
    bn_apply_kernel<<<(int)((total4 + 255) / 256), 256, 0, st>>>(
        (const float4*)src, (float4*)dst, total4, d / 4, kp / 4, mean, rstd,
        (__nv_bfloat162*)outHi, (__nv_bfloat162*)outLo);
}

// ---------------------------------------------------------------------------
// Gate u, z_in, fused attention, heads
// ---------------------------------------------------------------------------
__device__ __forceinline__ float coms_at(const float* t1, const float* t2,
                                         const float* t3, const float* t4,
                                         int n, int k)
{
    if (k < 500)  return t1[(size_t)n * 500 + k];
    if (k < 1000) return t2[(size_t)n * 500 + (k - 500)];
    if (k < 3000) return t3[(size_t)n * 2000 + (k - 1000)];
    return t4[(size_t)n * 64 + (k - 3000)];
}

__global__ void u_kernel(const float* __restrict__ t1, const float* __restrict__ t2,
                         const float* __restrict__ t3, const float* __restrict__ t4,
                         const float* __restrict__ W, const float* __restrict__ b,
                         float* __restrict__ u)
{
    int warp = (blockIdx.x * blockDim.x + threadIdx.x) >> 5;
    int lane = threadIdx.x & 31;
    if (warp >= NNODES) return;
    float acc[5] = {0.f, 0.f, 0.f, 0.f, 0.f};
    for (int k = lane; k < COMS_D; k += 32) {
        float v = coms_at(t1, t2, t3, t4, warp, k);
        const float* w = &W[(size_t)k * 5];
#pragma unroll
        for (int j = 0; j < 5; j++) acc[j] = fmaf(v, w[j], acc[j]);
    }
#pragma unroll
    for (int j = 0; j < 5; j++) {
        for (int off = 16; off > 0; off >>= 1)
            acc[j] += __shfl_down_sync(0xFFFFFFFF, acc[j], off);
    }
    if (lane == 0) {
        float l[5], m = -1e30f;
#pragma unroll
        for (int j = 0; j < 5; j++) { l[j] = tanhf(acc[j] + b[j]); m = fmaxf(m, l[j]); }
        float s = 0.f;
#pragma unroll
        for (int j = 0; j < 5; j++) { l[j] = expf(l[j] - m); s += l[j]; }
        float nrm = 0.f;
#pragma unroll
        for (int j = 0; j < 5; j++) { l[j] /= s; nrm += l[j] * l[j]; }
        nrm = fmaxf(sqrtf(nrm), 1e-12f);
#pragma unroll
        for (int j = 0; j < 5; j++) u[(size_t)warp * 5 + j] = l[j] / nrm;
    }
}

__global__ void zin_conv_kernel(const float* __restrict__ t1, const float* __restrict__ t2,
                                const float* __restrict__ t3, const float* __restrict__ t4,
                                const float* __restrict__ u,
                                __nv_bfloat16* __restrict__ hi, __nv_bfloat16* __restrict__ lo)
{
    long i = (long)blockIdx.x * blockDim.x + threadIdx.x;
    long total = (long)NNODES * 3072;
    if (i >= total) return;
    int n = (int)(i / 3072);
    int k = (int)(i % 3072);
    float v = 0.f;
    if (k < COMS_D) {
        int seg = (k < 500) ? 0 : (k < 1000) ? 1 : (k < 3000) ? 2 : 3;
        v = u[(size_t)n * 5 + seg] * coms_at(t1, t2, t3, t4, n, k);
    }
    __nv_bfloat16 h, l;
    split_bf16(v, h, l);
    hi[i] = h; lo[i] = l;
}

__global__ __launch_bounds__(256) void att_fused_kernel(
    const float* __restrict__ z, const float* __restrict__ ztopo,
    const float* __restrict__ W1, const float* __restrict__ b1,
    const float* __restrict__ w2, float* __restrict__ embp)
{
    __shared__ float sW1[64 * 128];
    __shared__ float sb1[128];
    __shared__ float sw2[128];
    __shared__ float sS[8][64];
    __shared__ float sc[8];
    int tid = threadIdx.x;
    for (int i = tid; i < 64 * 128; i += 256) sW1[i] = W1[i];
    if (tid < 128) { sb1[tid] = b1[tid]; sw2[tid] = w2[tid]; }

    int wid = tid >> 5, lane = tid & 31;
    int nodeBase = blockIdx.x * 4;
    int n = nodeBase + (wid >> 1);
    int br = wid & 1;
    bool valid = (n < NNODES);
    if (valid) {
        const float* s = br ? &ztopo[(size_t)n * 64] : &z[(size_t)n * 64];
        sS[wid][lane] = s[lane];
        sS[wid][lane + 32] = s[lane + 32];
    }
    __syncthreads();

    float partial = 0.f;
    if (valid) {
#pragma unroll
        for (int jj = 0; jj < 4; jj++) {
            int j = lane + jj * 32;
            float h = sb1[j];
#pragma unroll
            for (int k = 0; k < 64; k++)
                h = fmaf(sS[wid][k], sW1[k * 128 + j], h);
            partial = fmaf(tanhf(h), sw2[j], partial);
        }
    }
    for (int off = 16; off > 0; off >>= 1)
        partial += __shfl_down_sync(0xFFFFFFFF, partial, off);
    if (lane == 0) sc[wid] = partial;
    __syncthreads();

    int nl = tid >> 6;
    int d  = tid & 63;
    int n2 = nodeBase + nl;
    if (n2 < NNODES) {
        float s0 = sc[nl * 2], s1 = sc[nl * 2 + 1];
        float m = fmaxf(s0, s1);
        float e0 = expf(s0 - m), e1 = expf(s1 - m);
        float inv = 1.f / (e0 + e1);
        embp[(size_t)n2 * 64 + d] = (e0 * inv) * z[(size_t)n2 * 64 + d]
                                  + (e1 * inv) * ztopo[(size_t)n2 * 64 + d];
    }
}

__global__ void heads_kernel(const float* __restrict__ emb, const float* __restrict__ z,
                             const float* __restrict__ cluster,
                             float* __restrict__ pred, float* __restrict__ q)
{
    int n = blockIdx.x;
    int t = threadIdx.x;
    __shared__ float sh[64];
    __shared__ float zs[64];

    float v = emb[(size_t)n * 64 + t];
    sh[t] = v;
    __syncthreads();
    for (int s = 32; s > 0; s >>= 1) {
        if (t < s) sh[t] = fmaxf(sh[t], sh[t + s]);
        __syncthreads();
    }
    float m = sh[0];
    __syncthreads();
    float e = expf(v - m);
    sh[t] = e;
    __syncthreads();
    for (int s = 32; s > 0; s >>= 1) {
        if (t < s) sh[t] += sh[t + s];
        __syncthreads();
    }
    pred[(size_t)n * 64 + t] = e / sh[0];
    __syncthreads();

    zs[t] = z[(size_t)n * 64 + t];
    __syncthreads();
    float d2 = 0.f;
    const float* c = &cluster[(size_t)t * 64];
    for (int k = 0; k < 64; k++) {
        float diff = zs[k] - c[k];
        d2 = fmaf(diff, diff, d2);
    }
    float qv = 1.f / (1.f + d2);
    sh[t] = qv;
    __syncthreads();
    for (int s = 32; s > 0; s >>= 1) {
        if (t < s) sh[t] += sh[t + s];
        __syncthreads();
    }
    q[(size_t)n * 64 + t] = qv / sh[0];
}

// ---------------------------------------------------------------------------
// Host-side helpers (stream-aware)
// ---------------------------------------------------------------------------
static inline void conv_w(const float* Bw, int K, int N,
                          __nv_bfloat16* Whi, __nv_bfloat16* Wlo, int wsel, cudaStream_t st)
{
    int Kpad = (K + 31) & ~31;
    dim3 tg((Kpad + 31) / 32, (N + 31) / 32);
    convBT_kernel<<<tg, dim3(32, 8), 0, st>>>(Bw, Whi + (size_t)wsel * WOFF,
                                              Wlo + (size_t)wsel * WOFF, K, N, Kpad);
}

static inline void gemm_run(const __nv_bfloat16* aHi, const __nv_bfloat16* aLo,
                            const float* bias, float* C,
                            __nv_bfloat16* outHi, __nv_bfloat16* outLo,
                            int M, int N, int K, int mode,
                            __nv_bfloat16* Whi, __nv_bfloat16* Wlo, int wsel, cudaStream_t st)
{
    int Kpad = (K + 31) & ~31;
    int KpadOut = (N + 31) & ~31;
    cudaFuncSetAttribute(mma_gemm_kernel, cudaFuncAttributeMaxDynamicSharedMemorySize, GEMM_DSMEM);
    dim3 grid((N + 63) / 64, (M + 127) / 128);
    mma_gemm_kernel<<<grid, 256, GEMM_DSMEM, st>>>(aHi, aLo,
                                                   Whi + (size_t)wsel * WOFF, Wlo + (size_t)wsel * WOFF,
                                                   bias, C, outHi, outLo, KpadOut, M, N, Kpad, mode);
}

static inline void gemm_pre(const __nv_bfloat16* aHi, const __nv_bfloat16* aLo,
                            const float* Bw, const float* bias, float* C,
                            __nv_bfloat16* outHi, __nv_bfloat16* outLo,
                            int M, int N, int K, int mode,
                            __nv_bfloat16* Whi, __nv_bfloat16* Wlo, int wsel, cudaStream_t st)
{
    conv_w(Bw, K, N, Whi, Wlo, wsel, st);
    gemm_run(aHi, aLo, bias, C, outHi, outLo, M, N, K, mode, Whi, Wlo, wsel, st);
}

// ---------------------------------------------------------------------------
// Launch: fork topo chain (s2) against AE chain (stream 0); join for attention.
// ---------------------------------------------------------------------------
extern "C" void kernel_launch(void* const* d_in, const int* in_sizes, int n_in,
                              void* d_out, int out_size)
{
    const float* x       = (const float*)d_in[0];
    const float* adj_val = (const float*)d_in[1];
    const float* enc1_w  = (const float*)d_in[2];
    const float* enc1_b  = (const float*)d_in[3];
    const float* enc2_w  = (const float*)d_in[4];
    const float* enc2_b  = (const float*)d_in[5];
    const float* enc3_w  = (const float*)d_in[6];
    const float* enc3_b  = (const float*)d_in[7];
    const float* zl_w    = (const float*)d_in[8];
    const float* zl_b    = (const float*)d_in[9];
    const float* dec1_w  = (const float*)d_in[10];
    const float* dec1_b  = (const float*)d_in[11];
    const float* dec2_w  = (const float*)d_in[12];
    const float* dec2_b  = (const float*)d_in[13];
    const float* dec3_w  = (const float*)d_in[14];
    const float* dec3_b  = (const float*)d_in[15];
    const float* xbar_w  = (const float*)d_in[16];
    const float* xbar_b  = (const float*)d_in[17];
    const float* t1_w    = (const float*)d_in[18];
    const float* t2_w    = (const float*)d_in[19];
    const float* t3_w    = (const float*)d_in[20];
    const float* t4_w    = (const float*)d_in[21];
    const float* agcn_w  = (const float*)d_in[22];
    const float* mlpl_w  = (const float*)d_in[23];
    const float* mlpl_b  = (const float*)d_in[24];
    const float* att_w1  = (const float*)d_in[25];
    const float* att_b1  = (const float*)d_in[26];
    const float* att_w2  = (const float*)d_in[27];
    const float* cluster = (const float*)d_in[28];
    const int*   adj_row = (const int*)d_in[29];
    const int*   adj_col = (const int*)d_in[30];
    const int E = in_sizes[1];

    float* out      = (float*)d_out;
    float* out_xbar = out;
    float* out_q    = out + (size_t)NNODES * NIN;
    float* out_pred = out_q + (size_t)NNODES * NZC;
    float* out_emb  = out_pred + (size_t)NNODES * NZC;

    float *z, *g, *traw, *t1, *t2, *t3, *t4, *u, *ztopo, *embp, *mean, *rstd, *psum, *psq;
    int *cnt, *rowptr, *wp, *scol;
    float *sval;
    __nv_bfloat16 *A0h, *A0l, *A1h, *A1l, *A2h, *A2l, *A3h, *A3l, *Wh, *Wl;
    cudaGetSymbolAddress((void**)&z,  g_zbuf);
    cudaGetSymbolAddress((void**)&g,  g_gbuf);
    cudaGetSymbolAddress((void**)&traw, g_traw);
    cudaGetSymbolAddress((void**)&t1, g_t1);
    cudaGetSymbolAddress((void**)&t2, g_t2);
    cudaGetSymbolAddress((void**)&t3, g_t3);
    cudaGetSymbolAddress((void**)&t4, g_t4);
    cudaGetSymbolAddress((void**)&u,  g_u);
    cudaGetSymbolAddress((void**)&ztopo, g_ztopo);
    cudaGetSymbolAddress((void**)&embp, g_embp);
    cudaGetSymbolAddress((void**)&mean, g_mean);
    cudaGetSymbolAddress((void**)&rstd, g_rstd);
    cudaGetSymbolAddress((void**)&psum, g_psum);
    cudaGetSymbolAddress((void**)&psq,  g_psq);
    cudaGetSymbolAddress((void**)&cnt, g_cnt);
    cudaGetSymbolAddress((void**)&rowptr, g_rowptr);
    cudaGetSymbolAddress((void**)&wp, g_wp);
    cudaGetSymbolAddress((void**)&scol, g_scol);
    cudaGetSymbolAddress((void**)&sval, g_sval);
    cudaGetSymbolAddress((void**)&A0h, g_A0hi);
    cudaGetSymbolAddress((void**)&A0l, g_A0lo);
    cudaGetSymbolAddress((void**)&A1h, g_A1hi);
    cudaGetSymbolAddress((void**)&A1l, g_A1lo);
    cudaGetSymbolAddress((void**)&A2h, g_A2hi);
    cudaGetSymbolAddress((void**)&A2l, g_A2lo);
    cudaGetSymbolAddress((void**)&A3h, g_A3hi);
    cudaGetSymbolAddress((void**)&A3l, g_A3lo);
    cudaGetSymbolAddress((void**)&Wh, g_Whi);
    cudaGetSymbolAddress((void**)&Wl, g_Wlo);

    cudaStream_t s0 = 0;
    cudaStream_t s2;
    cudaStreamCreateWithFlags(&s2, cudaStreamNonBlocking);
    cudaEvent_t ev1, ev2;
    cudaEventCreateWithFlags(&ev1, cudaEventDisableTiming);
    cudaEventCreateWithFlags(&ev2, cudaEventDisableTiming);

    // ---------------- shared prologue (stream 0): convert x, build CSR ------
    {
        int Kpad = 2016;
        long tA = (long)NNODES * Kpad;
        convA_kernel<<<(int)((tA + 255) / 256), 256, 0, s0>>>(x, A0h, A0l, NIN, Kpad, tA);
    }
    csr_zero_kernel<<<(NNODES + 256) / 256, 256, 0, s0>>>(cnt);
    csr_count_kernel<<<(E + 255) / 256, 256, 0, s0>>>(adj_row, cnt, E);
    csr_scan_kernel<<<1, 1024, 0, s0>>>(cnt, rowptr, wp);
    csr_scatter_kernel<<<(E + 255) / 256, 256, 0, s0>>>(adj_row, adj_col, adj_val, wp, scol, sval, E);

    cudaEventRecord(ev1, s0);
    cudaStreamWaitEvent(s2, ev1, 0);

    // ---------------- topo chain (stream s2, W region 1, A2 buffer) ---------
    gemm_pre(A0h, A0l, t1_w, nullptr, g, nullptr, nullptr, NNODES, 500, NIN, 0, Wh, Wl, 1, s2);
    spmm_csr(g, traw, 500, 0, rowptr, scol, sval, s2);
    batchnorm(traw, t1, NNODES, 500, mean, rstd, psum, psq, s2, A2h, A2l, 512);
    gemm_pre(A2h, A2l, t2_w, nullptr, g, nullptr, nullptr, NNODES, 500, 500, 0, Wh, Wl, 1, s2);

    spmm_csr(g, traw, 500, 0, rowptr, scol, sval, s2);
    batchnorm(traw, t2, NNODES, 500, mean, rstd, psum, psq, s2, A2h, A2l, 512);
    gemm_pre(A2h, A2l, t3_w, nullptr, g, nullptr, nullptr, NNODES, 2000, 500, 0, Wh, Wl, 1, s2);

    spmm_csr(g, traw, 2000, 0, rowptr, scol, sval, s2);
    batchnorm(traw, t3, NNODES, 2000, mean, rstd, psum, psq, s2, A2h, A2l, 2016);
    gemm_pre(A2h, A2l, t4_w, nullptr, g, nullptr, nullptr, NNODES, NZC, 2000, 0, Wh, Wl, 1, s2);

    spmm_csr(g, traw, NZC, 0, rowptr, scol, sval, s2);
    batchnorm(traw, t4, NNODES, NZC, mean, rstd, psum, psq, s2);

    u_kernel<<<(NNODES * 32 + 255) / 256, 256, 0, s2>>>(t1, t2, t3, t4, mlpl_w, mlpl_b, u);
    {
        long total = (long)NNODES * 3072;
        zin_conv_kernel<<<(int)((total + 255) / 256), 256, 0, s2>>>(t1, t2, t3, t4, u, A2h, A2l);
    }
    gemm_pre(A2h, A2l, agcn_w, nullptr, g, nullptr, nullptr, NNODES, NZC, COMS_D, 0, Wh, Wl, 1, s2);
    spmm_csr(g, traw, NZC, 1, rowptr, scol, sval, s2);
    batchnorm(traw, ztopo, NNODES, NZC, mean, rstd, psum, psq, s2);

    cudaEventRecord(ev2, s2);

    // ---------------- AE chain (stream 0, W region 0, A1/A3 ping-pong) ------
    gemm_pre(A0h, A0l, enc1_w, enc1_b, nullptr, A1h, A1l, NNODES, D1, NIN, 2, Wh, Wl, 0, s0);
    gemm_pre(A1h, A1l, enc2_w, enc2_b, nullptr, A3h, A3l, NNODES, D2, D1, 2, Wh, Wl, 0, s0);
    gemm_pre(A3h, A3l, enc3_w, enc3_b, nullptr, A1h, A1l, NNODES, D3, D2, 2, Wh, Wl, 0, s0);
    gemm_pre(A1h, A1l, zl_w, zl_b, z, A3h, A3l, NNODES, NZC, D3, 1, Wh, Wl, 0, s0);
    gemm_pre(A3h, A3l, dec1_w, dec1_b, nullptr, A1h, A1l, NNODES, 2000, NZC, 2, Wh, Wl, 0, s0);
    gemm_pre(A1h, A1l, dec2_w, dec2_b, nullptr, A3h, A3l, NNODES, 500, 2000, 2, Wh, Wl, 0, s0);
    gemm_pre(A3h, A3l, dec3_w, dec3_b, nullptr, A1h, A1l, NNODES, 500, 500, 2, Wh, Wl, 0, s0);
    gemm_pre(A1h, A1l, xbar_w, xbar_b, out_xbar, nullptr, nullptr, NNODES, NIN, 500, 1, Wh, Wl, 0, s0);

    // ---------------- join: attention needs z (s0) + ztopo (s2) -------------
    cudaStreamWaitEvent(s0, ev2, 0);
    att_fused_kernel<<<(NNODES + 3) / 4, 256, 0, s0>>>(z, ztopo, att_w1, att_b1, att_w2, embp);
    batchnorm(embp, out_emb, NNODES, NZC, mean, rstd, psum, psq, s0);
    heads_kernel<<<NNODES, 64, 0, s0>>>(out_emb, z, cluster, out_pred, out_q);
    // streams/events intentionally not destroyed: kernel_launch runs only for
    // the correctness call + the capture call; destroying inside capture risks
    // invalidating the captured fork/join.
}